// round 10
// baseline (speedup 1.0000x reference)
#include <cuda_runtime.h>
#include <cuda_fp16.h>
#include <cstdint>

// ============================================================================
// GraphCastProcessor — fp16 weight-split mma.sync GEMMs (2 MMAs/k16) +
// fully-fp16 edge path: y1/y2 stored fp16x2, agg accumulated via
// red.global.add.noftz.v4.f16x2 (no fp32 agg, no convert pass).
//   y1 = x@We[:256], y2 = x@We[256:512]          (fp16x2 out)
//   h_e = y1[dst]+y2[src]+ea@W3+b ; msg = silu(LN(h)); aggs += msg (f16x2 RED)
//   u = x@Wn1[:256]+aggs@Wn1[256:]+b ; t = silu(LN(u))
//   x = x + t@Wn2 + b2
// ============================================================================

#define MAXN 40962
#define MAXD 163848
#define MAXNL 6

__device__ float g_bufA[MAXN * 256];
__device__ float g_bufB[MAXN * 256];
__device__ uint32_t g_y1h [MAXN * 128];   // fp16x2 rows (512B)
__device__ uint32_t g_y2h [MAXN * 128];
__device__ uint32_t g_xs  [MAXN * 128];   // fp16x2 activations
__device__ uint32_t g_aggs[MAXN * 128];   // fp16x2, RED-accumulated
__device__ uint32_t g_tmps[MAXN * 128];
// fragment-ordered split weights: [layer][chunk16][wn(4)][nt(8)][lane(32)]
// uint4 = {hi_k0pair, hi_k1pair, lo_k0pair, lo_k1pair}
__device__ uint4 g_We [MAXNL * 32 * 1024];
__device__ uint4 g_Wn1[MAXNL * 32 * 1024];
__device__ uint4 g_Wn2[MAXNL * 16 * 1024];

// ---- dynamic smem layout (bytes) ----
#define SA_OFF    0                       // u32 sA[2][64][20] = 10240 (80B row)
#define SB_OFF    10240                   // uint4 sB[2][2048] = 65536 -> 75776
#define SOUT_OFF  0                       // float sOut[64][260] = 66560 (aliases)
#define SBIAS_OFF 75776
#define SG_OFF    76800
#define SBV_OFF   77824
#define MBAR_OFF  78848                   // 2 x u64
#define SMEM_BYTES 78880

__device__ __forceinline__ float fast_silu(float y) {
    return __fdividef(y, 1.0f + __expf(-y));
}

__device__ __forceinline__ uint32_t packh(float a, float b) {
    __half2 h = __floats2half2_rn(a, b);
    return *(uint32_t*)&h;
}
__device__ __forceinline__ float2 unpackh(uint32_t u) {
    __half2 h = *(__half2*)&u;
    return __half22float2(h);
}
__device__ __forceinline__ uint2 wsplit(float a, float b) {
    __half h0 = __float2half_rn(a);
    __half h1 = __float2half_rn(b);
    __half l0 = __float2half_rn(a - __half2float(h0));
    __half l1 = __float2half_rn(b - __half2float(h1));
    uint2 r;
    r.x = (uint32_t)__half_as_ushort(h0) | ((uint32_t)__half_as_ushort(h1) << 16);
    r.y = (uint32_t)__half_as_ushort(l0) | ((uint32_t)__half_as_ushort(l1) << 16);
    return r;
}

__device__ __forceinline__ void mma_f16(float c[4], const uint32_t a[4],
                                        uint32_t b0, uint32_t b1) {
    asm volatile(
        "mma.sync.aligned.m16n8k16.row.col.f32.f16.f16.f32 "
        "{%0,%1,%2,%3}, {%4,%5,%6,%7}, {%8,%9}, {%0,%1,%2,%3};"
        : "+f"(c[0]), "+f"(c[1]), "+f"(c[2]), "+f"(c[3])
        : "r"(a[0]), "r"(a[1]), "r"(a[2]), "r"(a[3]), "r"(b0), "r"(b1));
}

__device__ __forceinline__ void red_h8(uint32_t* p, uint32_t a, uint32_t b,
                                       uint32_t c, uint32_t d) {
    asm volatile("red.global.add.noftz.v4.f16x2 [%0], {%1,%2,%3,%4};"
                 :: "l"(p), "r"(a), "r"(b), "r"(c), "r"(d) : "memory");
}

__device__ __forceinline__ void cp16(uint32_t smem_dst, const void* gsrc) {
    asm volatile("cp.async.cg.shared.global [%0], [%1], 16;\n"
                 :: "r"(smem_dst), "l"(gsrc));
}
#define CP_COMMIT() asm volatile("cp.async.commit_group;\n" ::: "memory")
#define CP_WAIT(n)  asm volatile("cp.async.wait_group %0;\n" :: "n"(n) : "memory")

__device__ __forceinline__ void mbar_init(uint32_t mbar, uint32_t count) {
    asm volatile("mbarrier.init.shared.b64 [%0], %1;" :: "r"(mbar), "r"(count) : "memory");
}
__device__ __forceinline__ void mbar_expect_tx(uint32_t mbar, uint32_t bytes) {
    asm volatile("mbarrier.arrive.expect_tx.shared.b64 _, [%0], %1;"
                 :: "r"(mbar), "r"(bytes) : "memory");
}
__device__ __forceinline__ void mbar_wait(uint32_t mbar, uint32_t parity) {
    asm volatile(
        "{\n\t.reg .pred P1;\n\t"
        "WAIT_LOOP_%=:\n\t"
        "mbarrier.try_wait.parity.acquire.cta.shared::cta.b64 P1, [%0], %1, 0x989680;\n\t"
        "@P1 bra.uni WAIT_DONE_%=;\n\t"
        "bra.uni WAIT_LOOP_%=;\n\t"
        "WAIT_DONE_%=:\n\t}"
        :: "r"(mbar), "r"(parity) : "memory");
}
__device__ __forceinline__ void bulk_cp(uint32_t smem_dst, const void* gsrc,
                                        uint32_t bytes, uint32_t mbar) {
    asm volatile(
        "cp.async.bulk.shared::cta.global.mbarrier::complete_tx::bytes [%0], [%1], %2, [%3];"
        :: "r"(smem_dst), "l"(gsrc), "r"(bytes), "r"(mbar) : "memory");
}

// LN(256)+SiLU; row spread as 8 vals/lane (cols tx*4+j / 128+tx*4+j-4)
__device__ __forceinline__ void ln_silu_row(float v[8], int tx,
                                            const float* sG, const float* sB) {
    float s = v[0] + v[1] + v[2] + v[3] + v[4] + v[5] + v[6] + v[7];
#pragma unroll
    for (int o = 16; o > 0; o >>= 1) s += __shfl_xor_sync(0xffffffffu, s, o);
    float mean = s * (1.0f / 256.0f);
    float vs = 0.f;
#pragma unroll
    for (int j = 0; j < 8; j++) { float d = v[j] - mean; vs += d * d; }
#pragma unroll
    for (int o = 16; o > 0; o >>= 1) vs += __shfl_xor_sync(0xffffffffu, vs, o);
    float rstd = rsqrtf(vs * (1.0f / 256.0f) + 1e-5f);
#pragma unroll
    for (int j = 0; j < 8; j++) {
        int col = (j < 4) ? (tx * 4 + j) : (128 + tx * 4 + j - 4);
        float y = (v[j] - mean) * rstd * sG[col] + sB[col];
        v[j] = fast_silu(y);
    }
}

// one K32 superchunk: two k16 halves, 2 MMAs each (xh*wh + xh*wl)
__device__ __forceinline__ void compute_schunk(const char* smraw, int buf,
                                               int wm, int wn, int lane,
                                               float acc[2][8][4]) {
    const uint32_t* sAp = (const uint32_t*)(smraw + SA_OFF + buf * 5120);
    const uint4* sBp = (const uint4*)(smraw + SB_OFF + buf * 32768);
    const int q = lane & 3;
#pragma unroll
    for (int h = 0; h < 2; h++) {
        uint32_t a[2][4];
#pragma unroll
        for (int mt = 0; mt < 2; mt++) {
            int r = wm * 32 + mt * 16 + (lane >> 2);
            a[mt][0] = sAp[r * 20 + h * 8 + q];
            a[mt][1] = sAp[(r + 8) * 20 + h * 8 + q];
            a[mt][2] = sAp[r * 20 + h * 8 + q + 4];
            a[mt][3] = sAp[(r + 8) * 20 + h * 8 + q + 4];
        }
#pragma unroll
        for (int nt = 0; nt < 8; nt++) {
            uint4 b = sBp[h * 1024 + wn * 256 + nt * 32 + lane];
#pragma unroll
            for (int mt = 0; mt < 2; mt++) {
                mma_f16(acc[mt][nt], a[mt], b.x, b.y);
                mma_f16(acc[mt][nt], a[mt], b.z, b.w);
            }
        }
    }
}

template <typename FA>
__device__ __forceinline__ void gemm_pipeline(FA stageA, const uint4* __restrict__ Wp,
                                              char* smraw, uint32_t sbase, int tid,
                                              int wm, int wn, int lane, int schunks,
                                              float acc[2][8][4]) {
    const uint32_t mbar0 = sbase + MBAR_OFF;
    auto issueB = [&](int c, int buf) {
        if (tid == 0) {
            uint32_t mb = mbar0 + buf * 8;
            mbar_expect_tx(mb, 32768);
            bulk_cp(sbase + SB_OFF + buf * 32768, Wp + (size_t)c * 2048, 32768, mb);
        }
    };
    stageA(0, 0); CP_COMMIT(); issueB(0, 0);
#pragma unroll 1
    for (int c = 0; c < schunks; c++) {
        if (c + 1 < schunks) {
            stageA(c + 1, (c + 1) & 1); CP_COMMIT(); issueB(c + 1, (c + 1) & 1);
            CP_WAIT(1);
        } else {
            CP_WAIT(0);
        }
        mbar_wait(mbar0 + (c & 1) * 8, (c >> 1) & 1);
        __syncthreads();
        compute_schunk(smraw, c & 1, wm, wn, lane, acc);
        __syncthreads();
    }
}

__device__ __forceinline__ void acc_to_sout(char* smraw, int wm, int wn,
                                            int lane, float acc[2][8][4],
                                            const float* sBias) {
    float (*sOut)[260] = (float(*)[260])(smraw + SOUT_OFF);
#pragma unroll
    for (int mt = 0; mt < 2; mt++)
#pragma unroll
        for (int nt = 0; nt < 8; nt++) {
            int r0 = wm * 32 + mt * 16 + (lane >> 2);
            int c = wn * 64 + nt * 8 + 2 * (lane & 3);
            float b0 = sBias ? sBias[c] : 0.f;
            float b1 = sBias ? sBias[c + 1] : 0.f;
            sOut[r0][c]         = acc[mt][nt][0] + b0;
            sOut[r0][c + 1]     = acc[mt][nt][1] + b1;
            sOut[r0 + 8][c]     = acc[mt][nt][2] + b0;
            sOut[r0 + 8][c + 1] = acc[mt][nt][3] + b1;
        }
}

// ---------------------------------------------------------------------------
// packers
// ---------------------------------------------------------------------------
__global__ void pack_w_frag(const float* __restrict__ W, uint4* __restrict__ out,
                            int Ksrc, int lstride, int C, int NL) {
    size_t idx = (size_t)blockIdx.x * blockDim.x + threadIdx.x;
    size_t total = (size_t)NL * C * 1024;
    if (idx >= total) return;
    int t = (int)(idx & 1023);
    int lane = t & 31, nt = (t >> 5) & 7, wn = t >> 8;
    int c = (int)((idx >> 10) % C);
    int l = (int)(idx / ((size_t)C * 1024));
    int n = wn * 64 + nt * 8 + (lane >> 2);
    int q = lane & 3;
    int kp0 = c * 8 + q, kp1 = c * 8 + q + 4;
    const float* Wl = W + (size_t)l * lstride * 256;
    float a0 = (2 * kp0     < Ksrc) ? Wl[(size_t)(2 * kp0)     * 256 + n] : 0.f;
    float a1 = (2 * kp0 + 1 < Ksrc) ? Wl[(size_t)(2 * kp0 + 1) * 256 + n] : 0.f;
    float b0 = (2 * kp1     < Ksrc) ? Wl[(size_t)(2 * kp1)     * 256 + n] : 0.f;
    float b1 = (2 * kp1 + 1 < Ksrc) ? Wl[(size_t)(2 * kp1 + 1) * 256 + n] : 0.f;
    uint2 p0 = wsplit(a0, a1);
    uint2 p1 = wsplit(b0, b1);
    out[idx] = make_uint4(p0.x, p1.x, p0.y, p1.y);
}

__global__ void convert_h(const float* __restrict__ in, uint32_t* __restrict__ out,
                          int n) {
    int i = blockIdx.x * blockDim.x + threadIdx.x;
    if (i < n) {
        float2 v = ((const float2*)in)[i];
        out[i] = packh(v.x, v.y);
    }
}

__global__ void zero_kernel(float4* __restrict__ p, int n4) {
    int i = blockIdx.x * blockDim.x + threadIdx.x;
    if (i < n4) p[i] = make_float4(0.f, 0.f, 0.f, 0.f);
}

// ---------------------------------------------------------------------------
// y12 kernel: y = x @ We[half*256 : (half+1)*256] (no bias) -> fp16x2 rows
// ---------------------------------------------------------------------------
__global__ __launch_bounds__(256, 2) void y12_kernel(
    const uint32_t* __restrict__ xs, const uint4* __restrict__ WpBase,
    uint32_t* __restrict__ y1h, uint32_t* __restrict__ y2h, int N) {
    extern __shared__ char smraw[];
    const int tid = threadIdx.x;
    const int lane = tid & 31, warp = tid >> 5;
    const int wm = warp >> 2, wn = warp & 3;
    const int n0 = blockIdx.x * 64;
    const int half = blockIdx.y;
    const uint32_t sbase = (uint32_t)__cvta_generic_to_shared(smraw);
    const int arow = tid >> 2, apart = tid & 3;
    int rowg = n0 + arow; if (rowg >= N) rowg = N - 1;

    if (tid == 0) { mbar_init(sbase + MBAR_OFF, 1); mbar_init(sbase + MBAR_OFF + 8, 1); }
    __syncthreads();

    const uint4* Wp = WpBase + (size_t)half * 16 * 1024;
    uint32_t* yout = half ? y2h : y1h;

    float acc[2][8][4];
#pragma unroll
    for (int mt = 0; mt < 2; mt++)
#pragma unroll
        for (int nt = 0; nt < 8; nt++)
#pragma unroll
            for (int j = 0; j < 4; j++) acc[mt][nt][j] = 0.f;

    auto stageA = [&](int c, int buf) {
        const char* src = (const char*)(xs + (size_t)rowg * 128 + c * 16) + apart * 16;
        cp16(sbase + SA_OFF + buf * 5120 + arow * 80 + apart * 16, src);
    };
    gemm_pipeline(stageA, Wp, smraw, sbase, tid, wm, wn, lane, 8, acc);

    acc_to_sout(smraw, wm, wn, lane, acc, nullptr);
    __syncthreads();
    float (*sOut)[260] = (float(*)[260])(smraw + SOUT_OFF);
#pragma unroll 1
    for (int i = 0; i < 8; i++) {
        int r = i * 8 + warp;
        int row = n0 + r;
        if (row < N) {
            float v[8];
            *(float4*)&v[0] = *(float4*)&sOut[r][lane * 8];
            *(float4*)&v[4] = *(float4*)&sOut[r][lane * 8 + 4];
            uint4 o = make_uint4(packh(v[0], v[1]), packh(v[2], v[3]),
                                 packh(v[4], v[5]), packh(v[6], v[7]));
            *(uint4*)(yout + (size_t)row * 128 + lane * 4) = o;
        }
    }
}

// ---------------------------------------------------------------------------
// Edge pass: h = y1h[dst]+y2h[src]+ea@W3+b; silu(LN(h)) -> f16x2 RED into aggs
// one edge per warp, 8 edges per block; lane owns cols lane*8..lane*8+7
// ---------------------------------------------------------------------------
__global__ __launch_bounds__(256) void edge_pass(
    const uint32_t* __restrict__ y1h, const uint32_t* __restrict__ y2h,
    const int* __restrict__ eidx, const float* __restrict__ ea,
    const float* __restrict__ W3, const float* __restrict__ Wb,
    const float* __restrict__ gam, const float* __restrict__ bet,
    uint32_t* __restrict__ aggs, int D) {
    const int lane = threadIdx.x & 31, warp = threadIdx.x >> 5;
    const int e = blockIdx.x * 8 + warp;

    float w3r[4][8], biasr[8], gr[8], br[8];
#pragma unroll
    for (int j = 0; j < 8; j++) {
        int col = lane * 8 + j;
        biasr[j] = __ldg(Wb + col);
        gr[j] = __ldg(gam + col);
        br[j] = __ldg(bet + col);
#pragma unroll
        for (int k = 0; k < 4; k++) w3r[k][j] = __ldg(W3 + k * 256 + col);
    }
    if (e >= D) return;

    int src = __ldg(eidx + e);
    int dst = __ldg(eidx + (size_t)D + e);
    uint4 u1 = *(const uint4*)(y1h + (size_t)dst * 128 + lane * 4);
    uint4 u2 = *(const uint4*)(y2h + (size_t)src * 128 + lane * 4);
    float4 eav = *(const float4*)(ea + (size_t)e * 4);

    float v[8];
    {
        float2 a0 = unpackh(u1.x), a1 = unpackh(u1.y), a2 = unpackh(u1.z), a3 = unpackh(u1.w);
        float2 c0 = unpackh(u2.x), c1 = unpackh(u2.y), c2 = unpackh(u2.z), c3 = unpackh(u2.w);
        v[0] = a0.x + c0.x; v[1] = a0.y + c0.y;
        v[2] = a1.x + c1.x; v[3] = a1.y + c1.y;
        v[4] = a2.x + c2.x; v[5] = a2.y + c2.y;
        v[6] = a3.x + c3.x; v[7] = a3.y + c3.y;
    }
#pragma unroll
    for (int j = 0; j < 8; j++) {
        float h = v[j] + biasr[j];
        h = fmaf(eav.x, w3r[0][j], h);
        h = fmaf(eav.y, w3r[1][j], h);
        h = fmaf(eav.z, w3r[2][j], h);
        h = fmaf(eav.w, w3r[3][j], h);
        v[j] = h;
    }
    float s = v[0] + v[1] + v[2] + v[3] + v[4] + v[5] + v[6] + v[7];
#pragma unroll
    for (int o = 16; o > 0; o >>= 1) s += __shfl_xor_sync(0xffffffffu, s, o);
    float mean = s * (1.0f / 256.0f);
    float vs = 0.f;
#pragma unroll
    for (int j = 0; j < 8; j++) { float d = v[j] - mean; vs += d * d; }
#pragma unroll
    for (int o = 16; o > 0; o >>= 1) vs += __shfl_xor_sync(0xffffffffu, vs, o);
    float rstd = rsqrtf(vs * (1.0f / 256.0f) + 1e-5f);

    float m[8];
#pragma unroll
    for (int j = 0; j < 8; j++)
        m[j] = fast_silu((v[j] - mean) * rstd * gr[j] + br[j]);

    red_h8(aggs + (size_t)dst * 128 + lane * 4,
           packh(m[0], m[1]), packh(m[2], m[3]),
           packh(m[4], m[5]), packh(m[6], m[7]));
}

// ---------------------------------------------------------------------------
// Node kernel 1: t = silu(LN(x@Wn1[:256] + aggs@Wn1[256:] + b)) -> tmps (fp16)
// ---------------------------------------------------------------------------
__global__ __launch_bounds__(256, 2) void node1_kernel(
    const uint32_t* __restrict__ xs, const uint32_t* __restrict__ aggs,
    const uint4* __restrict__ Wp, const float* __restrict__ Wb,
    const float* __restrict__ gam, const float* __restrict__ bet,
    uint32_t* __restrict__ tmps, int N) {
    extern __shared__ char smraw[];
    float* sBias = (float*)(smraw + SBIAS_OFF);
    float* sG    = (float*)(smraw + SG_OFF);
    float* sBv   = (float*)(smraw + SBV_OFF);

    const int tid = threadIdx.x;
    const int lane = tid & 31, warp = tid >> 5;
    const int wm = warp >> 2, wn = warp & 3;
    const int n0 = blockIdx.x * 64;
    const uint32_t sbase = (uint32_t)__cvta_generic_to_shared(smraw);
    const int arow = tid >> 2, apart = tid & 3;

    sBias[tid] = Wb[tid]; sG[tid] = gam[tid]; sBv[tid] = bet[tid];
    if (tid == 0) { mbar_init(sbase + MBAR_OFF, 1); mbar_init(sbase + MBAR_OFF + 8, 1); }
    __syncthreads();

    int rowg = n0 + arow; if (rowg >= N) rowg = N - 1;

    float acc[2][8][4];
#pragma unroll
    for (int mt = 0; mt < 2; mt++)
#pragma unroll
        for (int nt = 0; nt < 8; nt++)
#pragma unroll
            for (int j = 0; j < 4; j++) acc[mt][nt][j] = 0.f;

    auto stageA = [&](int c, int buf) {
        const uint32_t* bA = (c < 8) ? xs : aggs;
        const char* src = (const char*)(bA + (size_t)rowg * 128 + (c & 7) * 16) + apart * 16;
        cp16(sbase + SA_OFF + buf * 5120 + arow * 80 + apart * 16, src);
    };
    gemm_pipeline(stageA, Wp, smraw, sbase, tid, wm, wn, lane, 16, acc);

    acc_to_sout(smraw, wm, wn, lane, acc, sBias);
    __syncthreads();
    float (*sOut)[260] = (float(*)[260])(smraw + SOUT_OFF);
#pragma unroll 1
    for (int i = 0; i < 8; i++) {
        int r = i * 8 + warp;
        float vv[8];
        *(float4*)&vv[0] = *(float4*)&sOut[r][lane * 4];
        *(float4*)&vv[4] = *(float4*)&sOut[r][128 + lane * 4];
        ln_silu_row(vv, lane, sG, sBv);
        int row = n0 + r;
        if (row < N) {
            uint32_t* op = tmps + (size_t)row * 128;
            op[lane * 2]          = packh(vv[0], vv[1]);
            op[lane * 2 + 1]      = packh(vv[2], vv[3]);
            op[64 + lane * 2]     = packh(vv[4], vv[5]);
            op[64 + lane * 2 + 1] = packh(vv[6], vv[7]);
        }
    }
}

// ---------------------------------------------------------------------------
// Node kernel 2: out = x + t@Wn2 + b2; also writes fp16 xs for next layer
// ---------------------------------------------------------------------------
__global__ __launch_bounds__(256, 2) void node2_kernel(
    const uint32_t* __restrict__ tmps, const float* __restrict__ xres,
    const uint4* __restrict__ Wp, const float* __restrict__ Wb,
    float* __restrict__ out, uint32_t* __restrict__ xs_next, int N) {
    extern __shared__ char smraw[];
    float* sBias = (float*)(smraw + SBIAS_OFF);

    const int tid = threadIdx.x;
    const int lane = tid & 31, warp = tid >> 5;
    const int wm = warp >> 2, wn = warp & 3;
    const int n0 = blockIdx.x * 64;
    const uint32_t sbase = (uint32_t)__cvta_generic_to_shared(smraw);
    const int arow = tid >> 2, apart = tid & 3;

    sBias[tid] = Wb[tid];
    if (tid == 0) { mbar_init(sbase + MBAR_OFF, 1); mbar_init(sbase + MBAR_OFF + 8, 1); }
    __syncthreads();

    int rowg = n0 + arow; if (rowg >= N) rowg = N - 1;

    float acc[2][8][4];
#pragma unroll
    for (int mt = 0; mt < 2; mt++)
#pragma unroll
        for (int nt = 0; nt < 8; nt++)
#pragma unroll
            for (int j = 0; j < 4; j++) acc[mt][nt][j] = 0.f;

    auto stageA = [&](int c, int buf) {
        const char* src = (const char*)(tmps + (size_t)rowg * 128 + c * 16) + apart * 16;
        cp16(sbase + SA_OFF + buf * 5120 + arow * 80 + apart * 16, src);
    };
    gemm_pipeline(stageA, Wp, smraw, sbase, tid, wm, wn, lane, 8, acc);

    acc_to_sout(smraw, wm, wn, lane, acc, sBias);
    __syncthreads();
    float (*sOut)[260] = (float(*)[260])(smraw + SOUT_OFF);
#pragma unroll 1
    for (int i = 0; i < 8; i++) {
        int r = i * 8 + warp;
        int row = n0 + r;
        if (row < N) {
            const float* xr = xres + (size_t)row * 256;
            float4 lo = *(float4*)&sOut[r][lane * 4];
            float4 hi = *(float4*)&sOut[r][128 + lane * 4];
            float4 xlo = *(const float4*)(xr + lane * 4);
            float4 xhi = *(const float4*)(xr + 128 + lane * 4);
            lo.x += xlo.x; lo.y += xlo.y; lo.z += xlo.z; lo.w += xlo.w;
            hi.x += xhi.x; hi.y += xhi.y; hi.z += xhi.z; hi.w += xhi.w;
            float* op = out + (size_t)row * 256;
            *(float4*)(op + lane * 4) = lo;
            *(float4*)(op + 128 + lane * 4) = hi;
            uint32_t* xp = xs_next + (size_t)row * 128;
            xp[lane * 2]          = packh(lo.x, lo.y);
            xp[lane * 2 + 1]      = packh(lo.z, lo.w);
            xp[64 + lane * 2]     = packh(hi.x, hi.y);
            xp[64 + lane * 2 + 1] = packh(hi.z, hi.w);
        }
    }
}

// ---------------------------------------------------------------------------
extern "C" void kernel_launch(void* const* d_in, const int* in_sizes, int n_in,
                              void* d_out, int out_size) {
    const float* x_in  = (const float*)d_in[0];
    const int*   eidx  = (const int*)d_in[1];
    const float* ea    = (const float*)d_in[2];
    const float* We_w  = (const float*)d_in[3];
    const float* We_b  = (const float*)d_in[4];
    const float* g1    = (const float*)d_in[5];
    const float* b1    = (const float*)d_in[6];
    const float* Wn1_w = (const float*)d_in[7];
    const float* Wn1_b = (const float*)d_in[8];
    const float* g2    = (const float*)d_in[9];
    const float* b2    = (const float*)d_in[10];
    const float* Wn2_w = (const float*)d_in[11];
    const float* Wn2_b = (const float*)d_in[12];

    const int N  = in_sizes[0] / 256;
    const int D  = in_sizes[1] / 2;
    const int NL = in_sizes[4] / 256;

    float *bufA, *bufB;
    uint32_t *y1h, *y2h, *xs, *aggs, *tmps;
    uint4 *wE, *wN1, *wN2;
    cudaGetSymbolAddress((void**)&bufA, g_bufA);
    cudaGetSymbolAddress((void**)&bufB, g_bufB);
    cudaGetSymbolAddress((void**)&y1h,  g_y1h);
    cudaGetSymbolAddress((void**)&y2h,  g_y2h);
    cudaGetSymbolAddress((void**)&xs,   g_xs);
    cudaGetSymbolAddress((void**)&aggs, g_aggs);
    cudaGetSymbolAddress((void**)&tmps, g_tmps);
    cudaGetSymbolAddress((void**)&wE,   g_We);
    cudaGetSymbolAddress((void**)&wN1,  g_Wn1);
    cudaGetSymbolAddress((void**)&wN2,  g_Wn2);

    cudaFuncSetAttribute(y12_kernel,   cudaFuncAttributeMaxDynamicSharedMemorySize, SMEM_BYTES);
    cudaFuncSetAttribute(node1_kernel, cudaFuncAttributeMaxDynamicSharedMemorySize, SMEM_BYTES);
    cudaFuncSetAttribute(node2_kernel, cudaFuncAttributeMaxDynamicSharedMemorySize, SMEM_BYTES);

    // one-time packs (deterministic, inside capture)
    {
        size_t t0 = (size_t)NL * 32 * 1024;
        pack_w_frag<<<(int)((t0 + 255) / 256), 256>>>(We_w, wE, 512, 516, 32, NL);
        pack_w_frag<<<(int)((t0 + 255) / 256), 256>>>(Wn1_w, wN1, 512, 512, 32, NL);
        size_t t2 = (size_t)NL * 16 * 1024;
        pack_w_frag<<<(int)((t2 + 255) / 256), 256>>>(Wn2_w, wN2, 256, 256, 16, NL);
        int nx = N * 128;
        convert_h<<<(nx + 255) / 256, 256>>>(x_in, xs, nx);
    }

    const int nblk_n = (N + 63) / 64;
    const int nblk_e = (D + 7) / 8;
    const int n4h = (N * 128) / 4;            // aggs zero (uint32 count / 4)
    const int zblk = (n4h + 255) / 256;

    const float* xcur = x_in;
    for (int l = 0; l < NL; l++) {
        float* xnext = (l == NL - 1) ? (float*)d_out : ((l & 1) ? bufB : bufA);
        zero_kernel<<<zblk, 256>>>((float4*)aggs, n4h);
        y12_kernel<<<dim3(nblk_n, 2), 256, SMEM_BYTES>>>(
            xs, wE + (size_t)l * 32 * 1024, y1h, y2h, N);
        edge_pass<<<nblk_e, 256>>>(
            y1h, y2h, eidx, ea,
            We_w + (size_t)l * 516 * 256 + (size_t)512 * 256,
            We_b + (size_t)l * 256, g1 + (size_t)l * 256, b1 + (size_t)l * 256,
            aggs, D);
        node1_kernel<<<nblk_n, 256, SMEM_BYTES>>>(
            xs, aggs, wN1 + (size_t)l * 32 * 1024,
            Wn1_b + (size_t)l * 256, g2 + (size_t)l * 256, b2 + (size_t)l * 256,
            tmps, N);
        node2_kernel<<<nblk_n, 256, SMEM_BYTES>>>(
            tmps, xcur, wN2 + (size_t)l * 16 * 1024,
            Wn2_b + (size_t)l * 256, xnext, xs, N);
        xcur = xnext;
    }
}

// round 11
// speedup vs baseline: 1.0067x; 1.0067x over previous
#include <cuda_runtime.h>
#include <cuda_fp16.h>
#include <cstdint>

// ============================================================================
// GraphCastProcessor — fp16 weight-split mma.sync GEMMs (2 MMAs/k16).
// y1/y2 stored fp16x2 (halved edge-read traffic); agg accumulated in fp32 via
// red.global.add.v4.f32 (proven fast), then converted to fp16 for node1.
//   y1 = x@We[:256], y2 = x@We[256:512]          (fp16x2 out)
//   h_e = y1[dst]+y2[src]+ea@W3+b ; msg = silu(LN(h)); agg += msg (f32 RED)
//   u = x@Wn1[:256]+agg@Wn1[256:]+b ; t = silu(LN(u))
//   x = x + t@Wn2 + b2
// ============================================================================

#define MAXN 40962
#define MAXD 163848
#define MAXNL 6

__device__ float g_bufA[MAXN * 256];
__device__ float g_bufB[MAXN * 256];
__device__ float g_agg [MAXN * 256];
__device__ uint32_t g_y1h [MAXN * 128];   // fp16x2 rows (512B)
__device__ uint32_t g_y2h [MAXN * 128];
__device__ uint32_t g_xs  [MAXN * 128];   // fp16x2 activations
__device__ uint32_t g_aggs[MAXN * 128];
__device__ uint32_t g_tmps[MAXN * 128];
// fragment-ordered split weights: [layer][chunk16][wn(4)][nt(8)][lane(32)]
// uint4 = {hi_k0pair, hi_k1pair, lo_k0pair, lo_k1pair}
__device__ uint4 g_We [MAXNL * 32 * 1024];
__device__ uint4 g_Wn1[MAXNL * 32 * 1024];
__device__ uint4 g_Wn2[MAXNL * 16 * 1024];

// ---- dynamic smem layout (bytes) ----
#define SA_OFF    0                       // u32 sA[2][64][20] = 10240 (80B row)
#define SB_OFF    10240                   // uint4 sB[2][2048] = 65536 -> 75776
#define SOUT_OFF  0                       // float sOut[64][260] = 66560 (aliases)
#define SBIAS_OFF 75776
#define SG_OFF    76800
#define SBV_OFF   77824
#define MBAR_OFF  78848                   // 2 x u64
#define SMEM_BYTES 78880

__device__ __forceinline__ float fast_silu(float y) {
    return __fdividef(y, 1.0f + __expf(-y));
}

__device__ __forceinline__ uint32_t packh(float a, float b) {
    __half2 h = __floats2half2_rn(a, b);
    return *(uint32_t*)&h;
}
__device__ __forceinline__ float2 unpackh(uint32_t u) {
    __half2 h = *(__half2*)&u;
    return __half22float2(h);
}
__device__ __forceinline__ uint2 wsplit(float a, float b) {
    __half h0 = __float2half_rn(a);
    __half h1 = __float2half_rn(b);
    __half l0 = __float2half_rn(a - __half2float(h0));
    __half l1 = __float2half_rn(b - __half2float(h1));
    uint2 r;
    r.x = (uint32_t)__half_as_ushort(h0) | ((uint32_t)__half_as_ushort(h1) << 16);
    r.y = (uint32_t)__half_as_ushort(l0) | ((uint32_t)__half_as_ushort(l1) << 16);
    return r;
}

__device__ __forceinline__ void mma_f16(float c[4], const uint32_t a[4],
                                        uint32_t b0, uint32_t b1) {
    asm volatile(
        "mma.sync.aligned.m16n8k16.row.col.f32.f16.f16.f32 "
        "{%0,%1,%2,%3}, {%4,%5,%6,%7}, {%8,%9}, {%0,%1,%2,%3};"
        : "+f"(c[0]), "+f"(c[1]), "+f"(c[2]), "+f"(c[3])
        : "r"(a[0]), "r"(a[1]), "r"(a[2]), "r"(a[3]), "r"(b0), "r"(b1));
}

__device__ __forceinline__ void red_v4(float* p, float a, float b, float c, float d) {
    asm volatile("red.global.add.v4.f32 [%0], {%1,%2,%3,%4};"
                 :: "l"(p), "f"(a), "f"(b), "f"(c), "f"(d) : "memory");
}

__device__ __forceinline__ void cp16(uint32_t smem_dst, const void* gsrc) {
    asm volatile("cp.async.cg.shared.global [%0], [%1], 16;\n"
                 :: "r"(smem_dst), "l"(gsrc));
}
#define CP_COMMIT() asm volatile("cp.async.commit_group;\n" ::: "memory")
#define CP_WAIT(n)  asm volatile("cp.async.wait_group %0;\n" :: "n"(n) : "memory")

__device__ __forceinline__ void mbar_init(uint32_t mbar, uint32_t count) {
    asm volatile("mbarrier.init.shared.b64 [%0], %1;" :: "r"(mbar), "r"(count) : "memory");
}
__device__ __forceinline__ void mbar_expect_tx(uint32_t mbar, uint32_t bytes) {
    asm volatile("mbarrier.arrive.expect_tx.shared.b64 _, [%0], %1;"
                 :: "r"(mbar), "r"(bytes) : "memory");
}
__device__ __forceinline__ void mbar_wait(uint32_t mbar, uint32_t parity) {
    asm volatile(
        "{\n\t.reg .pred P1;\n\t"
        "WAIT_LOOP_%=:\n\t"
        "mbarrier.try_wait.parity.acquire.cta.shared::cta.b64 P1, [%0], %1, 0x989680;\n\t"
        "@P1 bra.uni WAIT_DONE_%=;\n\t"
        "bra.uni WAIT_LOOP_%=;\n\t"
        "WAIT_DONE_%=:\n\t}"
        :: "r"(mbar), "r"(parity) : "memory");
}
__device__ __forceinline__ void bulk_cp(uint32_t smem_dst, const void* gsrc,
                                        uint32_t bytes, uint32_t mbar) {
    asm volatile(
        "cp.async.bulk.shared::cta.global.mbarrier::complete_tx::bytes [%0], [%1], %2, [%3];"
        :: "r"(smem_dst), "l"(gsrc), "r"(bytes), "r"(mbar) : "memory");
}

// LN(256)+SiLU; row spread as 8 vals/lane (cols tx*4+j / 128+tx*4+j-4)
__device__ __forceinline__ void ln_silu_row(float v[8], int tx,
                                            const float* sG, const float* sB) {
    float s = v[0] + v[1] + v[2] + v[3] + v[4] + v[5] + v[6] + v[7];
#pragma unroll
    for (int o = 16; o > 0; o >>= 1) s += __shfl_xor_sync(0xffffffffu, s, o);
    float mean = s * (1.0f / 256.0f);
    float vs = 0.f;
#pragma unroll
    for (int j = 0; j < 8; j++) { float d = v[j] - mean; vs += d * d; }
#pragma unroll
    for (int o = 16; o > 0; o >>= 1) vs += __shfl_xor_sync(0xffffffffu, vs, o);
    float rstd = rsqrtf(vs * (1.0f / 256.0f) + 1e-5f);
#pragma unroll
    for (int j = 0; j < 8; j++) {
        int col = (j < 4) ? (tx * 4 + j) : (128 + tx * 4 + j - 4);
        float y = (v[j] - mean) * rstd * sG[col] + sB[col];
        v[j] = fast_silu(y);
    }
}

// one K32 superchunk: two k16 halves, 2 MMAs each (xh*wh + xh*wl)
__device__ __forceinline__ void compute_schunk(const char* smraw, int buf,
                                               int wm, int wn, int lane,
                                               float acc[2][8][4]) {
    const uint32_t* sAp = (const uint32_t*)(smraw + SA_OFF + buf * 5120);
    const uint4* sBp = (const uint4*)(smraw + SB_OFF + buf * 32768);
    const int q = lane & 3;
#pragma unroll
    for (int h = 0; h < 2; h++) {
        uint32_t a[2][4];
#pragma unroll
        for (int mt = 0; mt < 2; mt++) {
            int r = wm * 32 + mt * 16 + (lane >> 2);
            a[mt][0] = sAp[r * 20 + h * 8 + q];
            a[mt][1] = sAp[(r + 8) * 20 + h * 8 + q];
            a[mt][2] = sAp[r * 20 + h * 8 + q + 4];
            a[mt][3] = sAp[(r + 8) * 20 + h * 8 + q + 4];
        }
#pragma unroll
        for (int nt = 0; nt < 8; nt++) {
            uint4 b = sBp[h * 1024 + wn * 256 + nt * 32 + lane];
#pragma unroll
            for (int mt = 0; mt < 2; mt++) {
                mma_f16(acc[mt][nt], a[mt], b.x, b.y);
                mma_f16(acc[mt][nt], a[mt], b.z, b.w);
            }
        }
    }
}

template <typename FA>
__device__ __forceinline__ void gemm_pipeline(FA stageA, const uint4* __restrict__ Wp,
                                              char* smraw, uint32_t sbase, int tid,
                                              int wm, int wn, int lane, int schunks,
                                              float acc[2][8][4]) {
    const uint32_t mbar0 = sbase + MBAR_OFF;
    auto issueB = [&](int c, int buf) {
        if (tid == 0) {
            uint32_t mb = mbar0 + buf * 8;
            mbar_expect_tx(mb, 32768);
            bulk_cp(sbase + SB_OFF + buf * 32768, Wp + (size_t)c * 2048, 32768, mb);
        }
    };
    stageA(0, 0); CP_COMMIT(); issueB(0, 0);
#pragma unroll 1
    for (int c = 0; c < schunks; c++) {
        if (c + 1 < schunks) {
            stageA(c + 1, (c + 1) & 1); CP_COMMIT(); issueB(c + 1, (c + 1) & 1);
            CP_WAIT(1);
        } else {
            CP_WAIT(0);
        }
        mbar_wait(mbar0 + (c & 1) * 8, (c >> 1) & 1);
        __syncthreads();
        compute_schunk(smraw, c & 1, wm, wn, lane, acc);
        __syncthreads();
    }
}

__device__ __forceinline__ void acc_to_sout(char* smraw, int wm, int wn,
                                            int lane, float acc[2][8][4],
                                            const float* sBias) {
    float (*sOut)[260] = (float(*)[260])(smraw + SOUT_OFF);
#pragma unroll
    for (int mt = 0; mt < 2; mt++)
#pragma unroll
        for (int nt = 0; nt < 8; nt++) {
            int r0 = wm * 32 + mt * 16 + (lane >> 2);
            int c = wn * 64 + nt * 8 + 2 * (lane & 3);
            float b0 = sBias ? sBias[c] : 0.f;
            float b1 = sBias ? sBias[c + 1] : 0.f;
            sOut[r0][c]         = acc[mt][nt][0] + b0;
            sOut[r0][c + 1]     = acc[mt][nt][1] + b1;
            sOut[r0 + 8][c]     = acc[mt][nt][2] + b0;
            sOut[r0 + 8][c + 1] = acc[mt][nt][3] + b1;
        }
}

// ---------------------------------------------------------------------------
// packers
// ---------------------------------------------------------------------------
__global__ void pack_w_frag(const float* __restrict__ W, uint4* __restrict__ out,
                            int Ksrc, int lstride, int C, int NL) {
    size_t idx = (size_t)blockIdx.x * blockDim.x + threadIdx.x;
    size_t total = (size_t)NL * C * 1024;
    if (idx >= total) return;
    int t = (int)(idx & 1023);
    int lane = t & 31, nt = (t >> 5) & 7, wn = t >> 8;
    int c = (int)((idx >> 10) % C);
    int l = (int)(idx / ((size_t)C * 1024));
    int n = wn * 64 + nt * 8 + (lane >> 2);
    int q = lane & 3;
    int kp0 = c * 8 + q, kp1 = c * 8 + q + 4;
    const float* Wl = W + (size_t)l * lstride * 256;
    float a0 = (2 * kp0     < Ksrc) ? Wl[(size_t)(2 * kp0)     * 256 + n] : 0.f;
    float a1 = (2 * kp0 + 1 < Ksrc) ? Wl[(size_t)(2 * kp0 + 1) * 256 + n] : 0.f;
    float b0 = (2 * kp1     < Ksrc) ? Wl[(size_t)(2 * kp1)     * 256 + n] : 0.f;
    float b1 = (2 * kp1 + 1 < Ksrc) ? Wl[(size_t)(2 * kp1 + 1) * 256 + n] : 0.f;
    uint2 p0 = wsplit(a0, a1);
    uint2 p1 = wsplit(b0, b1);
    out[idx] = make_uint4(p0.x, p1.x, p0.y, p1.y);
}

__global__ void convert_h(const float* __restrict__ in, uint32_t* __restrict__ out,
                          int n) {
    int i = blockIdx.x * blockDim.x + threadIdx.x;
    if (i < n) {
        float2 v = ((const float2*)in)[i];
        out[i] = packh(v.x, v.y);
    }
}

__global__ void zero_kernel(float4* __restrict__ p, int n4) {
    int i = blockIdx.x * blockDim.x + threadIdx.x;
    if (i < n4) p[i] = make_float4(0.f, 0.f, 0.f, 0.f);
}

// ---------------------------------------------------------------------------
// y12 kernel: y = x @ We[half*256 : (half+1)*256] (no bias) -> fp16x2 rows
// ---------------------------------------------------------------------------
__global__ __launch_bounds__(256, 2) void y12_kernel(
    const uint32_t* __restrict__ xs, const uint4* __restrict__ WpBase,
    uint32_t* __restrict__ y1h, uint32_t* __restrict__ y2h, int N) {
    extern __shared__ char smraw[];
    const int tid = threadIdx.x;
    const int lane = tid & 31, warp = tid >> 5;
    const int wm = warp >> 2, wn = warp & 3;
    const int n0 = blockIdx.x * 64;
    const int half = blockIdx.y;
    const uint32_t sbase = (uint32_t)__cvta_generic_to_shared(smraw);
    const int arow = tid >> 2, apart = tid & 3;
    int rowg = n0 + arow; if (rowg >= N) rowg = N - 1;

    if (tid == 0) { mbar_init(sbase + MBAR_OFF, 1); mbar_init(sbase + MBAR_OFF + 8, 1); }
    __syncthreads();

    const uint4* Wp = WpBase + (size_t)half * 16 * 1024;
    uint32_t* yout = half ? y2h : y1h;

    float acc[2][8][4];
#pragma unroll
    for (int mt = 0; mt < 2; mt++)
#pragma unroll
        for (int nt = 0; nt < 8; nt++)
#pragma unroll
            for (int j = 0; j < 4; j++) acc[mt][nt][j] = 0.f;

    auto stageA = [&](int c, int buf) {
        const char* src = (const char*)(xs + (size_t)rowg * 128 + c * 16) + apart * 16;
        cp16(sbase + SA_OFF + buf * 5120 + arow * 80 + apart * 16, src);
    };
    gemm_pipeline(stageA, Wp, smraw, sbase, tid, wm, wn, lane, 8, acc);

    acc_to_sout(smraw, wm, wn, lane, acc, nullptr);
    __syncthreads();
    float (*sOut)[260] = (float(*)[260])(smraw + SOUT_OFF);
#pragma unroll 1
    for (int i = 0; i < 8; i++) {
        int r = i * 8 + warp;
        int row = n0 + r;
        if (row < N) {
            float v[8];
            *(float4*)&v[0] = *(float4*)&sOut[r][lane * 8];
            *(float4*)&v[4] = *(float4*)&sOut[r][lane * 8 + 4];
            uint4 o = make_uint4(packh(v[0], v[1]), packh(v[2], v[3]),
                                 packh(v[4], v[5]), packh(v[6], v[7]));
            *(uint4*)(yout + (size_t)row * 128 + lane * 4) = o;
        }
    }
}

// ---------------------------------------------------------------------------
// Edge pass: h = y1h[dst]+y2h[src]+ea@W3+b; silu(LN(h)) -> f32 red.v4 into agg
// one edge per warp, 8 edges per block; lane owns cols lane*8..lane*8+7
// ---------------------------------------------------------------------------
__global__ __launch_bounds__(256) void edge_pass(
    const uint32_t* __restrict__ y1h, const uint32_t* __restrict__ y2h,
    const int* __restrict__ eidx, const float* __restrict__ ea,
    const float* __restrict__ W3, const float* __restrict__ Wb,
    const float* __restrict__ gam, const float* __restrict__ bet,
    float* __restrict__ agg, int D) {
    const int lane = threadIdx.x & 31, warp = threadIdx.x >> 5;
    const int e = blockIdx.x * 8 + warp;

    float w3r[4][8], biasr[8], gr[8], br[8];
#pragma unroll
    for (int j = 0; j < 8; j++) {
        int col = lane * 8 + j;
        biasr[j] = __ldg(Wb + col);
        gr[j] = __ldg(gam + col);
        br[j] = __ldg(bet + col);
#pragma unroll
        for (int k = 0; k < 4; k++) w3r[k][j] = __ldg(W3 + k * 256 + col);
    }
    if (e >= D) return;

    int src = __ldg(eidx + e);
    int dst = __ldg(eidx + (size_t)D + e);
    uint4 u1 = *(const uint4*)(y1h + (size_t)dst * 128 + lane * 4);
    uint4 u2 = *(const uint4*)(y2h + (size_t)src * 128 + lane * 4);
    float4 eav = *(const float4*)(ea + (size_t)e * 4);

    float v[8];
    {
        float2 a0 = unpackh(u1.x), a1 = unpackh(u1.y), a2 = unpackh(u1.z), a3 = unpackh(u1.w);
        float2 c0 = unpackh(u2.x), c1 = unpackh(u2.y), c2 = unpackh(u2.z), c3 = unpackh(u2.w);
        v[0] = a0.x + c0.x; v[1] = a0.y + c0.y;
        v[2] = a1.x + c1.x; v[3] = a1.y + c1.y;
        v[4] = a2.x + c2.x; v[5] = a2.y + c2.y;
        v[6] = a3.x + c3.x; v[7] = a3.y + c3.y;
    }
#pragma unroll
    for (int j = 0; j < 8; j++) {
        float h = v[j] + biasr[j];
        h = fmaf(eav.x, w3r[0][j], h);
        h = fmaf(eav.y, w3r[1][j], h);
        h = fmaf(eav.z, w3r[2][j], h);
        h = fmaf(eav.w, w3r[3][j], h);
        v[j] = h;
    }
    float s = v[0] + v[1] + v[2] + v[3] + v[4] + v[5] + v[6] + v[7];
#pragma unroll
    for (int o = 16; o > 0; o >>= 1) s += __shfl_xor_sync(0xffffffffu, s, o);
    float mean = s * (1.0f / 256.0f);
    float vs = 0.f;
#pragma unroll
    for (int j = 0; j < 8; j++) { float d = v[j] - mean; vs += d * d; }
#pragma unroll
    for (int o = 16; o > 0; o >>= 1) vs += __shfl_xor_sync(0xffffffffu, vs, o);
    float rstd = rsqrtf(vs * (1.0f / 256.0f) + 1e-5f);

    float m[8];
#pragma unroll
    for (int j = 0; j < 8; j++)
        m[j] = fast_silu((v[j] - mean) * rstd * gr[j] + br[j]);

    float* ag = agg + (size_t)dst * 256;
    red_v4(ag + lane * 8,     m[0], m[1], m[2], m[3]);
    red_v4(ag + lane * 8 + 4, m[4], m[5], m[6], m[7]);
}

// ---------------------------------------------------------------------------
// Node kernel 1: t = silu(LN(x@Wn1[:256] + aggs@Wn1[256:] + b)) -> tmps (fp16)
// ---------------------------------------------------------------------------
__global__ __launch_bounds__(256, 2) void node1_kernel(
    const uint32_t* __restrict__ xs, const uint32_t* __restrict__ aggs,
    const uint4* __restrict__ Wp, const float* __restrict__ Wb,
    const float* __restrict__ gam, const float* __restrict__ bet,
    uint32_t* __restrict__ tmps, int N) {
    extern __shared__ char smraw[];
    float* sBias = (float*)(smraw + SBIAS_OFF);
    float* sG    = (float*)(smraw + SG_OFF);
    float* sBv   = (float*)(smraw + SBV_OFF);

    const int tid = threadIdx.x;
    const int lane = tid & 31, warp = tid >> 5;
    const int wm = warp >> 2, wn = warp & 3;
    const int n0 = blockIdx.x * 64;
    const uint32_t sbase = (uint32_t)__cvta_generic_to_shared(smraw);
    const int arow = tid >> 2, apart = tid & 3;

    sBias[tid] = Wb[tid]; sG[tid] = gam[tid]; sBv[tid] = bet[tid];
    if (tid == 0) { mbar_init(sbase + MBAR_OFF, 1); mbar_init(sbase + MBAR_OFF + 8, 1); }
    __syncthreads();

    int rowg = n0 + arow; if (rowg >= N) rowg = N - 1;

    float acc[2][8][4];
#pragma unroll
    for (int mt = 0; mt < 2; mt++)
#pragma unroll
        for (int nt = 0; nt < 8; nt++)
#pragma unroll
            for (int j = 0; j < 4; j++) acc[mt][nt][j] = 0.f;

    auto stageA = [&](int c, int buf) {
        const uint32_t* bA = (c < 8) ? xs : aggs;
        const char* src = (const char*)(bA + (size_t)rowg * 128 + (c & 7) * 16) + apart * 16;
        cp16(sbase + SA_OFF + buf * 5120 + arow * 80 + apart * 16, src);
    };
    gemm_pipeline(stageA, Wp, smraw, sbase, tid, wm, wn, lane, 16, acc);

    acc_to_sout(smraw, wm, wn, lane, acc, sBias);
    __syncthreads();
    float (*sOut)[260] = (float(*)[260])(smraw + SOUT_OFF);
#pragma unroll 1
    for (int i = 0; i < 8; i++) {
        int r = i * 8 + warp;
        float vv[8];
        *(float4*)&vv[0] = *(float4*)&sOut[r][lane * 4];
        *(float4*)&vv[4] = *(float4*)&sOut[r][128 + lane * 4];
        ln_silu_row(vv, lane, sG, sBv);
        int row = n0 + r;
        if (row < N) {
            uint32_t* op = tmps + (size_t)row * 128;
            op[lane * 2]          = packh(vv[0], vv[1]);
            op[lane * 2 + 1]      = packh(vv[2], vv[3]);
            op[64 + lane * 2]     = packh(vv[4], vv[5]);
            op[64 + lane * 2 + 1] = packh(vv[6], vv[7]);
        }
    }
}

// ---------------------------------------------------------------------------
// Node kernel 2: out = x + t@Wn2 + b2; also writes fp16 xs for next layer
// ---------------------------------------------------------------------------
__global__ __launch_bounds__(256, 2) void node2_kernel(
    const uint32_t* __restrict__ tmps, const float* __restrict__ xres,
    const uint4* __restrict__ Wp, const float* __restrict__ Wb,
    float* __restrict__ out, uint32_t* __restrict__ xs_next, int N) {
    extern __shared__ char smraw[];
    float* sBias = (float*)(smraw + SBIAS_OFF);

    const int tid = threadIdx.x;
    const int lane = tid & 31, warp = tid >> 5;
    const int wm = warp >> 2, wn = warp & 3;
    const int n0 = blockIdx.x * 64;
    const uint32_t sbase = (uint32_t)__cvta_generic_to_shared(smraw);
    const int arow = tid >> 2, apart = tid & 3;

    sBias[tid] = Wb[tid];
    if (tid == 0) { mbar_init(sbase + MBAR_OFF, 1); mbar_init(sbase + MBAR_OFF + 8, 1); }
    __syncthreads();

    int rowg = n0 + arow; if (rowg >= N) rowg = N - 1;

    float acc[2][8][4];
#pragma unroll
    for (int mt = 0; mt < 2; mt++)
#pragma unroll
        for (int nt = 0; nt < 8; nt++)
#pragma unroll
            for (int j = 0; j < 4; j++) acc[mt][nt][j] = 0.f;

    auto stageA = [&](int c, int buf) {
        const char* src = (const char*)(tmps + (size_t)rowg * 128 + c * 16) + apart * 16;
        cp16(sbase + SA_OFF + buf * 5120 + arow * 80 + apart * 16, src);
    };
    gemm_pipeline(stageA, Wp, smraw, sbase, tid, wm, wn, lane, 8, acc);

    acc_to_sout(smraw, wm, wn, lane, acc, sBias);
    __syncthreads();
    float (*sOut)[260] = (float(*)[260])(smraw + SOUT_OFF);
#pragma unroll 1
    for (int i = 0; i < 8; i++) {
        int r = i * 8 + warp;
        int row = n0 + r;
        if (row < N) {
            const float* xr = xres + (size_t)row * 256;
            float4 lo = *(float4*)&sOut[r][lane * 4];
            float4 hi = *(float4*)&sOut[r][128 + lane * 4];
            float4 xlo = *(const float4*)(xr + lane * 4);
            float4 xhi = *(const float4*)(xr + 128 + lane * 4);
            lo.x += xlo.x; lo.y += xlo.y; lo.z += xlo.z; lo.w += xlo.w;
            hi.x += xhi.x; hi.y += xhi.y; hi.z += xhi.z; hi.w += xhi.w;
            float* op = out + (size_t)row * 256;
            *(float4*)(op + lane * 4) = lo;
            *(float4*)(op + 128 + lane * 4) = hi;
            uint32_t* xp = xs_next + (size_t)row * 128;
            xp[lane * 2]          = packh(lo.x, lo.y);
            xp[lane * 2 + 1]      = packh(lo.z, lo.w);
            xp[64 + lane * 2]     = packh(hi.x, hi.y);
            xp[64 + lane * 2 + 1] = packh(hi.z, hi.w);
        }
    }
}

// ---------------------------------------------------------------------------
extern "C" void kernel_launch(void* const* d_in, const int* in_sizes, int n_in,
                              void* d_out, int out_size) {
    const float* x_in  = (const float*)d_in[0];
    const int*   eidx  = (const int*)d_in[1];
    const float* ea    = (const float*)d_in[2];
    const float* We_w  = (const float*)d_in[3];
    const float* We_b  = (const float*)d_in[4];
    const float* g1    = (const float*)d_in[5];
    const float* b1    = (const float*)d_in[6];
    const float* Wn1_w = (const float*)d_in[7];
    const float* Wn1_b = (const float*)d_in[8];
    const float* g2    = (const float*)d_in[9];
    const float* b2    = (const float*)d_in[10];
    const float* Wn2_w = (const float*)d_in[11];
    const float* Wn2_b = (const float*)d_in[12];

    const int N  = in_sizes[0] / 256;
    const int D  = in_sizes[1] / 2;
    const int NL = in_sizes[4] / 256;

    float *bufA, *bufB, *aggp;
    uint32_t *y1h, *y2h, *xs, *aggs, *tmps;
    uint4 *wE, *wN1, *wN2;
    cudaGetSymbolAddress((void**)&bufA, g_bufA);
    cudaGetSymbolAddress((void**)&bufB, g_bufB);
    cudaGetSymbolAddress((void**)&aggp, g_agg);
    cudaGetSymbolAddress((void**)&y1h,  g_y1h);
    cudaGetSymbolAddress((void**)&y2h,  g_y2h);
    cudaGetSymbolAddress((void**)&xs,   g_xs);
    cudaGetSymbolAddress((void**)&aggs, g_aggs);
    cudaGetSymbolAddress((void**)&tmps, g_tmps);
    cudaGetSymbolAddress((void**)&wE,   g_We);
    cudaGetSymbolAddress((void**)&wN1,  g_Wn1);
    cudaGetSymbolAddress((void**)&wN2,  g_Wn2);

    cudaFuncSetAttribute(y12_kernel,   cudaFuncAttributeMaxDynamicSharedMemorySize, SMEM_BYTES);
    cudaFuncSetAttribute(node1_kernel, cudaFuncAttributeMaxDynamicSharedMemorySize, SMEM_BYTES);
    cudaFuncSetAttribute(node2_kernel, cudaFuncAttributeMaxDynamicSharedMemorySize, SMEM_BYTES);

    // one-time packs (deterministic, inside capture)
    {
        size_t t0 = (size_t)NL * 32 * 1024;
        pack_w_frag<<<(int)((t0 + 255) / 256), 256>>>(We_w, wE, 512, 516, 32, NL);
        pack_w_frag<<<(int)((t0 + 255) / 256), 256>>>(Wn1_w, wN1, 512, 512, 32, NL);
        size_t t2 = (size_t)NL * 16 * 1024;
        pack_w_frag<<<(int)((t2 + 255) / 256), 256>>>(Wn2_w, wN2, 256, 256, 16, NL);
        int nx = N * 128;
        convert_h<<<(nx + 255) / 256, 256>>>(x_in, xs, nx);
    }

    const int nblk_n = (N + 63) / 64;
    const int nblk_e = (D + 7) / 8;
    const int n4 = (N * 256) / 4;
    const int zblk = (n4 + 255) / 256;
    const int ncv = N * 128;
    const int cvblk = (ncv + 255) / 256;

    const float* xcur = x_in;
    for (int l = 0; l < NL; l++) {
        float* xnext = (l == NL - 1) ? (float*)d_out : ((l & 1) ? bufB : bufA);
        zero_kernel<<<zblk, 256>>>((float4*)aggp, n4);
        y12_kernel<<<dim3(nblk_n, 2), 256, SMEM_BYTES>>>(
            xs, wE + (size_t)l * 32 * 1024, y1h, y2h, N);
        edge_pass<<<nblk_e, 256>>>(
            y1h, y2h, eidx, ea,
            We_w + (size_t)l * 516 * 256 + (size_t)512 * 256,
            We_b + (size_t)l * 256, g1 + (size_t)l * 256, b1 + (size_t)l * 256,
            aggp, D);
        convert_h<<<cvblk, 256>>>(aggp, aggs, ncv);
        node1_kernel<<<nblk_n, 256, SMEM_BYTES>>>(
            xs, aggs, wN1 + (size_t)l * 32 * 1024,
            Wn1_b + (size_t)l * 256, g2 + (size_t)l * 256, b2 + (size_t)l * 256,
            tmps, N);
        node2_kernel<<<nblk_n, 256, SMEM_BYTES>>>(
            tmps, xcur, wN2 + (size_t)l * 16 * 1024,
            Wn2_b + (size_t)l * 256, xnext, xs, N);
        xcur = xnext;
    }
}

// round 12
// speedup vs baseline: 1.3617x; 1.3526x over previous
#include <cuda_runtime.h>
#include <cuda_fp16.h>
#include <cstdint>

// ============================================================================
// GraphCastProcessor — fp16 weight-split mma.sync GEMMs (2 MMAs/k16).
// y1/y2 stored fp16x2 (halved edge-read traffic); edge pass uses the R9
// contiguous-RED column layout (lane*4 / 128+lane*4) with fp32 red.v4.
//   y1 = x@We[:256], y2 = x@We[256:512]          (fp16x2 out)
//   h_e = y1[dst]+y2[src]+ea@W3+b ; msg = silu(LN(h)); agg += msg (f32 RED)
//   u = x@Wn1[:256]+agg@Wn1[256:]+b ; t = silu(LN(u))
//   x = x + t@Wn2 + b2
// ============================================================================

#define MAXN 40962
#define MAXD 163848
#define MAXNL 6

__device__ float g_bufA[MAXN * 256];
__device__ float g_bufB[MAXN * 256];
__device__ float g_agg [MAXN * 256];
__device__ uint32_t g_y1h [MAXN * 128];   // fp16x2 rows (512B)
__device__ uint32_t g_y2h [MAXN * 128];
__device__ uint32_t g_xs  [MAXN * 128];   // fp16x2 activations
__device__ uint32_t g_aggs[MAXN * 128];
__device__ uint32_t g_tmps[MAXN * 128];
// fragment-ordered split weights: [layer][chunk16][wn(4)][nt(8)][lane(32)]
// uint4 = {hi_k0pair, hi_k1pair, lo_k0pair, lo_k1pair}
__device__ uint4 g_We [MAXNL * 32 * 1024];
__device__ uint4 g_Wn1[MAXNL * 32 * 1024];
__device__ uint4 g_Wn2[MAXNL * 16 * 1024];

// ---- dynamic smem layout (bytes) ----
#define SA_OFF    0                       // u32 sA[2][64][20] = 10240 (80B row)
#define SB_OFF    10240                   // uint4 sB[2][2048] = 65536 -> 75776
#define SOUT_OFF  0                       // float sOut[64][260] = 66560 (aliases)
#define SBIAS_OFF 75776
#define SG_OFF    76800
#define SBV_OFF   77824
#define MBAR_OFF  78848                   // 2 x u64
#define SMEM_BYTES 78880

__device__ __forceinline__ float fast_silu(float y) {
    return __fdividef(y, 1.0f + __expf(-y));
}

__device__ __forceinline__ uint32_t packh(float a, float b) {
    __half2 h = __floats2half2_rn(a, b);
    return *(uint32_t*)&h;
}
__device__ __forceinline__ float2 unpackh(uint32_t u) {
    __half2 h = *(__half2*)&u;
    return __half22float2(h);
}
__device__ __forceinline__ uint2 wsplit(float a, float b) {
    __half h0 = __float2half_rn(a);
    __half h1 = __float2half_rn(b);
    __half l0 = __float2half_rn(a - __half2float(h0));
    __half l1 = __float2half_rn(b - __half2float(h1));
    uint2 r;
    r.x = (uint32_t)__half_as_ushort(h0) | ((uint32_t)__half_as_ushort(h1) << 16);
    r.y = (uint32_t)__half_as_ushort(l0) | ((uint32_t)__half_as_ushort(l1) << 16);
    return r;
}

__device__ __forceinline__ void mma_f16(float c[4], const uint32_t a[4],
                                        uint32_t b0, uint32_t b1) {
    asm volatile(
        "mma.sync.aligned.m16n8k16.row.col.f32.f16.f16.f32 "
        "{%0,%1,%2,%3}, {%4,%5,%6,%7}, {%8,%9}, {%0,%1,%2,%3};"
        : "+f"(c[0]), "+f"(c[1]), "+f"(c[2]), "+f"(c[3])
        : "r"(a[0]), "r"(a[1]), "r"(a[2]), "r"(a[3]), "r"(b0), "r"(b1));
}

__device__ __forceinline__ void red_v4(float* p, float a, float b, float c, float d) {
    asm volatile("red.global.add.v4.f32 [%0], {%1,%2,%3,%4};"
                 :: "l"(p), "f"(a), "f"(b), "f"(c), "f"(d) : "memory");
}

__device__ __forceinline__ void cp16(uint32_t smem_dst, const void* gsrc) {
    asm volatile("cp.async.cg.shared.global [%0], [%1], 16;\n"
                 :: "r"(smem_dst), "l"(gsrc));
}
#define CP_COMMIT() asm volatile("cp.async.commit_group;\n" ::: "memory")
#define CP_WAIT(n)  asm volatile("cp.async.wait_group %0;\n" :: "n"(n) : "memory")

__device__ __forceinline__ void mbar_init(uint32_t mbar, uint32_t count) {
    asm volatile("mbarrier.init.shared.b64 [%0], %1;" :: "r"(mbar), "r"(count) : "memory");
}
__device__ __forceinline__ void mbar_expect_tx(uint32_t mbar, uint32_t bytes) {
    asm volatile("mbarrier.arrive.expect_tx.shared.b64 _, [%0], %1;"
                 :: "r"(mbar), "r"(bytes) : "memory");
}
__device__ __forceinline__ void mbar_wait(uint32_t mbar, uint32_t parity) {
    asm volatile(
        "{\n\t.reg .pred P1;\n\t"
        "WAIT_LOOP_%=:\n\t"
        "mbarrier.try_wait.parity.acquire.cta.shared::cta.b64 P1, [%0], %1, 0x989680;\n\t"
        "@P1 bra.uni WAIT_DONE_%=;\n\t"
        "bra.uni WAIT_LOOP_%=;\n\t"
        "WAIT_DONE_%=:\n\t}"
        :: "r"(mbar), "r"(parity) : "memory");
}
__device__ __forceinline__ void bulk_cp(uint32_t smem_dst, const void* gsrc,
                                        uint32_t bytes, uint32_t mbar) {
    asm volatile(
        "cp.async.bulk.shared::cta.global.mbarrier::complete_tx::bytes [%0], [%1], %2, [%3];"
        :: "r"(smem_dst), "l"(gsrc), "r"(bytes), "r"(mbar) : "memory");
}

// LN(256)+SiLU; row spread as 8 vals/lane (cols tx*4+j / 128+tx*4+j-4)
__device__ __forceinline__ void ln_silu_row(float v[8], int tx,
                                            const float* sG, const float* sB) {
    float s = v[0] + v[1] + v[2] + v[3] + v[4] + v[5] + v[6] + v[7];
#pragma unroll
    for (int o = 16; o > 0; o >>= 1) s += __shfl_xor_sync(0xffffffffu, s, o);
    float mean = s * (1.0f / 256.0f);
    float vs = 0.f;
#pragma unroll
    for (int j = 0; j < 8; j++) { float d = v[j] - mean; vs += d * d; }
#pragma unroll
    for (int o = 16; o > 0; o >>= 1) vs += __shfl_xor_sync(0xffffffffu, vs, o);
    float rstd = rsqrtf(vs * (1.0f / 256.0f) + 1e-5f);
#pragma unroll
    for (int j = 0; j < 8; j++) {
        int col = (j < 4) ? (tx * 4 + j) : (128 + tx * 4 + j - 4);
        float y = (v[j] - mean) * rstd * sG[col] + sB[col];
        v[j] = fast_silu(y);
    }
}

// one K32 superchunk: two k16 halves, 2 MMAs each (xh*wh + xh*wl)
__device__ __forceinline__ void compute_schunk(const char* smraw, int buf,
                                               int wm, int wn, int lane,
                                               float acc[2][8][4]) {
    const uint32_t* sAp = (const uint32_t*)(smraw + SA_OFF + buf * 5120);
    const uint4* sBp = (const uint4*)(smraw + SB_OFF + buf * 32768);
    const int q = lane & 3;
#pragma unroll
    for (int h = 0; h < 2; h++) {
        uint32_t a[2][4];
#pragma unroll
        for (int mt = 0; mt < 2; mt++) {
            int r = wm * 32 + mt * 16 + (lane >> 2);
            a[mt][0] = sAp[r * 20 + h * 8 + q];
            a[mt][1] = sAp[(r + 8) * 20 + h * 8 + q];
            a[mt][2] = sAp[r * 20 + h * 8 + q + 4];
            a[mt][3] = sAp[(r + 8) * 20 + h * 8 + q + 4];
        }
#pragma unroll
        for (int nt = 0; nt < 8; nt++) {
            uint4 b = sBp[h * 1024 + wn * 256 + nt * 32 + lane];
#pragma unroll
            for (int mt = 0; mt < 2; mt++) {
                mma_f16(acc[mt][nt], a[mt], b.x, b.y);
                mma_f16(acc[mt][nt], a[mt], b.z, b.w);
            }
        }
    }
}

template <typename FA>
__device__ __forceinline__ void gemm_pipeline(FA stageA, const uint4* __restrict__ Wp,
                                              char* smraw, uint32_t sbase, int tid,
                                              int wm, int wn, int lane, int schunks,
                                              float acc[2][8][4]) {
    const uint32_t mbar0 = sbase + MBAR_OFF;
    auto issueB = [&](int c, int buf) {
        if (tid == 0) {
            uint32_t mb = mbar0 + buf * 8;
            mbar_expect_tx(mb, 32768);
            bulk_cp(sbase + SB_OFF + buf * 32768, Wp + (size_t)c * 2048, 32768, mb);
        }
    };
    stageA(0, 0); CP_COMMIT(); issueB(0, 0);
#pragma unroll 1
    for (int c = 0; c < schunks; c++) {
        if (c + 1 < schunks) {
            stageA(c + 1, (c + 1) & 1); CP_COMMIT(); issueB(c + 1, (c + 1) & 1);
            CP_WAIT(1);
        } else {
            CP_WAIT(0);
        }
        mbar_wait(mbar0 + (c & 1) * 8, (c >> 1) & 1);
        __syncthreads();
        compute_schunk(smraw, c & 1, wm, wn, lane, acc);
        __syncthreads();
    }
}

__device__ __forceinline__ void acc_to_sout(char* smraw, int wm, int wn,
                                            int lane, float acc[2][8][4],
                                            const float* sBias) {
    float (*sOut)[260] = (float(*)[260])(smraw + SOUT_OFF);
#pragma unroll
    for (int mt = 0; mt < 2; mt++)
#pragma unroll
        for (int nt = 0; nt < 8; nt++) {
            int r0 = wm * 32 + mt * 16 + (lane >> 2);
            int c = wn * 64 + nt * 8 + 2 * (lane & 3);
            float b0 = sBias ? sBias[c] : 0.f;
            float b1 = sBias ? sBias[c + 1] : 0.f;
            sOut[r0][c]         = acc[mt][nt][0] + b0;
            sOut[r0][c + 1]     = acc[mt][nt][1] + b1;
            sOut[r0 + 8][c]     = acc[mt][nt][2] + b0;
            sOut[r0 + 8][c + 1] = acc[mt][nt][3] + b1;
        }
}

// ---------------------------------------------------------------------------
// packers
// ---------------------------------------------------------------------------
__global__ void pack_w_frag(const float* __restrict__ W, uint4* __restrict__ out,
                            int Ksrc, int lstride, int C, int NL) {
    size_t idx = (size_t)blockIdx.x * blockDim.x + threadIdx.x;
    size_t total = (size_t)NL * C * 1024;
    if (idx >= total) return;
    int t = (int)(idx & 1023);
    int lane = t & 31, nt = (t >> 5) & 7, wn = t >> 8;
    int c = (int)((idx >> 10) % C);
    int l = (int)(idx / ((size_t)C * 1024));
    int n = wn * 64 + nt * 8 + (lane >> 2);
    int q = lane & 3;
    int kp0 = c * 8 + q, kp1 = c * 8 + q + 4;
    const float* Wl = W + (size_t)l * lstride * 256;
    float a0 = (2 * kp0     < Ksrc) ? Wl[(size_t)(2 * kp0)     * 256 + n] : 0.f;
    float a1 = (2 * kp0 + 1 < Ksrc) ? Wl[(size_t)(2 * kp0 + 1) * 256 + n] : 0.f;
    float b0 = (2 * kp1     < Ksrc) ? Wl[(size_t)(2 * kp1)     * 256 + n] : 0.f;
    float b1 = (2 * kp1 + 1 < Ksrc) ? Wl[(size_t)(2 * kp1 + 1) * 256 + n] : 0.f;
    uint2 p0 = wsplit(a0, a1);
    uint2 p1 = wsplit(b0, b1);
    out[idx] = make_uint4(p0.x, p1.x, p0.y, p1.y);
}

__global__ void convert_h(const float* __restrict__ in, uint32_t* __restrict__ out,
                          int n) {
    int i = blockIdx.x * blockDim.x + threadIdx.x;
    if (i < n) {
        float2 v = ((const float2*)in)[i];
        out[i] = packh(v.x, v.y);
    }
}

__global__ void zero_kernel(float4* __restrict__ p, int n4) {
    int i = blockIdx.x * blockDim.x + threadIdx.x;
    if (i < n4) p[i] = make_float4(0.f, 0.f, 0.f, 0.f);
}

// ---------------------------------------------------------------------------
// y12 kernel: y = x @ We[half*256 : (half+1)*256] (no bias) -> fp16x2 rows
// ---------------------------------------------------------------------------
__global__ __launch_bounds__(256, 2) void y12_kernel(
    const uint32_t* __restrict__ xs, const uint4* __restrict__ WpBase,
    uint32_t* __restrict__ y1h, uint32_t* __restrict__ y2h, int N) {
    extern __shared__ char smraw[];
    const int tid = threadIdx.x;
    const int lane = tid & 31, warp = tid >> 5;
    const int wm = warp >> 2, wn = warp & 3;
    const int n0 = blockIdx.x * 64;
    const int half = blockIdx.y;
    const uint32_t sbase = (uint32_t)__cvta_generic_to_shared(smraw);
    const int arow = tid >> 2, apart = tid & 3;
    int rowg = n0 + arow; if (rowg >= N) rowg = N - 1;

    if (tid == 0) { mbar_init(sbase + MBAR_OFF, 1); mbar_init(sbase + MBAR_OFF + 8, 1); }
    __syncthreads();

    const uint4* Wp = WpBase + (size_t)half * 16 * 1024;
    uint32_t* yout = half ? y2h : y1h;

    float acc[2][8][4];
#pragma unroll
    for (int mt = 0; mt < 2; mt++)
#pragma unroll
        for (int nt = 0; nt < 8; nt++)
#pragma unroll
            for (int j = 0; j < 4; j++) acc[mt][nt][j] = 0.f;

    auto stageA = [&](int c, int buf) {
        const char* src = (const char*)(xs + (size_t)rowg * 128 + c * 16) + apart * 16;
        cp16(sbase + SA_OFF + buf * 5120 + arow * 80 + apart * 16, src);
    };
    gemm_pipeline(stageA, Wp, smraw, sbase, tid, wm, wn, lane, 8, acc);

    acc_to_sout(smraw, wm, wn, lane, acc, nullptr);
    __syncthreads();
    float (*sOut)[260] = (float(*)[260])(smraw + SOUT_OFF);
#pragma unroll 1
    for (int i = 0; i < 8; i++) {
        int r = i * 8 + warp;
        int row = n0 + r;
        if (row < N) {
            // pack in R9 column order: words 0..63 = cols 0..127, 64..127 = 128..255
            float4 lo = *(float4*)&sOut[r][lane * 4];
            float4 hi = *(float4*)&sOut[r][128 + lane * 4];
            uint32_t* op = yout + (size_t)row * 128;
            *(uint2*)(op + lane * 2)      = make_uint2(packh(lo.x, lo.y), packh(lo.z, lo.w));
            *(uint2*)(op + 64 + lane * 2) = make_uint2(packh(hi.x, hi.y), packh(hi.z, hi.w));
        }
    }
}

// ---------------------------------------------------------------------------
// Edge pass: h = y1h[dst]+y2h[src]+ea@W3+b; silu(LN(h)) -> f32 red.v4 into agg
// R9 layout: lane owns cols lane*4+j (j<4) and 128+lane*4+(j-4); contiguous REDs
// ---------------------------------------------------------------------------
__global__ __launch_bounds__(256) void edge_pass(
    const uint32_t* __restrict__ y1h, const uint32_t* __restrict__ y2h,
    const int* __restrict__ eidx, const float* __restrict__ ea,
    const float* __restrict__ W3, const float* __restrict__ Wb,
    const float* __restrict__ gam, const float* __restrict__ bet,
    float* __restrict__ agg, int D) {
    const int lane = threadIdx.x & 31, warp = threadIdx.x >> 5;
    const int e = blockIdx.x * 8 + warp;

    float w3r[4][8], biasr[8], gr[8], br[8];
#pragma unroll
    for (int j = 0; j < 8; j++) {
        int col = (j < 4) ? (lane * 4 + j) : (128 + lane * 4 + j - 4);
        biasr[j] = __ldg(Wb + col);
        gr[j] = __ldg(gam + col);
        br[j] = __ldg(bet + col);
#pragma unroll
        for (int k = 0; k < 4; k++) w3r[k][j] = __ldg(W3 + k * 256 + col);
    }
    if (e >= D) return;

    int src = __ldg(eidx + e);
    int dst = __ldg(eidx + (size_t)D + e);
    // fp16x2 words: cols lane*4..lane*4+3 = words lane*2, lane*2+1;
    //               cols 128+lane*4..+3   = words 64+lane*2, 64+lane*2+1
    uint2 u1lo = *(const uint2*)(y1h + (size_t)dst * 128 + lane * 2);
    uint2 u1hi = *(const uint2*)(y1h + (size_t)dst * 128 + 64 + lane * 2);
    uint2 u2lo = *(const uint2*)(y2h + (size_t)src * 128 + lane * 2);
    uint2 u2hi = *(const uint2*)(y2h + (size_t)src * 128 + 64 + lane * 2);
    float4 eav = *(const float4*)(ea + (size_t)e * 4);

    float v[8];
    {
        float2 a0 = unpackh(u1lo.x), a1 = unpackh(u1lo.y);
        float2 a2 = unpackh(u1hi.x), a3 = unpackh(u1hi.y);
        float2 c0 = unpackh(u2lo.x), c1 = unpackh(u2lo.y);
        float2 c2 = unpackh(u2hi.x), c3 = unpackh(u2hi.y);
        v[0] = a0.x + c0.x; v[1] = a0.y + c0.y;
        v[2] = a1.x + c1.x; v[3] = a1.y + c1.y;
        v[4] = a2.x + c2.x; v[5] = a2.y + c2.y;
        v[6] = a3.x + c3.x; v[7] = a3.y + c3.y;
    }
#pragma unroll
    for (int j = 0; j < 8; j++) {
        float h = v[j] + biasr[j];
        h = fmaf(eav.x, w3r[0][j], h);
        h = fmaf(eav.y, w3r[1][j], h);
        h = fmaf(eav.z, w3r[2][j], h);
        h = fmaf(eav.w, w3r[3][j], h);
        v[j] = h;
    }
    float s = v[0] + v[1] + v[2] + v[3] + v[4] + v[5] + v[6] + v[7];
#pragma unroll
    for (int o = 16; o > 0; o >>= 1) s += __shfl_xor_sync(0xffffffffu, s, o);
    float mean = s * (1.0f / 256.0f);
    float vs = 0.f;
#pragma unroll
    for (int j = 0; j < 8; j++) { float d = v[j] - mean; vs += d * d; }
#pragma unroll
    for (int o = 16; o > 0; o >>= 1) vs += __shfl_xor_sync(0xffffffffu, vs, o);
    float rstd = rsqrtf(vs * (1.0f / 256.0f) + 1e-5f);

    float m[8];
#pragma unroll
    for (int j = 0; j < 8; j++)
        m[j] = fast_silu((v[j] - mean) * rstd * gr[j] + br[j]);

    float* ag = agg + (size_t)dst * 256;
    red_v4(ag + lane * 4,       m[0], m[1], m[2], m[3]);
    red_v4(ag + 128 + lane * 4, m[4], m[5], m[6], m[7]);
}

// ---------------------------------------------------------------------------
// Node kernel 1: t = silu(LN(x@Wn1[:256] + aggs@Wn1[256:] + b)) -> tmps (fp16)
// ---------------------------------------------------------------------------
__global__ __launch_bounds__(256, 2) void node1_kernel(
    const uint32_t* __restrict__ xs, const uint32_t* __restrict__ aggs,
    const uint4* __restrict__ Wp, const float* __restrict__ Wb,
    const float* __restrict__ gam, const float* __restrict__ bet,
    uint32_t* __restrict__ tmps, int N) {
    extern __shared__ char smraw[];
    float* sBias = (float*)(smraw + SBIAS_OFF);
    float* sG    = (float*)(smraw + SG_OFF);
    float* sBv   = (float*)(smraw + SBV_OFF);

    const int tid = threadIdx.x;
    const int lane = tid & 31, warp = tid >> 5;
    const int wm = warp >> 2, wn = warp & 3;
    const int n0 = blockIdx.x * 64;
    const uint32_t sbase = (uint32_t)__cvta_generic_to_shared(smraw);
    const int arow = tid >> 2, apart = tid & 3;

    sBias[tid] = Wb[tid]; sG[tid] = gam[tid]; sBv[tid] = bet[tid];
    if (tid == 0) { mbar_init(sbase + MBAR_OFF, 1); mbar_init(sbase + MBAR_OFF + 8, 1); }
    __syncthreads();

    int rowg = n0 + arow; if (rowg >= N) rowg = N - 1;

    float acc[2][8][4];
#pragma unroll
    for (int mt = 0; mt < 2; mt++)
#pragma unroll
        for (int nt = 0; nt < 8; nt++)
#pragma unroll
            for (int j = 0; j < 4; j++) acc[mt][nt][j] = 0.f;

    auto stageA = [&](int c, int buf) {
        const uint32_t* bA = (c < 8) ? xs : aggs;
        const char* src = (const char*)(bA + (size_t)rowg * 128 + (c & 7) * 16) + apart * 16;
        cp16(sbase + SA_OFF + buf * 5120 + arow * 80 + apart * 16, src);
    };
    gemm_pipeline(stageA, Wp, smraw, sbase, tid, wm, wn, lane, 16, acc);

    acc_to_sout(smraw, wm, wn, lane, acc, sBias);
    __syncthreads();
    float (*sOut)[260] = (float(*)[260])(smraw + SOUT_OFF);
#pragma unroll 1
    for (int i = 0; i < 8; i++) {
        int r = i * 8 + warp;
        float vv[8];
        *(float4*)&vv[0] = *(float4*)&sOut[r][lane * 4];
        *(float4*)&vv[4] = *(float4*)&sOut[r][128 + lane * 4];
        ln_silu_row(vv, lane, sG, sBv);
        int row = n0 + r;
        if (row < N) {
            uint32_t* op = tmps + (size_t)row * 128;
            op[lane * 2]          = packh(vv[0], vv[1]);
            op[lane * 2 + 1]      = packh(vv[2], vv[3]);
            op[64 + lane * 2]     = packh(vv[4], vv[5]);
            op[64 + lane * 2 + 1] = packh(vv[6], vv[7]);
        }
    }
}

// ---------------------------------------------------------------------------
// Node kernel 2: out = x + t@Wn2 + b2; also writes fp16 xs for next layer
// ---------------------------------------------------------------------------
__global__ __launch_bounds__(256, 2) void node2_kernel(
    const uint32_t* __restrict__ tmps, const float* __restrict__ xres,
    const uint4* __restrict__ Wp, const float* __restrict__ Wb,
    float* __restrict__ out, uint32_t* __restrict__ xs_next, int N) {
    extern __shared__ char smraw[];
    float* sBias = (float*)(smraw + SBIAS_OFF);

    const int tid = threadIdx.x;
    const int lane = tid & 31, warp = tid >> 5;
    const int wm = warp >> 2, wn = warp & 3;
    const int n0 = blockIdx.x * 64;
    const uint32_t sbase = (uint32_t)__cvta_generic_to_shared(smraw);
    const int arow = tid >> 2, apart = tid & 3;

    sBias[tid] = Wb[tid];
    if (tid == 0) { mbar_init(sbase + MBAR_OFF, 1); mbar_init(sbase + MBAR_OFF + 8, 1); }
    __syncthreads();

    int rowg = n0 + arow; if (rowg >= N) rowg = N - 1;

    float acc[2][8][4];
#pragma unroll
    for (int mt = 0; mt < 2; mt++)
#pragma unroll
        for (int nt = 0; nt < 8; nt++)
#pragma unroll
            for (int j = 0; j < 4; j++) acc[mt][nt][j] = 0.f;

    auto stageA = [&](int c, int buf) {
        const char* src = (const char*)(tmps + (size_t)rowg * 128 + c * 16) + apart * 16;
        cp16(sbase + SA_OFF + buf * 5120 + arow * 80 + apart * 16, src);
    };
    gemm_pipeline(stageA, Wp, smraw, sbase, tid, wm, wn, lane, 8, acc);

    acc_to_sout(smraw, wm, wn, lane, acc, sBias);
    __syncthreads();
    float (*sOut)[260] = (float(*)[260])(smraw + SOUT_OFF);
#pragma unroll 1
    for (int i = 0; i < 8; i++) {
        int r = i * 8 + warp;
        int row = n0 + r;
        if (row < N) {
            const float* xr = xres + (size_t)row * 256;
            float4 lo = *(float4*)&sOut[r][lane * 4];
            float4 hi = *(float4*)&sOut[r][128 + lane * 4];
            float4 xlo = *(const float4*)(xr + lane * 4);
            float4 xhi = *(const float4*)(xr + 128 + lane * 4);
            lo.x += xlo.x; lo.y += xlo.y; lo.z += xlo.z; lo.w += xlo.w;
            hi.x += xhi.x; hi.y += xhi.y; hi.z += xhi.z; hi.w += xhi.w;
            float* op = out + (size_t)row * 256;
            *(float4*)(op + lane * 4) = lo;
            *(float4*)(op + 128 + lane * 4) = hi;
            uint32_t* xp = xs_next + (size_t)row * 128;
            xp[lane * 2]          = packh(lo.x, lo.y);
            xp[lane * 2 + 1]      = packh(lo.z, lo.w);
            xp[64 + lane * 2]     = packh(hi.x, hi.y);
            xp[64 + lane * 2 + 1] = packh(hi.z, hi.w);
        }
    }
}

// ---------------------------------------------------------------------------
extern "C" void kernel_launch(void* const* d_in, const int* in_sizes, int n_in,
                              void* d_out, int out_size) {
    const float* x_in  = (const float*)d_in[0];
    const int*   eidx  = (const int*)d_in[1];
    const float* ea    = (const float*)d_in[2];
    const float* We_w  = (const float*)d_in[3];
    const float* We_b  = (const float*)d_in[4];
    const float* g1    = (const float*)d_in[5];
    const float* b1    = (const float*)d_in[6];
    const float* Wn1_w = (const float*)d_in[7];
    const float* Wn1_b = (const float*)d_in[8];
    const float* g2    = (const float*)d_in[9];
    const float* b2    = (const float*)d_in[10];
    const float* Wn2_w = (const float*)d_in[11];
    const float* Wn2_b = (const float*)d_in[12];

    const int N  = in_sizes[0] / 256;
    const int D  = in_sizes[1] / 2;
    const int NL = in_sizes[4] / 256;

    float *bufA, *bufB, *aggp;
    uint32_t *y1h, *y2h, *xs, *aggs, *tmps;
    uint4 *wE, *wN1, *wN2;
    cudaGetSymbolAddress((void**)&bufA, g_bufA);
    cudaGetSymbolAddress((void**)&bufB, g_bufB);
    cudaGetSymbolAddress((void**)&aggp, g_agg);
    cudaGetSymbolAddress((void**)&y1h,  g_y1h);
    cudaGetSymbolAddress((void**)&y2h,  g_y2h);
    cudaGetSymbolAddress((void**)&xs,   g_xs);
    cudaGetSymbolAddress((void**)&aggs, g_aggs);
    cudaGetSymbolAddress((void**)&tmps, g_tmps);
    cudaGetSymbolAddress((void**)&wE,   g_We);
    cudaGetSymbolAddress((void**)&wN1,  g_Wn1);
    cudaGetSymbolAddress((void**)&wN2,  g_Wn2);

    cudaFuncSetAttribute(y12_kernel,   cudaFuncAttributeMaxDynamicSharedMemorySize, SMEM_BYTES);
    cudaFuncSetAttribute(node1_kernel, cudaFuncAttributeMaxDynamicSharedMemorySize, SMEM_BYTES);
    cudaFuncSetAttribute(node2_kernel, cudaFuncAttributeMaxDynamicSharedMemorySize, SMEM_BYTES);

    // one-time packs (deterministic, inside capture)
    {
        size_t t0 = (size_t)NL * 32 * 1024;
        pack_w_frag<<<(int)((t0 + 255) / 256), 256>>>(We_w, wE, 512, 516, 32, NL);
        pack_w_frag<<<(int)((t0 + 255) / 256), 256>>>(Wn1_w, wN1, 512, 512, 32, NL);
        size_t t2 = (size_t)NL * 16 * 1024;
        pack_w_frag<<<(int)((t2 + 255) / 256), 256>>>(Wn2_w, wN2, 256, 256, 16, NL);
        int nx = N * 128;
        convert_h<<<(nx + 255) / 256, 256>>>(x_in, xs, nx);
    }

    const int nblk_n = (N + 63) / 64;
    const int nblk_e = (D + 7) / 8;
    const int n4 = (N * 256) / 4;
    const int zblk = (n4 + 255) / 256;
    const int ncv = N * 128;
    const int cvblk = (ncv + 255) / 256;

    const float* xcur = x_in;
    for (int l = 0; l < NL; l++) {
        float* xnext = (l == NL - 1) ? (float*)d_out : ((l & 1) ? bufB : bufA);
        zero_kernel<<<zblk, 256>>>((float4*)aggp, n4);
        y12_kernel<<<dim3(nblk_n, 2), 256, SMEM_BYTES>>>(
            xs, wE + (size_t)l * 32 * 1024, y1h, y2h, N);
        edge_pass<<<nblk_e, 256>>>(
            y1h, y2h, eidx, ea,
            We_w + (size_t)l * 516 * 256 + (size_t)512 * 256,
            We_b + (size_t)l * 256, g1 + (size_t)l * 256, b1 + (size_t)l * 256,
            aggp, D);
        convert_h<<<cvblk, 256>>>(aggp, aggs, ncv);
        node1_kernel<<<nblk_n, 256, SMEM_BYTES>>>(
            xs, aggs, wN1 + (size_t)l * 32 * 1024,
            Wn1_b + (size_t)l * 256, g2 + (size_t)l * 256, b2 + (size_t)l * 256,
            tmps, N);
        node2_kernel<<<nblk_n, 256, SMEM_BYTES>>>(
            tmps, xcur, wN2 + (size_t)l * 16 * 1024,
            Wn2_b + (size_t)l * 256, xnext, xs, N);
        xcur = xnext;
    }
}

// round 13
// speedup vs baseline: 1.5837x; 1.1630x over previous
#include <cuda_runtime.h>
#include <cuda_fp16.h>
#include <cstdint>

// ============================================================================
// GraphCastProcessor — plain fp16 mma.sync GEMMs (1 MMA/k16, fp32 acc).
// y1/y2 stored fp16x2; R9 contiguous-RED edge pass with fp32 red.v4.
//   y1 = x@We[:256], y2 = x@We[256:512]          (fp16x2 out)
//   h_e = y1[dst]+y2[src]+ea@W3+b ; msg = silu(LN(h)); agg += msg (f32 RED)
//   u = x@Wn1[:256]+agg@Wn1[256:]+b ; t = silu(LN(u))
//   x = x + t@Wn2 + b2
// GEMM: block 64x256, 8 warps, K-superchunk 32 (2x k16), cp.async A +
// cp.async.bulk B (16KB/stage), double-buffered via mbarrier.
// ============================================================================

#define MAXN 40962
#define MAXD 163848
#define MAXNL 6

__device__ float g_bufA[MAXN * 256];
__device__ float g_bufB[MAXN * 256];
__device__ float g_agg [MAXN * 256];
__device__ uint32_t g_y1h [MAXN * 128];   // fp16x2 rows (512B)
__device__ uint32_t g_y2h [MAXN * 128];
__device__ uint32_t g_xs  [MAXN * 128];   // fp16x2 activations
__device__ uint32_t g_aggs[MAXN * 128];
__device__ uint32_t g_tmps[MAXN * 128];
// fragment-ordered fp16 weights: [layer][chunk16][wn(4)][nt(8)][lane(32)]
// uint2 = {k0pair, k1pair} (B-fragment regs b0, b1)
__device__ uint2 g_We [MAXNL * 32 * 1024];
__device__ uint2 g_Wn1[MAXNL * 32 * 1024];
__device__ uint2 g_Wn2[MAXNL * 16 * 1024];

// ---- dynamic smem layout (bytes) ----
#define SA_OFF    0                       // u32 sA[2][64][20] = 10240 (80B row)
#define SB_OFF    10240                   // uint2 sB[2][2048] = 32768 -> 43008
#define SOUT_OFF  0                       // float sOut[64][260] = 66560 (aliases)
#define SBIAS_OFF 66560
#define SG_OFF    67584
#define SBV_OFF   68608
#define MBAR_OFF  69632                   // 2 x u64
#define SMEM_BYTES 69664

__device__ __forceinline__ float fast_silu(float y) {
    return __fdividef(y, 1.0f + __expf(-y));
}

__device__ __forceinline__ uint32_t packh(float a, float b) {
    __half2 h = __floats2half2_rn(a, b);
    return *(uint32_t*)&h;
}
__device__ __forceinline__ float2 unpackh(uint32_t u) {
    __half2 h = *(__half2*)&u;
    return __half22float2(h);
}

__device__ __forceinline__ void mma_f16(float c[4], const uint32_t a[4],
                                        uint32_t b0, uint32_t b1) {
    asm volatile(
        "mma.sync.aligned.m16n8k16.row.col.f32.f16.f16.f32 "
        "{%0,%1,%2,%3}, {%4,%5,%6,%7}, {%8,%9}, {%0,%1,%2,%3};"
        : "+f"(c[0]), "+f"(c[1]), "+f"(c[2]), "+f"(c[3])
        : "r"(a[0]), "r"(a[1]), "r"(a[2]), "r"(a[3]), "r"(b0), "r"(b1));
}

__device__ __forceinline__ void red_v4(float* p, float a, float b, float c, float d) {
    asm volatile("red.global.add.v4.f32 [%0], {%1,%2,%3,%4};"
                 :: "l"(p), "f"(a), "f"(b), "f"(c), "f"(d) : "memory");
}

__device__ __forceinline__ void cp16(uint32_t smem_dst, const void* gsrc) {
    asm volatile("cp.async.cg.shared.global [%0], [%1], 16;\n"
                 :: "r"(smem_dst), "l"(gsrc));
}
#define CP_COMMIT() asm volatile("cp.async.commit_group;\n" ::: "memory")
#define CP_WAIT(n)  asm volatile("cp.async.wait_group %0;\n" :: "n"(n) : "memory")

__device__ __forceinline__ void mbar_init(uint32_t mbar, uint32_t count) {
    asm volatile("mbarrier.init.shared.b64 [%0], %1;" :: "r"(mbar), "r"(count) : "memory");
}
__device__ __forceinline__ void mbar_expect_tx(uint32_t mbar, uint32_t bytes) {
    asm volatile("mbarrier.arrive.expect_tx.shared.b64 _, [%0], %1;"
                 :: "r"(mbar), "r"(bytes) : "memory");
}
__device__ __forceinline__ void mbar_wait(uint32_t mbar, uint32_t parity) {
    asm volatile(
        "{\n\t.reg .pred P1;\n\t"
        "WAIT_LOOP_%=:\n\t"
        "mbarrier.try_wait.parity.acquire.cta.shared::cta.b64 P1, [%0], %1, 0x989680;\n\t"
        "@P1 bra.uni WAIT_DONE_%=;\n\t"
        "bra.uni WAIT_LOOP_%=;\n\t"
        "WAIT_DONE_%=:\n\t}"
        :: "r"(mbar), "r"(parity) : "memory");
}
__device__ __forceinline__ void bulk_cp(uint32_t smem_dst, const void* gsrc,
                                        uint32_t bytes, uint32_t mbar) {
    asm volatile(
        "cp.async.bulk.shared::cta.global.mbarrier::complete_tx::bytes [%0], [%1], %2, [%3];"
        :: "r"(smem_dst), "l"(gsrc), "r"(bytes), "r"(mbar) : "memory");
}

// LN(256)+SiLU; row spread as 8 vals/lane (cols tx*4+j / 128+tx*4+j-4)
__device__ __forceinline__ void ln_silu_row(float v[8], int tx,
                                            const float* sG, const float* sB) {
    float s = v[0] + v[1] + v[2] + v[3] + v[4] + v[5] + v[6] + v[7];
#pragma unroll
    for (int o = 16; o > 0; o >>= 1) s += __shfl_xor_sync(0xffffffffu, s, o);
    float mean = s * (1.0f / 256.0f);
    float vs = 0.f;
#pragma unroll
    for (int j = 0; j < 8; j++) { float d = v[j] - mean; vs += d * d; }
#pragma unroll
    for (int o = 16; o > 0; o >>= 1) vs += __shfl_xor_sync(0xffffffffu, vs, o);
    float rstd = rsqrtf(vs * (1.0f / 256.0f) + 1e-5f);
#pragma unroll
    for (int j = 0; j < 8; j++) {
        int col = (j < 4) ? (tx * 4 + j) : (128 + tx * 4 + j - 4);
        float y = (v[j] - mean) * rstd * sG[col] + sB[col];
        v[j] = fast_silu(y);
    }
}

// one K32 superchunk: two k16 halves, 1 MMA each
__device__ __forceinline__ void compute_schunk(const char* smraw, int buf,
                                               int wm, int wn, int lane,
                                               float acc[2][8][4]) {
    const uint32_t* sAp = (const uint32_t*)(smraw + SA_OFF + buf * 5120);
    const uint2* sBp = (const uint2*)(smraw + SB_OFF + buf * 16384);
    const int q = lane & 3;
#pragma unroll
    for (int h = 0; h < 2; h++) {
        uint32_t a[2][4];
#pragma unroll
        for (int mt = 0; mt < 2; mt++) {
            int r = wm * 32 + mt * 16 + (lane >> 2);
            a[mt][0] = sAp[r * 20 + h * 8 + q];
            a[mt][1] = sAp[(r + 8) * 20 + h * 8 + q];
            a[mt][2] = sAp[r * 20 + h * 8 + q + 4];
            a[mt][3] = sAp[(r + 8) * 20 + h * 8 + q + 4];
        }
#pragma unroll
        for (int nt = 0; nt < 8; nt++) {
            uint2 b = sBp[h * 1024 + wn * 256 + nt * 32 + lane];
#pragma unroll
            for (int mt = 0; mt < 2; mt++)
                mma_f16(acc[mt][nt], a[mt], b.x, b.y);
        }
    }
}

template <typename FA>
__device__ __forceinline__ void gemm_pipeline(FA stageA, const uint2* __restrict__ Wp,
                                              char* smraw, uint32_t sbase, int tid,
                                              int wm, int wn, int lane, int schunks,
                                              float acc[2][8][4]) {
    const uint32_t mbar0 = sbase + MBAR_OFF;
    auto issueB = [&](int c, int buf) {
        if (tid == 0) {
            uint32_t mb = mbar0 + buf * 8;
            mbar_expect_tx(mb, 16384);
            bulk_cp(sbase + SB_OFF + buf * 16384, Wp + (size_t)c * 2048, 16384, mb);
        }
    };
    stageA(0, 0); CP_COMMIT(); issueB(0, 0);
#pragma unroll 1
    for (int c = 0; c < schunks; c++) {
        if (c + 1 < schunks) {
            stageA(c + 1, (c + 1) & 1); CP_COMMIT(); issueB(c + 1, (c + 1) & 1);
            CP_WAIT(1);
        } else {
            CP_WAIT(0);
        }
        mbar_wait(mbar0 + (c & 1) * 8, (c >> 1) & 1);
        __syncthreads();
        compute_schunk(smraw, c & 1, wm, wn, lane, acc);
        __syncthreads();
    }
}

__device__ __forceinline__ void acc_to_sout(char* smraw, int wm, int wn,
                                            int lane, float acc[2][8][4],
                                            const float* sBias) {
    float (*sOut)[260] = (float(*)[260])(smraw + SOUT_OFF);
#pragma unroll
    for (int mt = 0; mt < 2; mt++)
#pragma unroll
        for (int nt = 0; nt < 8; nt++) {
            int r0 = wm * 32 + mt * 16 + (lane >> 2);
            int c = wn * 64 + nt * 8 + 2 * (lane & 3);
            float b0 = sBias ? sBias[c] : 0.f;
            float b1 = sBias ? sBias[c + 1] : 0.f;
            sOut[r0][c]         = acc[mt][nt][0] + b0;
            sOut[r0][c + 1]     = acc[mt][nt][1] + b1;
            sOut[r0 + 8][c]     = acc[mt][nt][2] + b0;
            sOut[r0 + 8][c + 1] = acc[mt][nt][3] + b1;
        }
}

// ---------------------------------------------------------------------------
// packers
// ---------------------------------------------------------------------------
__global__ void pack_w_frag(const float* __restrict__ W, uint2* __restrict__ out,
                            int Ksrc, int lstride, int C, int NL) {
    size_t idx = (size_t)blockIdx.x * blockDim.x + threadIdx.x;
    size_t total = (size_t)NL * C * 1024;
    if (idx >= total) return;
    int t = (int)(idx & 1023);
    int lane = t & 31, nt = (t >> 5) & 7, wn = t >> 8;
    int c = (int)((idx >> 10) % C);
    int l = (int)(idx / ((size_t)C * 1024));
    int n = wn * 64 + nt * 8 + (lane >> 2);
    int q = lane & 3;
    int kp0 = c * 8 + q, kp1 = c * 8 + q + 4;
    const float* Wl = W + (size_t)l * lstride * 256;
    float a0 = (2 * kp0     < Ksrc) ? Wl[(size_t)(2 * kp0)     * 256 + n] : 0.f;
    float a1 = (2 * kp0 + 1 < Ksrc) ? Wl[(size_t)(2 * kp0 + 1) * 256 + n] : 0.f;
    float b0 = (2 * kp1     < Ksrc) ? Wl[(size_t)(2 * kp1)     * 256 + n] : 0.f;
    float b1 = (2 * kp1 + 1 < Ksrc) ? Wl[(size_t)(2 * kp1 + 1) * 256 + n] : 0.f;
    out[idx] = make_uint2(packh(a0, a1), packh(b0, b1));
}

__global__ void convert_h(const float* __restrict__ in, uint32_t* __restrict__ out,
                          int n) {
    int i = blockIdx.x * blockDim.x + threadIdx.x;
    if (i < n) {
        float2 v = ((const float2*)in)[i];
        out[i] = packh(v.x, v.y);
    }
}

__global__ void zero_kernel(float4* __restrict__ p, int n4) {
    int i = blockIdx.x * blockDim.x + threadIdx.x;
    if (i < n4) p[i] = make_float4(0.f, 0.f, 0.f, 0.f);
}

// ---------------------------------------------------------------------------
// y12 kernel: y = x @ We[half*256 : (half+1)*256] (no bias) -> fp16x2 rows
// ---------------------------------------------------------------------------
__global__ __launch_bounds__(256, 2) void y12_kernel(
    const uint32_t* __restrict__ xs, const uint2* __restrict__ WpBase,
    uint32_t* __restrict__ y1h, uint32_t* __restrict__ y2h, int N) {
    extern __shared__ char smraw[];
    const int tid = threadIdx.x;
    const int lane = tid & 31, warp = tid >> 5;
    const int wm = warp >> 2, wn = warp & 3;
    const int n0 = blockIdx.x * 64;
    const int half = blockIdx.y;
    const uint32_t sbase = (uint32_t)__cvta_generic_to_shared(smraw);
    const int arow = tid >> 2, apart = tid & 3;
    int rowg = n0 + arow; if (rowg >= N) rowg = N - 1;

    if (tid == 0) { mbar_init(sbase + MBAR_OFF, 1); mbar_init(sbase + MBAR_OFF + 8, 1); }
    __syncthreads();

    const uint2* Wp = WpBase + (size_t)half * 16 * 1024;
    uint32_t* yout = half ? y2h : y1h;

    float acc[2][8][4];
#pragma unroll
    for (int mt = 0; mt < 2; mt++)
#pragma unroll
        for (int nt = 0; nt < 8; nt++)
#pragma unroll
            for (int j = 0; j < 4; j++) acc[mt][nt][j] = 0.f;

    auto stageA = [&](int c, int buf) {
        const char* src = (const char*)(xs + (size_t)rowg * 128 + c * 16) + apart * 16;
        cp16(sbase + SA_OFF + buf * 5120 + arow * 80 + apart * 16, src);
    };
    gemm_pipeline(stageA, Wp, smraw, sbase, tid, wm, wn, lane, 8, acc);

    acc_to_sout(smraw, wm, wn, lane, acc, nullptr);
    __syncthreads();
    float (*sOut)[260] = (float(*)[260])(smraw + SOUT_OFF);
#pragma unroll 1
    for (int i = 0; i < 8; i++) {
        int r = i * 8 + warp;
        int row = n0 + r;
        if (row < N) {
            // pack in R9 column order: words 0..63 = cols 0..127, 64..127 = 128..255
            float4 lo = *(float4*)&sOut[r][lane * 4];
            float4 hi = *(float4*)&sOut[r][128 + lane * 4];
            uint32_t* op = yout + (size_t)row * 128;
            *(uint2*)(op + lane * 2)      = make_uint2(packh(lo.x, lo.y), packh(lo.z, lo.w));
            *(uint2*)(op + 64 + lane * 2) = make_uint2(packh(hi.x, hi.y), packh(hi.z, hi.w));
        }
    }
}

// ---------------------------------------------------------------------------
// Edge pass: h = y1h[dst]+y2h[src]+ea@W3+b; silu(LN(h)) -> f32 red.v4 into agg
// R9 layout: lane owns cols lane*4+j (j<4) and 128+lane*4+(j-4); contiguous REDs
// ---------------------------------------------------------------------------
__global__ __launch_bounds__(256) void edge_pass(
    const uint32_t* __restrict__ y1h, const uint32_t* __restrict__ y2h,
    const int* __restrict__ eidx, const float* __restrict__ ea,
    const float* __restrict__ W3, const float* __restrict__ Wb,
    const float* __restrict__ gam, const float* __restrict__ bet,
    float* __restrict__ agg, int D) {
    const int lane = threadIdx.x & 31, warp = threadIdx.x >> 5;
    const int e = blockIdx.x * 8 + warp;

    float w3r[4][8], biasr[8], gr[8], br[8];
#pragma unroll
    for (int j = 0; j < 8; j++) {
        int col = (j < 4) ? (lane * 4 + j) : (128 + lane * 4 + j - 4);
        biasr[j] = __ldg(Wb + col);
        gr[j] = __ldg(gam + col);
        br[j] = __ldg(bet + col);
#pragma unroll
        for (int k = 0; k < 4; k++) w3r[k][j] = __ldg(W3 + k * 256 + col);
    }
    if (e >= D) return;

    int src = __ldg(eidx + e);
    int dst = __ldg(eidx + (size_t)D + e);
    uint2 u1lo = *(const uint2*)(y1h + (size_t)dst * 128 + lane * 2);
    uint2 u1hi = *(const uint2*)(y1h + (size_t)dst * 128 + 64 + lane * 2);
    uint2 u2lo = *(const uint2*)(y2h + (size_t)src * 128 + lane * 2);
    uint2 u2hi = *(const uint2*)(y2h + (size_t)src * 128 + 64 + lane * 2);
    float4 eav = *(const float4*)(ea + (size_t)e * 4);

    float v[8];
    {
        float2 a0 = unpackh(u1lo.x), a1 = unpackh(u1lo.y);
        float2 a2 = unpackh(u1hi.x), a3 = unpackh(u1hi.y);
        float2 c0 = unpackh(u2lo.x), c1 = unpackh(u2lo.y);
        float2 c2 = unpackh(u2hi.x), c3 = unpackh(u2hi.y);
        v[0] = a0.x + c0.x; v[1] = a0.y + c0.y;
        v[2] = a1.x + c1.x; v[3] = a1.y + c1.y;
        v[4] = a2.x + c2.x; v[5] = a2.y + c2.y;
        v[6] = a3.x + c3.x; v[7] = a3.y + c3.y;
    }
#pragma unroll
    for (int j = 0; j < 8; j++) {
        float h = v[j] + biasr[j];
        h = fmaf(eav.x, w3r[0][j], h);
        h = fmaf(eav.y, w3r[1][j], h);
        h = fmaf(eav.z, w3r[2][j], h);
        h = fmaf(eav.w, w3r[3][j], h);
        v[j] = h;
    }
    float s = v[0] + v[1] + v[2] + v[3] + v[4] + v[5] + v[6] + v[7];
#pragma unroll
    for (int o = 16; o > 0; o >>= 1) s += __shfl_xor_sync(0xffffffffu, s, o);
    float mean = s * (1.0f / 256.0f);
    float vs = 0.f;
#pragma unroll
    for (int j = 0; j < 8; j++) { float d = v[j] - mean; vs += d * d; }
#pragma unroll
    for (int o = 16; o > 0; o >>= 1) vs += __shfl_xor_sync(0xffffffffu, vs, o);
    float rstd = rsqrtf(vs * (1.0f / 256.0f) + 1e-5f);

    float m[8];
#pragma unroll
    for (int j = 0; j < 8; j++)
        m[j] = fast_silu((v[j] - mean) * rstd * gr[j] + br[j]);

    float* ag = agg + (size_t)dst * 256;
    red_v4(ag + lane * 4,       m[0], m[1], m[2], m[3]);
    red_v4(ag + 128 + lane * 4, m[4], m[5], m[6], m[7]);
}

// ---------------------------------------------------------------------------
// Node kernel 1: t = silu(LN(x@Wn1[:256] + aggs@Wn1[256:] + b)) -> tmps (fp16)
// ---------------------------------------------------------------------------
__global__ __launch_bounds__(256, 2) void node1_kernel(
    const uint32_t* __restrict__ xs, const uint32_t* __restrict__ aggs,
    const uint2* __restrict__ Wp, const float* __restrict__ Wb,
    const float* __restrict__ gam, const float* __restrict__ bet,
    uint32_t* __restrict__ tmps, int N) {
    extern __shared__ char smraw[];
    float* sBias = (float*)(smraw + SBIAS_OFF);
    float* sG    = (float*)(smraw + SG_OFF);
    float* sBv   = (float*)(smraw + SBV_OFF);

    const int tid = threadIdx.x;
    const int lane = tid & 31, warp = tid >> 5;
    const int wm = warp >> 2, wn = warp & 3;
    const int n0 = blockIdx.x * 64;
    const uint32_t sbase = (uint32_t)__cvta_generic_to_shared(smraw);
    const int arow = tid >> 2, apart = tid & 3;

    sBias[tid] = Wb[tid]; sG[tid] = gam[tid]; sBv[tid] = bet[tid];
    if (tid == 0) { mbar_init(sbase + MBAR_OFF, 1); mbar_init(sbase + MBAR_OFF + 8, 1); }
    __syncthreads();

    int rowg = n0 + arow; if (rowg >= N) rowg = N - 1;

    float acc[2][8][4];
#pragma unroll
    for (int mt = 0; mt < 2; mt++)
#pragma unroll
        for (int nt = 0; nt < 8; nt++)
#pragma unroll
            for (int j = 0; j < 4; j++) acc[mt][nt][j] = 0.f;

    auto stageA = [&](int c, int buf) {
        const uint32_t* bA = (c < 8) ? xs : aggs;
        const char* src = (const char*)(bA + (size_t)rowg * 128 + (c & 7) * 16) + apart * 16;
        cp16(sbase + SA_OFF + buf * 5120 + arow * 80 + apart * 16, src);
    };
    gemm_pipeline(stageA, Wp, smraw, sbase, tid, wm, wn, lane, 16, acc);

    acc_to_sout(smraw, wm, wn, lane, acc, sBias);
    __syncthreads();
    float (*sOut)[260] = (float(*)[260])(smraw + SOUT_OFF);
#pragma unroll 1
    for (int i = 0; i < 8; i++) {
        int r = i * 8 + warp;
        float vv[8];
        *(float4*)&vv[0] = *(float4*)&sOut[r][lane * 4];
        *(float4*)&vv[4] = *(float4*)&sOut[r][128 + lane * 4];
        ln_silu_row(vv, lane, sG, sBv);
        int row = n0 + r;
        if (row < N) {
            uint32_t* op = tmps + (size_t)row * 128;
            op[lane * 2]          = packh(vv[0], vv[1]);
            op[lane * 2 + 1]      = packh(vv[2], vv[3]);
            op[64 + lane * 2]     = packh(vv[4], vv[5]);
            op[64 + lane * 2 + 1] = packh(vv[6], vv[7]);
        }
    }
}

// ---------------------------------------------------------------------------
// Node kernel 2: out = x + t@Wn2 + b2; also writes fp16 xs for next layer
// ---------------------------------------------------------------------------
__global__ __launch_bounds__(256, 2) void node2_kernel(
    const uint32_t* __restrict__ tmps, const float* __restrict__ xres,
    const uint2* __restrict__ Wp, const float* __restrict__ Wb,
    float* __restrict__ out, uint32_t* __restrict__ xs_next, int N) {
    extern __shared__ char smraw[];
    float* sBias = (float*)(smraw + SBIAS_OFF);

    const int tid = threadIdx.x;
    const int lane = tid & 31, warp = tid >> 5;
    const int wm = warp >> 2, wn = warp & 3;
    const int n0 = blockIdx.x * 64;
    const uint32_t sbase = (uint32_t)__cvta_generic_to_shared(smraw);
    const int arow = tid >> 2, apart = tid & 3;

    sBias[tid] = Wb[tid];
    if (tid == 0) { mbar_init(sbase + MBAR_OFF, 1); mbar_init(sbase + MBAR_OFF + 8, 1); }
    __syncthreads();

    int rowg = n0 + arow; if (rowg >= N) rowg = N - 1;

    float acc[2][8][4];
#pragma unroll
    for (int mt = 0; mt < 2; mt++)
#pragma unroll
        for (int nt = 0; nt < 8; nt++)
#pragma unroll
            for (int j = 0; j < 4; j++) acc[mt][nt][j] = 0.f;

    auto stageA = [&](int c, int buf) {
        const char* src = (const char*)(tmps + (size_t)rowg * 128 + c * 16) + apart * 16;
        cp16(sbase + SA_OFF + buf * 5120 + arow * 80 + apart * 16, src);
    };
    gemm_pipeline(stageA, Wp, smraw, sbase, tid, wm, wn, lane, 8, acc);

    acc_to_sout(smraw, wm, wn, lane, acc, sBias);
    __syncthreads();
    float (*sOut)[260] = (float(*)[260])(smraw + SOUT_OFF);
#pragma unroll 1
    for (int i = 0; i < 8; i++) {
        int r = i * 8 + warp;
        int row = n0 + r;
        if (row < N) {
            const float* xr = xres + (size_t)row * 256;
            float4 lo = *(float4*)&sOut[r][lane * 4];
            float4 hi = *(float4*)&sOut[r][128 + lane * 4];
            float4 xlo = *(const float4*)(xr + lane * 4);
            float4 xhi = *(const float4*)(xr + 128 + lane * 4);
            lo.x += xlo.x; lo.y += xlo.y; lo.z += xlo.z; lo.w += xlo.w;
            hi.x += xhi.x; hi.y += xhi.y; hi.z += xhi.z; hi.w += xhi.w;
            float* op = out + (size_t)row * 256;
            *(float4*)(op + lane * 4) = lo;
            *(float4*)(op + 128 + lane * 4) = hi;
            uint32_t* xp = xs_next + (size_t)row * 128;
            xp[lane * 2]          = packh(lo.x, lo.y);
            xp[lane * 2 + 1]      = packh(lo.z, lo.w);
            xp[64 + lane * 2]     = packh(hi.x, hi.y);
            xp[64 + lane * 2 + 1] = packh(hi.z, hi.w);
        }
    }
}

// ---------------------------------------------------------------------------
extern "C" void kernel_launch(void* const* d_in, const int* in_sizes, int n_in,
                              void* d_out, int out_size) {
    const float* x_in  = (const float*)d_in[0];
    const int*   eidx  = (const int*)d_in[1];
    const float* ea    = (const float*)d_in[2];
    const float* We_w  = (const float*)d_in[3];
    const float* We_b  = (const float*)d_in[4];
    const float* g1    = (const float*)d_in[5];
    const float* b1    = (const float*)d_in[6];
    const float* Wn1_w = (const float*)d_in[7];
    const float* Wn1_b = (const float*)d_in[8];
    const float* g2    = (const float*)d_in[9];
    const float* b2    = (const float*)d_in[10];
    const float* Wn2_w = (const float*)d_in[11];
    const float* Wn2_b = (const float*)d_in[12];

    const int N  = in_sizes[0] / 256;
    const int D  = in_sizes[1] / 2;
    const int NL = in_sizes[4] / 256;

    float *bufA, *bufB, *aggp;
    uint32_t *y1h, *y2h, *xs, *aggs, *tmps;
    uint2 *wE, *wN1, *wN2;
    cudaGetSymbolAddress((void**)&bufA, g_bufA);
    cudaGetSymbolAddress((void**)&bufB, g_bufB);
    cudaGetSymbolAddress((void**)&aggp, g_agg);
    cudaGetSymbolAddress((void**)&y1h,  g_y1h);
    cudaGetSymbolAddress((void**)&y2h,  g_y2h);
    cudaGetSymbolAddress((void**)&xs,   g_xs);
    cudaGetSymbolAddress((void**)&aggs, g_aggs);
    cudaGetSymbolAddress((void**)&tmps, g_tmps);
    cudaGetSymbolAddress((void**)&wE,   g_We);
    cudaGetSymbolAddress((void**)&wN1,  g_Wn1);
    cudaGetSymbolAddress((void**)&wN2,  g_Wn2);

    cudaFuncSetAttribute(y12_kernel,   cudaFuncAttributeMaxDynamicSharedMemorySize, SMEM_BYTES);
    cudaFuncSetAttribute(node1_kernel, cudaFuncAttributeMaxDynamicSharedMemorySize, SMEM_BYTES);
    cudaFuncSetAttribute(node2_kernel, cudaFuncAttributeMaxDynamicSharedMemorySize, SMEM_BYTES);

    // one-time packs (deterministic, inside capture)
    {
        size_t t0 = (size_t)NL * 32 * 1024;
        pack_w_frag<<<(int)((t0 + 255) / 256), 256>>>(We_w, wE, 512, 516, 32, NL);
        pack_w_frag<<<(int)((t0 + 255) / 256), 256>>>(Wn1_w, wN1, 512, 512, 32, NL);
        size_t t2 = (size_t)NL * 16 * 1024;
        pack_w_frag<<<(int)((t2 + 255) / 256), 256>>>(Wn2_w, wN2, 256, 256, 16, NL);
        int nx = N * 128;
        convert_h<<<(nx + 255) / 256, 256>>>(x_in, xs, nx);
    }

    const int nblk_n = (N + 63) / 64;
    const int nblk_e = (D + 7) / 8;
    const int n4 = (N * 256) / 4;
    const int zblk = (n4 + 255) / 256;
    const int ncv = N * 128;
    const int cvblk = (ncv + 255) / 256;

    const float* xcur = x_in;
    for (int l = 0; l < NL; l++) {
        float* xnext = (l == NL - 1) ? (float*)d_out : ((l & 1) ? bufB : bufA);
        zero_kernel<<<zblk, 256>>>((float4*)aggp, n4);
        y12_kernel<<<dim3(nblk_n, 2), 256, SMEM_BYTES>>>(
            xs, wE + (size_t)l * 32 * 1024, y1h, y2h, N);
        edge_pass<<<nblk_e, 256>>>(
            y1h, y2h, eidx, ea,
            We_w + (size_t)l * 516 * 256 + (size_t)512 * 256,
            We_b + (size_t)l * 256, g1 + (size_t)l * 256, b1 + (size_t)l * 256,
            aggp, D);
        convert_h<<<cvblk, 256>>>(aggp, aggs, ncv);
        node1_kernel<<<nblk_n, 256, SMEM_BYTES>>>(
            xs, aggs, wN1 + (size_t)l * 32 * 1024,
            Wn1_b + (size_t)l * 256, g2 + (size_t)l * 256, b2 + (size_t)l * 256,
            tmps, N);
        node2_kernel<<<nblk_n, 256, SMEM_BYTES>>>(
            tmps, xcur, wN2 + (size_t)l * 16 * 1024,
            Wn2_b + (size_t)l * 256, xnext, xs, N);
        xcur = xnext;
    }
}

// round 15
// speedup vs baseline: 1.6373x; 1.0339x over previous
#include <cuda_runtime.h>
#include <cuda_fp16.h>
#include <cstdint>

// ============================================================================
// GraphCastProcessor — plain fp16 mma.sync GEMMs (1 MMA/k16, fp32 acc),
// K-superchunk 64 (4x k16). A stage: 128B/row (32 words), stride 144B.
// y1/y2 stored fp16x2; R9 contiguous-RED edge pass with fp32 red.v4.
//   y1 = x@We[:256], y2 = x@We[256:512]          (fp16x2 out)
//   h_e = y1[dst]+y2[src]+ea@W3+b ; msg = silu(LN(h)); agg += msg (f32 RED)
//   u = x@Wn1[:256]+agg@Wn1[256:]+b ; t = silu(LN(u))
//   x = x + t@Wn2 + b2
// ============================================================================

#define MAXN 40962
#define MAXD 163848
#define MAXNL 6

__device__ float g_bufA[MAXN * 256];
__device__ float g_bufB[MAXN * 256];
__device__ float g_agg [MAXN * 256];
__device__ uint32_t g_y1h [MAXN * 128];   // fp16x2 rows (512B)
__device__ uint32_t g_y2h [MAXN * 128];
__device__ uint32_t g_xs  [MAXN * 128];   // fp16x2 activations
__device__ uint32_t g_aggs[MAXN * 128];
__device__ uint32_t g_tmps[MAXN * 128];
// fragment-ordered fp16 weights: [layer][chunk16][wn(4)][nt(8)][lane(32)]
// uint2 = {k0pair, k1pair}
__device__ uint2 g_We [MAXNL * 32 * 1024];
__device__ uint2 g_Wn1[MAXNL * 32 * 1024];
__device__ uint2 g_Wn2[MAXNL * 16 * 1024];

// ---- dynamic smem layout (bytes) ----
// sA: 2 bufs x 64 rows x 144B (128B data + 16B pad) = 18432
// sB: 2 bufs x 32768B (4 k16-chunks of weights)     = 65536 -> ends 83968
// sOut aliases offset 0 (66560B)
#define SA_OFF    0
#define SA_BUF    9216
#define SB_OFF    18432
#define SB_BUF    32768
#define SOUT_OFF  0
#define SBIAS_OFF 83968
#define SG_OFF    84992
#define SBV_OFF   86016
#define MBAR_OFF  87040                   // 2 x u64
#define SMEM_BYTES 87072

__device__ __forceinline__ float fast_silu(float y) {
    return __fdividef(y, 1.0f + __expf(-y));
}

__device__ __forceinline__ uint32_t packh(float a, float b) {
    __half2 h = __floats2half2_rn(a, b);
    return *(uint32_t*)&h;
}
__device__ __forceinline__ float2 unpackh(uint32_t u) {
    __half2 h = *(__half2*)&u;
    return __half22float2(h);
}

__device__ __forceinline__ void mma_f16(float c[4], const uint32_t a[4],
                                        uint32_t b0, uint32_t b1) {
    asm volatile(
        "mma.sync.aligned.m16n8k16.row.col.f32.f16.f16.f32 "
        "{%0,%1,%2,%3}, {%4,%5,%6,%7}, {%8,%9}, {%0,%1,%2,%3};"
        : "+f"(c[0]), "+f"(c[1]), "+f"(c[2]), "+f"(c[3])
        : "r"(a[0]), "r"(a[1]), "r"(a[2]), "r"(a[3]), "r"(b0), "r"(b1));
}

__device__ __forceinline__ void red_v4(float* p, float a, float b, float c, float d) {
    asm volatile("red.global.add.v4.f32 [%0], {%1,%2,%3,%4};"
                 :: "l"(p), "f"(a), "f"(b), "f"(c), "f"(d) : "memory");
}

__device__ __forceinline__ void cp16(uint32_t smem_dst, const void* gsrc) {
    asm volatile("cp.async.cg.shared.global [%0], [%1], 16;\n"
                 :: "r"(smem_dst), "l"(gsrc));
}
#define CP_COMMIT() asm volatile("cp.async.commit_group;\n" ::: "memory")
#define CP_WAIT(n)  asm volatile("cp.async.wait_group %0;\n" :: "n"(n) : "memory")

__device__ __forceinline__ void mbar_init(uint32_t mbar, uint32_t count) {
    asm volatile("mbarrier.init.shared.b64 [%0], %1;" :: "r"(mbar), "r"(count) : "memory");
}
__device__ __forceinline__ void mbar_expect_tx(uint32_t mbar, uint32_t bytes) {
    asm volatile("mbarrier.arrive.expect_tx.shared.b64 _, [%0], %1;"
                 :: "r"(mbar), "r"(bytes) : "memory");
}
__device__ __forceinline__ void mbar_wait(uint32_t mbar, uint32_t parity) {
    asm volatile(
        "{\n\t.reg .pred P1;\n\t"
        "WAIT_LOOP_%=:\n\t"
        "mbarrier.try_wait.parity.acquire.cta.shared::cta.b64 P1, [%0], %1, 0x989680;\n\t"
        "@P1 bra.uni WAIT_DONE_%=;\n\t"
        "bra.uni WAIT_LOOP_%=;\n\t"
        "WAIT_DONE_%=:\n\t}"
        :: "r"(mbar), "r"(parity) : "memory");
}
__device__ __forceinline__ void bulk_cp(uint32_t smem_dst, const void* gsrc,
                                        uint32_t bytes, uint32_t mbar) {
    asm volatile(
        "cp.async.bulk.shared::cta.global.mbarrier::complete_tx::bytes [%0], [%1], %2, [%3];"
        :: "r"(smem_dst), "l"(gsrc), "r"(bytes), "r"(mbar) : "memory");
}

// LN(256)+SiLU; row spread as 8 vals/lane (cols tx*4+j / 128+tx*4+j-4)
__device__ __forceinline__ void ln_silu_row(float v[8], int tx,
                                            const float* sG, const float* sB) {
    float s = v[0] + v[1] + v[2] + v[3] + v[4] + v[5] + v[6] + v[7];
#pragma unroll
    for (int o = 16; o > 0; o >>= 1) s += __shfl_xor_sync(0xffffffffu, s, o);
    float mean = s * (1.0f / 256.0f);
    float vs = 0.f;
#pragma unroll
    for (int j = 0; j < 8; j++) { float d = v[j] - mean; vs += d * d; }
#pragma unroll
    for (int o = 16; o > 0; o >>= 1) vs += __shfl_xor_sync(0xffffffffu, vs, o);
    float rstd = rsqrtf(vs * (1.0f / 256.0f) + 1e-5f);
#pragma unroll
    for (int j = 0; j < 8; j++) {
        int col = (j < 4) ? (tx * 4 + j) : (128 + tx * 4 + j - 4);
        float y = (v[j] - mean) * rstd * sG[col] + sB[col];
        v[j] = fast_silu(y);
    }
}

// one K64 superchunk: four k16 halves, 1 MMA each
// sA row stride 36 words (144B); bank = (4r + 8h + q) mod 32, conflict-free
__device__ __forceinline__ void compute_schunk(const char* smraw, int buf,
                                               int wm, int wn, int lane,
                                               float acc[2][8][4]) {
    const uint32_t* sAp = (const uint32_t*)(smraw + SA_OFF + buf * SA_BUF);
    const uint2* sBp = (const uint2*)(smraw + SB_OFF + buf * SB_BUF);
    const int q = lane & 3;
#pragma unroll
    for (int h = 0; h < 4; h++) {
        uint32_t a[2][4];
#pragma unroll
        for (int mt = 0; mt < 2; mt++) {
            int r = wm * 32 + mt * 16 + (lane >> 2);
            a[mt][0] = sAp[r * 36 + h * 8 + q];
            a[mt][1] = sAp[(r + 8) * 36 + h * 8 + q];
            a[mt][2] = sAp[r * 36 + h * 8 + q + 4];
            a[mt][3] = sAp[(r + 8) * 36 + h * 8 + q + 4];
        }
#pragma unroll
        for (int nt = 0; nt < 8; nt++) {
            uint2 b = sBp[h * 1024 + wn * 256 + nt * 32 + lane];
#pragma unroll
            for (int mt = 0; mt < 2; mt++)
                mma_f16(acc[mt][nt], a[mt], b.x, b.y);
        }
    }
}

template <typename FA>
__device__ __forceinline__ void gemm_pipeline(FA stageA, const uint2* __restrict__ Wp,
                                              char* smraw, uint32_t sbase, int tid,
                                              int wm, int wn, int lane, int schunks,
                                              float acc[2][8][4]) {
    const uint32_t mbar0 = sbase + MBAR_OFF;
    auto issueB = [&](int c, int buf) {
        if (tid == 0) {
            uint32_t mb = mbar0 + buf * 8;
            mbar_expect_tx(mb, SB_BUF);
            bulk_cp(sbase + SB_OFF + buf * SB_BUF, Wp + (size_t)c * 4096, SB_BUF, mb);
        }
    };
    stageA(0, 0); CP_COMMIT(); issueB(0, 0);
#pragma unroll 1
    for (int c = 0; c < schunks; c++) {
        if (c + 1 < schunks) {
            stageA(c + 1, (c + 1) & 1); CP_COMMIT(); issueB(c + 1, (c + 1) & 1);
            CP_WAIT(1);
        } else {
            CP_WAIT(0);
        }
        mbar_wait(mbar0 + (c & 1) * 8, (c >> 1) & 1);
        __syncthreads();
        compute_schunk(smraw, c & 1, wm, wn, lane, acc);
        __syncthreads();
    }
}

__device__ __forceinline__ void acc_to_sout(char* smraw, int wm, int wn,
                                            int lane, float acc[2][8][4],
                                            const float* sBias) {
    float (*sOut)[260] = (float(*)[260])(smraw + SOUT_OFF);
#pragma unroll
    for (int mt = 0; mt < 2; mt++)
#pragma unroll
        for (int nt = 0; nt < 8; nt++) {
            int r0 = wm * 32 + mt * 16 + (lane >> 2);
            int c = wn * 64 + nt * 8 + 2 * (lane & 3);
            float b0 = sBias ? sBias[c] : 0.f;
            float b1 = sBias ? sBias[c + 1] : 0.f;
            sOut[r0][c]         = acc[mt][nt][0] + b0;
            sOut[r0][c + 1]     = acc[mt][nt][1] + b1;
            sOut[r0 + 8][c]     = acc[mt][nt][2] + b0;
            sOut[r0 + 8][c + 1] = acc[mt][nt][3] + b1;
        }
}

// ---------------------------------------------------------------------------
// packers
// ---------------------------------------------------------------------------
__global__ void pack_w_frag(const float* __restrict__ W, uint2* __restrict__ out,
                            int Ksrc, int lstride, int C, int NL) {
    size_t idx = (size_t)blockIdx.x * blockDim.x + threadIdx.x;
    size_t total = (size_t)NL * C * 1024;
    if (idx >= total) return;
    int t = (int)(idx & 1023);
    int lane = t & 31, nt = (t >> 5) & 7, wn = t >> 8;
    int c = (int)((idx >> 10) % C);
    int l = (int)(idx / ((size_t)C * 1024));
    int n = wn * 64 + nt * 8 + (lane >> 2);
    int q = lane & 3;
    int kp0 = c * 8 + q, kp1 = c * 8 + q + 4;
    const float* Wl = W + (size_t)l * lstride * 256;
    float a0 = (2 * kp0     < Ksrc) ? Wl[(size_t)(2 * kp0)     * 256 + n] : 0.f;
    float a1 = (2 * kp0 + 1 < Ksrc) ? Wl[(size_t)(2 * kp0 + 1) * 256 + n] : 0.f;
    float b0 = (2 * kp1     < Ksrc) ? Wl[(size_t)(2 * kp1)     * 256 + n] : 0.f;
    float b1 = (2 * kp1 + 1 < Ksrc) ? Wl[(size_t)(2 * kp1 + 1) * 256 + n] : 0.f;
    out[idx] = make_uint2(packh(a0, a1), packh(b0, b1));
}

__global__ void convert_h(const float* __restrict__ in, uint32_t* __restrict__ out,
                          int n) {
    int i = blockIdx.x * blockDim.x + threadIdx.x;
    if (i < n) {
        float2 v = ((const float2*)in)[i];
        out[i] = packh(v.x, v.y);
    }
}

__global__ void zero_kernel(float4* __restrict__ p, int n4) {
    int i = blockIdx.x * blockDim.x + threadIdx.x;
    if (i < n4) p[i] = make_float4(0.f, 0.f, 0.f, 0.f);
}

// ---------------------------------------------------------------------------
// y12 kernel: y = x @ We[half*256 : (half+1)*256] (no bias) -> fp16x2 rows
// ---------------------------------------------------------------------------
__global__ __launch_bounds__(256, 2) void y12_kernel(
    const uint32_t* __restrict__ xs, const uint2* __restrict__ WpBase,
    uint32_t* __restrict__ y1h, uint32_t* __restrict__ y2h, int N) {
    extern __shared__ char smraw[];
    const int tid = threadIdx.x;
    const int lane = tid & 31, warp = tid >> 5;
    const int wm = warp >> 2, wn = warp & 3;
    const int n0 = blockIdx.x * 64;
    const int half = blockIdx.y;
    const uint32_t sbase = (uint32_t)__cvta_generic_to_shared(smraw);
    const int arow = tid >> 2, apart = tid & 3;
    int rowg = n0 + arow; if (rowg >= N) rowg = N - 1;

    if (tid == 0) { mbar_init(sbase + MBAR_OFF, 1); mbar_init(sbase + MBAR_OFF + 8, 1); }
    __syncthreads();

    const uint2* Wp = WpBase + (size_t)half * 16 * 1024;
    uint32_t* yout = half ? y2h : y1h;

    float acc[2][8][4];
#pragma unroll
    for (int mt = 0; mt < 2; mt++)
#pragma unroll
        for (int nt = 0; nt < 8; nt++)
#pragma unroll
            for (int j = 0; j < 4; j++) acc[mt][nt][j] = 0.f;

    auto stageA = [&](int c, int buf) {
        const char* src = (const char*)(xs + (size_t)rowg * 128) + c * 128 + apart * 32;
        uint32_t d = sbase + SA_OFF + buf * SA_BUF + arow * 144 + apart * 32;
        cp16(d, src); cp16(d + 16, src + 16);
    };
    gemm_pipeline(stageA, Wp, smraw, sbase, tid, wm, wn, lane, 4, acc);

    acc_to_sout(smraw, wm, wn, lane, acc, nullptr);
    __syncthreads();
    float (*sOut)[260] = (float(*)[260])(smraw + SOUT_OFF);
#pragma unroll 1
    for (int i = 0; i < 8; i++) {
        int r = i * 8 + warp;
        int row = n0 + r;
        if (row < N) {
            float4 lo = *(float4*)&sOut[r][lane * 4];
            float4 hi = *(float4*)&sOut[r][128 + lane * 4];
            uint32_t* op = yout + (size_t)row * 128;
            *(uint2*)(op + lane * 2)      = make_uint2(packh(lo.x, lo.y), packh(lo.z, lo.w));
            *(uint2*)(op + 64 + lane * 2) = make_uint2(packh(hi.x, hi.y), packh(hi.z, hi.w));
        }
    }
}

// ---------------------------------------------------------------------------
// Edge pass: h = y1h[dst]+y2h[src]+ea@W3+b; silu(LN(h)) -> f32 red.v4 into agg
// R9 layout: lane owns cols lane*4+j (j<4) and 128+lane*4+(j-4); contiguous REDs
// ---------------------------------------------------------------------------
__global__ __launch_bounds__(256) void edge_pass(
    const uint32_t* __restrict__ y1h, const uint32_t* __restrict__ y2h,
    const int* __restrict__ eidx, const float* __restrict__ ea,
    const float* __restrict__ W3, const float* __restrict__ Wb,
    const float* __restrict__ gam, const float* __restrict__ bet,
    float* __restrict__ agg, int D) {
    const int lane = threadIdx.x & 31, warp = threadIdx.x >> 5;
    const int e = blockIdx.x * 8 + warp;

    float w3r[4][8], biasr[8], gr[8], br[8];
#pragma unroll
    for (int j = 0; j < 8; j++) {
        int col = (j < 4) ? (lane * 4 + j) : (128 + lane * 4 + j - 4);
        biasr[j] = __ldg(Wb + col);
        gr[j] = __ldg(gam + col);
        br[j] = __ldg(bet + col);
#pragma unroll
        for (int k = 0; k < 4; k++) w3r[k][j] = __ldg(W3 + k * 256 + col);
    }
    if (e >= D) return;

    int src = __ldg(eidx + e);
    int dst = __ldg(eidx + (size_t)D + e);
    uint2 u1lo = *(const uint2*)(y1h + (size_t)dst * 128 + lane * 2);
    uint2 u1hi = *(const uint2*)(y1h + (size_t)dst * 128 + 64 + lane * 2);
    uint2 u2lo = *(const uint2*)(y2h + (size_t)src * 128 + lane * 2);
    uint2 u2hi = *(const uint2*)(y2h + (size_t)src * 128 + 64 + lane * 2);
    float4 eav = *(const float4*)(ea + (size_t)e * 4);

    float v[8];
    {
        float2 a0 = unpackh(u1lo.x), a1 = unpackh(u1lo.y);
        float2 a2 = unpackh(u1hi.x), a3 = unpackh(u1hi.y);
        float2 c0 = unpackh(u2lo.x), c1 = unpackh(u2lo.y);
        float2 c2 = unpackh(u2hi.x), c3 = unpackh(u2hi.y);
        v[0] = a0.x + c0.x; v[1] = a0.y + c0.y;
        v[2] = a1.x + c1.x; v[3] = a1.y + c1.y;
        v[4] = a2.x + c2.x; v[5] = a2.y + c2.y;
        v[6] = a3.x + c3.x; v[7] = a3.y + c3.y;
    }
#pragma unroll
    for (int j = 0; j < 8; j++) {
        float h = v[j] + biasr[j];
        h = fmaf(eav.x, w3r[0][j], h);
        h = fmaf(eav.y, w3r[1][j], h);
        h = fmaf(eav.z, w3r[2][j], h);
        h = fmaf(eav.w, w3r[3][j], h);
        v[j] = h;
    }
    float s = v[0] + v[1] + v[2] + v[3] + v[4] + v[5] + v[6] + v[7];
#pragma unroll
    for (int o = 16; o > 0; o >>= 1) s += __shfl_xor_sync(0xffffffffu, s, o);
    float mean = s * (1.0f / 256.0f);
    float vs = 0.f;
#pragma unroll
    for (int j = 0; j < 8; j++) { float d = v[j] - mean; vs += d * d; }
#pragma unroll
    for (int o = 16; o > 0; o >>= 1) vs += __shfl_xor_sync(0xffffffffu, vs, o);
    float rstd = rsqrtf(vs * (1.0f / 256.0f) + 1e-5f);

    float m[8];
#pragma unroll
    for (int j = 0; j < 8; j++)
        m[j] = fast_silu((v[j] - mean) * rstd * gr[j] + br[j]);

    float* ag = agg + (size_t)dst * 256;
    red_v4(ag + lane * 4,       m[0], m[1], m[2], m[3]);
    red_v4(ag + 128 + lane * 4, m[4], m[5], m[6], m[7]);
}

// ---------------------------------------------------------------------------
// Node kernel 1: t = silu(LN(x@Wn1[:256] + aggs@Wn1[256:] + b)) -> tmps (fp16)
// ---------------------------------------------------------------------------
__global__ __launch_bounds__(256, 2) void node1_kernel(
    const uint32_t* __restrict__ xs, const uint32_t* __restrict__ aggs,
    const uint2* __restrict__ Wp, const float* __restrict__ Wb,
    const float* __restrict__ gam, const float* __restrict__ bet,
    uint32_t* __restrict__ tmps, int N) {
    extern __shared__ char smraw[];
    float* sBias = (float*)(smraw + SBIAS_OFF);
    float* sG    = (float*)(smraw + SG_OFF);
    float* sBv   = (float*)(smraw + SBV_OFF);

    const int tid = threadIdx.x;
    const int lane = tid & 31, warp = tid >> 5;
    const int wm = warp >> 2, wn = warp & 3;
    const int n0 = blockIdx.x * 64;
    const uint32_t sbase = (uint32_t)__cvta_generic_to_shared(smraw);
    const int arow = tid >> 2, apart = tid & 3;

    sBias[tid] = Wb[tid]; sG[tid] = gam[tid]; sBv[tid] = bet[tid];
    if (tid == 0) { mbar_init(sbase + MBAR_OFF, 1); mbar_init(sbase + MBAR_OFF + 8, 1); }
    __syncthreads();

    int rowg = n0 + arow; if (rowg >= N) rowg = N - 1;

    float acc[2][8][4];
#pragma unroll
    for (int mt = 0; mt < 2; mt++)
#pragma unroll
        for (int nt = 0; nt < 8; nt++)
#pragma unroll
            for (int j = 0; j < 4; j++) acc[mt][nt][j] = 0.f;

    auto stageA = [&](int c, int buf) {
        const uint32_t* bA = (c < 4) ? xs : aggs;
        const char* src = (const char*)(bA + (size_t)rowg * 128) + (c & 3) * 128 + apart * 32;
        uint32_t d = sbase + SA_OFF + buf * SA_BUF + arow * 144 + apart * 32;
        cp16(d, src); cp16(d + 16, src + 16);
    };
    gemm_pipeline(stageA, Wp, smraw, sbase, tid, wm, wn, lane, 8, acc);

    acc_to_sout(smraw, wm, wn, lane, acc, sBias);
    __syncthreads();
    float (*sOut)[260] = (float(*)[260])(smraw + SOUT_OFF);
#pragma unroll 1
    for (int i = 0; i < 8; i++) {
        int r = i * 8 + warp;
        float vv[8];
        *(float4*)&vv[0] = *(float4*)&sOut[r][lane * 4];
        *(float4*)&vv[4] = *(float4*)&sOut[r][128 + lane * 4];
        ln_silu_row(vv, lane, sG, sBv);
        int row = n0 + r;
        if (row < N) {
            uint32_t* op = tmps + (size_t)row * 128;
            op[lane * 2]          = packh(vv[0], vv[1]);
            op[lane * 2 + 1]      = packh(vv[2], vv[3]);
            op[64 + lane * 2]     = packh(vv[4], vv[5]);
            op[64 + lane * 2 + 1] = packh(vv[6], vv[7]);
        }
    }
}

// ---------------------------------------------------------------------------
// Node kernel 2: out = x + t@Wn2 + b2; also writes fp16 xs for next layer
// ---------------------------------------------------------------------------
__global__ __launch_bounds__(256, 2) void node2_kernel(
    const uint32_t* __restrict__ tmps, const float* __restrict__ xres,
    const uint2* __restrict__ Wp, const float* __restrict__ Wb,
    float* __restrict__ out, uint32_t* __restrict__ xs_next, int N) {
    extern __shared__ char smraw[];
    float* sBias = (float*)(smraw + SBIAS_OFF);

    const int tid = threadIdx.x;
    const int lane = tid & 31, warp = tid >> 5;
    const int wm = warp >> 2, wn = warp & 3;
    const int n0 = blockIdx.x * 64;
    const uint32_t sbase = (uint32_t)__cvta_generic_to_shared(smraw);
    const int arow = tid >> 2, apart = tid & 3;

    sBias[tid] = Wb[tid];
    if (tid == 0) { mbar_init(sbase + MBAR_OFF, 1); mbar_init(sbase + MBAR_OFF + 8, 1); }
    __syncthreads();

    int rowg = n0 + arow; if (rowg >= N) rowg = N - 1;

    float acc[2][8][4];
#pragma unroll
    for (int mt = 0; mt < 2; mt++)
#pragma unroll
        for (int nt = 0; nt < 8; nt++)
#pragma unroll
            for (int j = 0; j < 4; j++) acc[mt][nt][j] = 0.f;

    auto stageA = [&](int c, int buf) {
        const char* src = (const char*)(tmps + (size_t)rowg * 128) + c * 128 + apart * 32;
        uint32_t d = sbase + SA_OFF + buf * SA_BUF + arow * 144 + apart * 32;
        cp16(d, src); cp16(d + 16, src + 16);
    };
    gemm_pipeline(stageA, Wp, smraw, sbase, tid, wm, wn, lane, 4, acc);

    acc_to_sout(smraw, wm, wn, lane, acc, sBias);
    __syncthreads();
    float (*sOut)[260] = (float(*)[260])(smraw + SOUT_OFF);
#pragma unroll 1
    for (int i = 0; i < 8; i++) {
        int r = i * 8 + warp;
        int row = n0 + r;
        if (row < N) {
            const float* xr = xres + (size_t)row * 256;
            float4 lo = *(float4*)&sOut[r][lane * 4];
            float4 hi = *(float4*)&sOut[r][128 + lane * 4];
            float4 xlo = *(const float4*)(xr + lane * 4);
            float4 xhi = *(const float4*)(xr + 128 + lane * 4);
            lo.x += xlo.x; lo.y += xlo.y; lo.z += xlo.z; lo.w += xlo.w;
            hi.x += xhi.x; hi.y += xhi.y; hi.z += xhi.z; hi.w += xhi.w;
            float* op = out + (size_t)row * 256;
            *(float4*)(op + lane * 4) = lo;
            *(float4*)(op + 128 + lane * 4) = hi;
            uint32_t* xp = xs_next + (size_t)row * 128;
            xp[lane * 2]          = packh(lo.x, lo.y);
            xp[lane * 2 + 1]      = packh(lo.z, lo.w);
            xp[64 + lane * 2]     = packh(hi.x, hi.y);
            xp[64 + lane * 2 + 1] = packh(hi.z, hi.w);
        }
    }
}

// ---------------------------------------------------------------------------
extern "C" void kernel_launch(void* const* d_in, const int* in_sizes, int n_in,
                              void* d_out, int out_size) {
    const float* x_in  = (const float*)d_in[0];
    const int*   eidx  = (const int*)d_in[1];
    const float* ea    = (const float*)d_in[2];
    const float* We_w  = (const float*)d_in[3];
    const float* We_b  = (const float*)d_in[4];
    const float* g1    = (const float*)d_in[5];
    const float* b1    = (const float*)d_in[6];
    const float* Wn1_w = (const float*)d_in[7];
    const float* Wn1_b = (const float*)d_in[8];
    const float* g2    = (const float*)d_in[9];
    const float* b2    = (const float*)d_in[10];
    const float* Wn2_w = (const float*)d_in[11];
    const float* Wn2_b = (const float*)d_in[12];

    const int N  = in_sizes[0] / 256;
    const int D  = in_sizes[1] / 2;
    const int NL = in_sizes[4] / 256;

    float *bufA, *bufB, *aggp;
    uint32_t *y1h, *y2h, *xs, *aggs, *tmps;
    uint2 *wE, *wN1, *wN2;
    cudaGetSymbolAddress((void**)&bufA, g_bufA);
    cudaGetSymbolAddress((void**)&bufB, g_bufB);
    cudaGetSymbolAddress((void**)&aggp, g_agg);
    cudaGetSymbolAddress((void**)&y1h,  g_y1h);
    cudaGetSymbolAddress((void**)&y2h,  g_y2h);
    cudaGetSymbolAddress((void**)&xs,   g_xs);
    cudaGetSymbolAddress((void**)&aggs, g_aggs);
    cudaGetSymbolAddress((void**)&tmps, g_tmps);
    cudaGetSymbolAddress((void**)&wE,   g_We);
    cudaGetSymbolAddress((void**)&wN1,  g_Wn1);
    cudaGetSymbolAddress((void**)&wN2,  g_Wn2);

    cudaFuncSetAttribute(y12_kernel,   cudaFuncAttributeMaxDynamicSharedMemorySize, SMEM_BYTES);
    cudaFuncSetAttribute(node1_kernel, cudaFuncAttributeMaxDynamicSharedMemorySize, SMEM_BYTES);
    cudaFuncSetAttribute(node2_kernel, cudaFuncAttributeMaxDynamicSharedMemorySize, SMEM_BYTES);

    // one-time packs (deterministic, inside capture)
    {
        size_t t0 = (size_t)NL * 32 * 1024;
        pack_w_frag<<<(int)((t0 + 255) / 256), 256>>>(We_w, wE, 512, 516, 32, NL);
        pack_w_frag<<<(int)((t0 + 255) / 256), 256>>>(Wn1_w, wN1, 512, 512, 32, NL);
        size_t t2 = (size_t)NL * 16 * 1024;
        pack_w_frag<<<(int)((t2 + 255) / 256), 256>>>(Wn2_w, wN2, 256, 256, 16, NL);
        int nx = N * 128;
        convert_h<<<(nx + 255) / 256, 256>>>(x_in, xs, nx);
    }

    const int nblk_n = (N + 63) / 64;
    const int nblk_e = (D + 7) / 8;
    const int n4 = (N * 256) / 4;
    const int zblk = (n4 + 255) / 256;
    const int ncv = N * 128;
    const int cvblk = (ncv + 255) / 256;

    const float* xcur = x_in;
    for (int l = 0; l < NL; l++) {
        float* xnext = (l == NL - 1) ? (float*)d_out : ((l & 1) ? bufB : bufA);
        zero_kernel<<<zblk, 256>>>((float4*)aggp, n4);
        y12_kernel<<<dim3(nblk_n, 2), 256, SMEM_BYTES>>>(
            xs, wE + (size_t)l * 32 * 1024, y1h, y2h, N);
        edge_pass<<<nblk_e, 256>>>(
            y1h, y2h, eidx, ea,
            We_w + (size_t)l * 516 * 256 + (size_t)512 * 256,
            We_b + (size_t)l * 256, g1 + (size_t)l * 256, b1 + (size_t)l * 256,
            aggp, D);
        convert_h<<<cvblk, 256>>>(aggp, aggs, ncv);
        node1_kernel<<<nblk_n, 256, SMEM_BYTES>>>(
            xs, aggs, wN1 + (size_t)l * 32 * 1024,
            Wn1_b + (size_t)l * 256, g2 + (size_t)l * 256, b2 + (size_t)l * 256,
            tmps, N);
        node2_kernel<<<nblk_n, 256, SMEM_BYTES>>>(
            tmps, xcur, wN2 + (size_t)l * 16 * 1024,
            Wn2_b + (size_t)l * 256, xnext, xs, N);
        xcur = xnext;
    }
}

// round 16
// speedup vs baseline: 1.6544x; 1.0104x over previous
#include <cuda_runtime.h>
#include <cuda_fp16.h>
#include <cstdint>

// ============================================================================
// GraphCastProcessor — plain fp16 mma.sync GEMMs (1 MMA/k16, fp32 acc),
// K-superchunk 64, A-fragments via ldmatrix.x4, fused convert+zero pass.
//   y1 = x@We[:256], y2 = x@We[256:512]          (fp16x2 out)
//   h_e = y1[dst]+y2[src]+ea@W3+b ; msg = silu(LN(h)); agg += msg (f32 RED)
//   u = x@Wn1[:256]+agg@Wn1[256:]+b ; t = silu(LN(u))
//   x = x + t@Wn2 + b2
// ============================================================================

#define MAXN 40962
#define MAXD 163848
#define MAXNL 6

__device__ float g_bufA[MAXN * 256];
__device__ float g_bufB[MAXN * 256];
__device__ float g_agg [MAXN * 256];
__device__ uint32_t g_y1h [MAXN * 128];   // fp16x2 rows (512B)
__device__ uint32_t g_y2h [MAXN * 128];
__device__ uint32_t g_xs  [MAXN * 128];   // fp16x2 activations
__device__ uint32_t g_aggs[MAXN * 128];
__device__ uint32_t g_tmps[MAXN * 128];
// fragment-ordered fp16 weights: [layer][chunk16][wn(4)][nt(8)][lane(32)]
// uint2 = {k0pair, k1pair}
__device__ uint2 g_We [MAXNL * 32 * 1024];
__device__ uint2 g_Wn1[MAXNL * 32 * 1024];
__device__ uint2 g_Wn2[MAXNL * 16 * 1024];

// ---- dynamic smem layout (bytes) ----
// sA: 2 bufs x 64 rows x 144B (128B data + 16B pad) = 18432
// sB: 2 bufs x 32768B (4 k16-chunks of weights)     = 65536 -> ends 83968
// sOut aliases offset 0 (66560B)
#define SA_OFF    0
#define SA_BUF    9216
#define SB_OFF    18432
#define SB_BUF    32768
#define SOUT_OFF  0
#define SBIAS_OFF 83968
#define SG_OFF    84992
#define SBV_OFF   86016
#define MBAR_OFF  87040                   // 2 x u64
#define SMEM_BYTES 87072

__device__ __forceinline__ float fast_silu(float y) {
    return __fdividef(y, 1.0f + __expf(-y));
}

__device__ __forceinline__ uint32_t packh(float a, float b) {
    __half2 h = __floats2half2_rn(a, b);
    return *(uint32_t*)&h;
}
__device__ __forceinline__ float2 unpackh(uint32_t u) {
    __half2 h = *(__half2*)&u;
    return __half22float2(h);
}

__device__ __forceinline__ void mma_f16(float c[4], const uint32_t a[4],
                                        uint32_t b0, uint32_t b1) {
    asm volatile(
        "mma.sync.aligned.m16n8k16.row.col.f32.f16.f16.f32 "
        "{%0,%1,%2,%3}, {%4,%5,%6,%7}, {%8,%9}, {%0,%1,%2,%3};"
        : "+f"(c[0]), "+f"(c[1]), "+f"(c[2]), "+f"(c[3])
        : "r"(a[0]), "r"(a[1]), "r"(a[2]), "r"(a[3]), "r"(b0), "r"(b1));
}

__device__ __forceinline__ void ldsm_x4(uint32_t a[4], uint32_t addr) {
    asm volatile("ldmatrix.sync.aligned.m8n8.x4.shared.b16 {%0,%1,%2,%3}, [%4];"
                 : "=r"(a[0]), "=r"(a[1]), "=r"(a[2]), "=r"(a[3]) : "r"(addr));
}

__device__ __forceinline__ void red_v4(float* p, float a, float b, float c, float d) {
    asm volatile("red.global.add.v4.f32 [%0], {%1,%2,%3,%4};"
                 :: "l"(p), "f"(a), "f"(b), "f"(c), "f"(d) : "memory");
}

__device__ __forceinline__ void cp16(uint32_t smem_dst, const void* gsrc) {
    asm volatile("cp.async.cg.shared.global [%0], [%1], 16;\n"
                 :: "r"(smem_dst), "l"(gsrc));
}
#define CP_COMMIT() asm volatile("cp.async.commit_group;\n" ::: "memory")
#define CP_WAIT(n)  asm volatile("cp.async.wait_group %0;\n" :: "n"(n) : "memory")

__device__ __forceinline__ void mbar_init(uint32_t mbar, uint32_t count) {
    asm volatile("mbarrier.init.shared.b64 [%0], %1;" :: "r"(mbar), "r"(count) : "memory");
}
__device__ __forceinline__ void mbar_expect_tx(uint32_t mbar, uint32_t bytes) {
    asm volatile("mbarrier.arrive.expect_tx.shared.b64 _, [%0], %1;"
                 :: "r"(mbar), "r"(bytes) : "memory");
}
__device__ __forceinline__ void mbar_wait(uint32_t mbar, uint32_t parity) {
    asm volatile(
        "{\n\t.reg .pred P1;\n\t"
        "WAIT_LOOP_%=:\n\t"
        "mbarrier.try_wait.parity.acquire.cta.shared::cta.b64 P1, [%0], %1, 0x989680;\n\t"
        "@P1 bra.uni WAIT_DONE_%=;\n\t"
        "bra.uni WAIT_LOOP_%=;\n\t"
        "WAIT_DONE_%=:\n\t}"
        :: "r"(mbar), "r"(parity) : "memory");
}
__device__ __forceinline__ void bulk_cp(uint32_t smem_dst, const void* gsrc,
                                        uint32_t bytes, uint32_t mbar) {
    asm volatile(
        "cp.async.bulk.shared::cta.global.mbarrier::complete_tx::bytes [%0], [%1], %2, [%3];"
        :: "r"(smem_dst), "l"(gsrc), "r"(bytes), "r"(mbar) : "memory");
}

// LN(256)+SiLU; row spread as 8 vals/lane (cols tx*4+j / 128+tx*4+j-4)
__device__ __forceinline__ void ln_silu_row(float v[8], int tx,
                                            const float* sG, const float* sB) {
    float s = v[0] + v[1] + v[2] + v[3] + v[4] + v[5] + v[6] + v[7];
#pragma unroll
    for (int o = 16; o > 0; o >>= 1) s += __shfl_xor_sync(0xffffffffu, s, o);
    float mean = s * (1.0f / 256.0f);
    float vs = 0.f;
#pragma unroll
    for (int j = 0; j < 8; j++) { float d = v[j] - mean; vs += d * d; }
#pragma unroll
    for (int o = 16; o > 0; o >>= 1) vs += __shfl_xor_sync(0xffffffffu, vs, o);
    float rstd = rsqrtf(vs * (1.0f / 256.0f) + 1e-5f);
#pragma unroll
    for (int j = 0; j < 8; j++) {
        int col = (j < 4) ? (tx * 4 + j) : (128 + tx * 4 + j - 4);
        float y = (v[j] - mean) * rstd * sG[col] + sB[col];
        v[j] = fast_silu(y);
    }
}

// one K64 superchunk: four k16 halves, 1 MMA each; A via ldmatrix.x4
// sA row stride 144B; ldmatrix addr: (lane&15)*144 + h*32 + (lane>>4)*16
__device__ __forceinline__ void compute_schunk(char* smraw, uint32_t sbase, int buf,
                                               int wm, int wn, int lane,
                                               float acc[2][8][4]) {
    const uint2* sBp = (const uint2*)(smraw + SB_OFF + buf * SB_BUF);
    const uint32_t abase = sbase + SA_OFF + buf * SA_BUF
                         + (uint32_t)(lane & 15) * 144 + (uint32_t)(lane >> 4) * 16;
#pragma unroll
    for (int h = 0; h < 4; h++) {
        uint32_t a[2][4];
#pragma unroll
        for (int mt = 0; mt < 2; mt++)
            ldsm_x4(a[mt], abase + (wm * 32 + mt * 16) * 144 + h * 32);
#pragma unroll
        for (int nt = 0; nt < 8; nt++) {
            uint2 b = sBp[h * 1024 + wn * 256 + nt * 32 + lane];
#pragma unroll
            for (int mt = 0; mt < 2; mt++)
                mma_f16(acc[mt][nt], a[mt], b.x, b.y);
        }
    }
}

template <typename FA>
__device__ __forceinline__ void gemm_pipeline(FA stageA, const uint2* __restrict__ Wp,
                                              char* smraw, uint32_t sbase, int tid,
                                              int wm, int wn, int lane, int schunks,
                                              float acc[2][8][4]) {
    const uint32_t mbar0 = sbase + MBAR_OFF;
    auto issueB = [&](int c, int buf) {
        if (tid == 0) {
            uint32_t mb = mbar0 + buf * 8;
            mbar_expect_tx(mb, SB_BUF);
            bulk_cp(sbase + SB_OFF + buf * SB_BUF, Wp + (size_t)c * 4096, SB_BUF, mb);
        }
    };
    stageA(0, 0); CP_COMMIT(); issueB(0, 0);
#pragma unroll 1
    for (int c = 0; c < schunks; c++) {
        if (c + 1 < schunks) {
            stageA(c + 1, (c + 1) & 1); CP_COMMIT(); issueB(c + 1, (c + 1) & 1);
            CP_WAIT(1);
        } else {
            CP_WAIT(0);
        }
        mbar_wait(mbar0 + (c & 1) * 8, (c >> 1) & 1);
        __syncthreads();
        compute_schunk(smraw, sbase, c & 1, wm, wn, lane, acc);
        __syncthreads();
    }
}

__device__ __forceinline__ void acc_to_sout(char* smraw, int wm, int wn,
                                            int lane, float acc[2][8][4],
                                            const float* sBias) {
    float (*sOut)[260] = (float(*)[260])(smraw + SOUT_OFF);
#pragma unroll
    for (int mt = 0; mt < 2; mt++)
#pragma unroll
        for (int nt = 0; nt < 8; nt++) {
            int r0 = wm * 32 + mt * 16 + (lane >> 2);
            int c = wn * 64 + nt * 8 + 2 * (lane & 3);
            float b0 = sBias ? sBias[c] : 0.f;
            float b1 = sBias ? sBias[c + 1] : 0.f;
            sOut[r0][c]         = acc[mt][nt][0] + b0;
            sOut[r0][c + 1]     = acc[mt][nt][1] + b1;
            sOut[r0 + 8][c]     = acc[mt][nt][2] + b0;
            sOut[r0 + 8][c + 1] = acc[mt][nt][3] + b1;
        }
}

// ---------------------------------------------------------------------------
// packers
// ---------------------------------------------------------------------------
__global__ void pack_w_frag(const float* __restrict__ W, uint2* __restrict__ out,
                            int Ksrc, int lstride, int C, int NL) {
    size_t idx = (size_t)blockIdx.x * blockDim.x + threadIdx.x;
    size_t total = (size_t)NL * C * 1024;
    if (idx >= total) return;
    int t = (int)(idx & 1023);
    int lane = t & 31, nt = (t >> 5) & 7, wn = t >> 8;
    int c = (int)((idx >> 10) % C);
    int l = (int)(idx / ((size_t)C * 1024));
    int n = wn * 64 + nt * 8 + (lane >> 2);
    int q = lane & 3;
    int kp0 = c * 8 + q, kp1 = c * 8 + q + 4;
    const float* Wl = W + (size_t)l * lstride * 256;
    float a0 = (2 * kp0     < Ksrc) ? Wl[(size_t)(2 * kp0)     * 256 + n] : 0.f;
    float a1 = (2 * kp0 + 1 < Ksrc) ? Wl[(size_t)(2 * kp0 + 1) * 256 + n] : 0.f;
    float b0 = (2 * kp1     < Ksrc) ? Wl[(size_t)(2 * kp1)     * 256 + n] : 0.f;
    float b1 = (2 * kp1 + 1 < Ksrc) ? Wl[(size_t)(2 * kp1 + 1) * 256 + n] : 0.f;
    out[idx] = make_uint2(packh(a0, a1), packh(b0, b1));
}

__global__ void convert_h(const float* __restrict__ in, uint32_t* __restrict__ out,
                          int n) {
    int i = blockIdx.x * blockDim.x + threadIdx.x;
    if (i < n) {
        float2 v = ((const float2*)in)[i];
        out[i] = packh(v.x, v.y);
    }
}

// read agg -> fp16 aggs, AND re-zero agg for the next layer's edge pass
__global__ void convert_zero(float* __restrict__ agg, uint32_t* __restrict__ out,
                             int n) {
    int i = blockIdx.x * blockDim.x + threadIdx.x;
    if (i < n) {
        float2 v = ((float2*)agg)[i];
        out[i] = packh(v.x, v.y);
        ((float2*)agg)[i] = make_float2(0.f, 0.f);
    }
}

__global__ void zero_kernel(float4* __restrict__ p, int n4) {
    int i = blockIdx.x * blockDim.x + threadIdx.x;
    if (i < n4) p[i] = make_float4(0.f, 0.f, 0.f, 0.f);
}

// ---------------------------------------------------------------------------
// y12 kernel: y = x @ We[half*256 : (half+1)*256] (no bias) -> fp16x2 rows
// ---------------------------------------------------------------------------
__global__ __launch_bounds__(256, 2) void y12_kernel(
    const uint32_t* __restrict__ xs, const uint2* __restrict__ WpBase,
    uint32_t* __restrict__ y1h, uint32_t* __restrict__ y2h, int N) {
    extern __shared__ char smraw[];
    const int tid = threadIdx.x;
    const int lane = tid & 31, warp = tid >> 5;
    const int wm = warp >> 2, wn = warp & 3;
    const int n0 = blockIdx.x * 64;
    const int half = blockIdx.y;
    const uint32_t sbase = (uint32_t)__cvta_generic_to_shared(smraw);
    const int arow = tid >> 2, apart = tid & 3;
    int rowg = n0 + arow; if (rowg >= N) rowg = N - 1;

    if (tid == 0) { mbar_init(sbase + MBAR_OFF, 1); mbar_init(sbase + MBAR_OFF + 8, 1); }
    __syncthreads();

    const uint2* Wp = WpBase + (size_t)half * 16 * 1024;
    uint32_t* yout = half ? y2h : y1h;

    float acc[2][8][4];
#pragma unroll
    for (int mt = 0; mt < 2; mt++)
#pragma unroll
        for (int nt = 0; nt < 8; nt++)
#pragma unroll
            for (int j = 0; j < 4; j++) acc[mt][nt][j] = 0.f;

    auto stageA = [&](int c, int buf) {
        const char* src = (const char*)(xs + (size_t)rowg * 128) + c * 128 + apart * 32;
        uint32_t d = sbase + SA_OFF + buf * SA_BUF + arow * 144 + apart * 32;
        cp16(d, src); cp16(d + 16, src + 16);
    };
    gemm_pipeline(stageA, Wp, smraw, sbase, tid, wm, wn, lane, 4, acc);

    acc_to_sout(smraw, wm, wn, lane, acc, nullptr);
    __syncthreads();
    float (*sOut)[260] = (float(*)[260])(smraw + SOUT_OFF);
#pragma unroll 1
    for (int i = 0; i < 8; i++) {
        int r = i * 8 + warp;
        int row = n0 + r;
        if (row < N) {
            float4 lo = *(float4*)&sOut[r][lane * 4];
            float4 hi = *(float4*)&sOut[r][128 + lane * 4];
            uint32_t* op = yout + (size_t)row * 128;
            *(uint2*)(op + lane * 2)      = make_uint2(packh(lo.x, lo.y), packh(lo.z, lo.w));
            *(uint2*)(op + 64 + lane * 2) = make_uint2(packh(hi.x, hi.y), packh(hi.z, hi.w));
        }
    }
}

// ---------------------------------------------------------------------------
// Edge pass: h = y1h[dst]+y2h[src]+ea@W3+b; silu(LN(h)) -> f32 red.v4 into agg
// R9 layout: lane owns cols lane*4+j (j<4) and 128+lane*4+(j-4); contiguous REDs
// ---------------------------------------------------------------------------
__global__ __launch_bounds__(256) void edge_pass(
    const uint32_t* __restrict__ y1h, const uint32_t* __restrict__ y2h,
    const int* __restrict__ eidx, const float* __restrict__ ea,
    const float* __restrict__ W3, const float* __restrict__ Wb,
    const float* __restrict__ gam, const float* __restrict__ bet,
    float* __restrict__ agg, int D) {
    const int lane = threadIdx.x & 31, warp = threadIdx.x >> 5;
    const int e = blockIdx.x * 8 + warp;

    float w3r[4][8], biasr[8], gr[8], br[8];
#pragma unroll
    for (int j = 0; j < 8; j++) {
        int col = (j < 4) ? (lane * 4 + j) : (128 + lane * 4 + j - 4);
        biasr[j] = __ldg(Wb + col);
        gr[j] = __ldg(gam + col);
        br[j] = __ldg(bet + col);
#pragma unroll
        for (int k = 0; k < 4; k++) w3r[k][j] = __ldg(W3 + k * 256 + col);
    }
    if (e >= D) return;

    int src = __ldg(eidx + e);
    int dst = __ldg(eidx + (size_t)D + e);
    uint2 u1lo = *(const uint2*)(y1h + (size_t)dst * 128 + lane * 2);
    uint2 u1hi = *(const uint2*)(y1h + (size_t)dst * 128 + 64 + lane * 2);
    uint2 u2lo = *(const uint2*)(y2h + (size_t)src * 128 + lane * 2);
    uint2 u2hi = *(const uint2*)(y2h + (size_t)src * 128 + 64 + lane * 2);
    float4 eav = *(const float4*)(ea + (size_t)e * 4);

    float v[8];
    {
        float2 a0 = unpackh(u1lo.x), a1 = unpackh(u1lo.y);
        float2 a2 = unpackh(u1hi.x), a3 = unpackh(u1hi.y);
        float2 c0 = unpackh(u2lo.x), c1 = unpackh(u2lo.y);
        float2 c2 = unpackh(u2hi.x), c3 = unpackh(u2hi.y);
        v[0] = a0.x + c0.x; v[1] = a0.y + c0.y;
        v[2] = a1.x + c1.x; v[3] = a1.y + c1.y;
        v[4] = a2.x + c2.x; v[5] = a2.y + c2.y;
        v[6] = a3.x + c3.x; v[7] = a3.y + c3.y;
    }
#pragma unroll
    for (int j = 0; j < 8; j++) {
        float h = v[j] + biasr[j];
        h = fmaf(eav.x, w3r[0][j], h);
        h = fmaf(eav.y, w3r[1][j], h);
        h = fmaf(eav.z, w3r[2][j], h);
        h = fmaf(eav.w, w3r[3][j], h);
        v[j] = h;
    }
    float s = v[0] + v[1] + v[2] + v[3] + v[4] + v[5] + v[6] + v[7];
#pragma unroll
    for (int o = 16; o > 0; o >>= 1) s += __shfl_xor_sync(0xffffffffu, s, o);
    float mean = s * (1.0f / 256.0f);
    float vs = 0.f;
#pragma unroll
    for (int j = 0; j < 8; j++) { float d = v[j] - mean; vs += d * d; }
#pragma unroll
    for (int o = 16; o > 0; o >>= 1) vs += __shfl_xor_sync(0xffffffffu, vs, o);
    float rstd = rsqrtf(vs * (1.0f / 256.0f) + 1e-5f);

    float m[8];
#pragma unroll
    for (int j = 0; j < 8; j++)
        m[j] = fast_silu((v[j] - mean) * rstd * gr[j] + br[j]);

    float* ag = agg + (size_t)dst * 256;
    red_v4(ag + lane * 4,       m[0], m[1], m[2], m[3]);
    red_v4(ag + 128 + lane * 4, m[4], m[5], m[6], m[7]);
}

// ---------------------------------------------------------------------------
// Node kernel 1: t = silu(LN(x@Wn1[:256] + aggs@Wn1[256:] + b)) -> tmps (fp16)
// ---------------------------------------------------------------------------
__global__ __launch_bounds__(256, 2) void node1_kernel(
    const uint32_t* __restrict__ xs, const uint32_t* __restrict__ aggs,
    const uint2* __restrict__ Wp, const float* __restrict__ Wb,
    const float* __restrict__ gam, const float* __restrict__ bet,
    uint32_t* __restrict__ tmps, int N) {
    extern __shared__ char smraw[];
    float* sBias = (float*)(smraw + SBIAS_OFF);
    float* sG    = (float*)(smraw + SG_OFF);
    float* sBv   = (float*)(smraw + SBV_OFF);

    const int tid = threadIdx.x;
    const int lane = tid & 31, warp = tid >> 5;
    const int wm = warp >> 2, wn = warp & 3;
    const int n0 = blockIdx.x * 64;
    const uint32_t sbase = (uint32_t)__cvta_generic_to_shared(smraw);
    const int arow = tid >> 2, apart = tid & 3;

    sBias[tid] = Wb[tid]; sG[tid] = gam[tid]; sBv[tid] = bet[tid];
    if (tid == 0) { mbar_init(sbase + MBAR_OFF, 1); mbar_init(sbase + MBAR_OFF + 8, 1); }
    __syncthreads();

    int rowg = n0 + arow; if (rowg >= N) rowg = N - 1;

    float acc[2][8][4];
#pragma unroll
    for (int mt = 0; mt < 2; mt++)
#pragma unroll
        for (int nt = 0; nt < 8; nt++)
#pragma unroll
            for (int j = 0; j < 4; j++) acc[mt][nt][j] = 0.f;

    auto stageA = [&](int c, int buf) {
        const uint32_t* bA = (c < 4) ? xs : aggs;
        const char* src = (const char*)(bA + (size_t)rowg * 128) + (c & 3) * 128 + apart * 32;
        uint32_t d = sbase + SA_OFF + buf * SA_BUF + arow * 144 + apart * 32;
        cp16(d, src); cp16(d + 16, src + 16);
    };
    gemm_pipeline(stageA, Wp, smraw, sbase, tid, wm, wn, lane, 8, acc);

    acc_to_sout(smraw, wm, wn, lane, acc, sBias);
    __syncthreads();
    float (*sOut)[260] = (float(*)[260])(smraw + SOUT_OFF);
#pragma unroll 1
    for (int i = 0; i < 8; i++) {
        int r = i * 8 + warp;
        float vv[8];
        *(float4*)&vv[0] = *(float4*)&sOut[r][lane * 4];
        *(float4*)&vv[4] = *(float4*)&sOut[r][128 + lane * 4];
        ln_silu_row(vv, lane, sG, sBv);
        int row = n0 + r;
        if (row < N) {
            uint32_t* op = tmps + (size_t)row * 128;
            op[lane * 2]          = packh(vv[0], vv[1]);
            op[lane * 2 + 1]      = packh(vv[2], vv[3]);
            op[64 + lane * 2]     = packh(vv[4], vv[5]);
            op[64 + lane * 2 + 1] = packh(vv[6], vv[7]);
        }
    }
}

// ---------------------------------------------------------------------------
// Node kernel 2: out = x + t@Wn2 + b2; also writes fp16 xs for next layer
// ---------------------------------------------------------------------------
__global__ __launch_bounds__(256, 2) void node2_kernel(
    const uint32_t* __restrict__ tmps, const float* __restrict__ xres,
    const uint2* __restrict__ Wp, const float* __restrict__ Wb,
    float* __restrict__ out, uint32_t* __restrict__ xs_next, int N) {
    extern __shared__ char smraw[];
    float* sBias = (float*)(smraw + SBIAS_OFF);

    const int tid = threadIdx.x;
    const int lane = tid & 31, warp = tid >> 5;
    const int wm = warp >> 2, wn = warp & 3;
    const int n0 = blockIdx.x * 64;
    const uint32_t sbase = (uint32_t)__cvta_generic_to_shared(smraw);
    const int arow = tid >> 2, apart = tid & 3;

    sBias[tid] = Wb[tid];
    if (tid == 0) { mbar_init(sbase + MBAR_OFF, 1); mbar_init(sbase + MBAR_OFF + 8, 1); }
    __syncthreads();

    int rowg = n0 + arow; if (rowg >= N) rowg = N - 1;

    float acc[2][8][4];
#pragma unroll
    for (int mt = 0; mt < 2; mt++)
#pragma unroll
        for (int nt = 0; nt < 8; nt++)
#pragma unroll
            for (int j = 0; j < 4; j++) acc[mt][nt][j] = 0.f;

    auto stageA = [&](int c, int buf) {
        const char* src = (const char*)(tmps + (size_t)rowg * 128) + c * 128 + apart * 32;
        uint32_t d = sbase + SA_OFF + buf * SA_BUF + arow * 144 + apart * 32;
        cp16(d, src); cp16(d + 16, src + 16);
    };
    gemm_pipeline(stageA, Wp, smraw, sbase, tid, wm, wn, lane, 4, acc);

    acc_to_sout(smraw, wm, wn, lane, acc, sBias);
    __syncthreads();
    float (*sOut)[260] = (float(*)[260])(smraw + SOUT_OFF);
#pragma unroll 1
    for (int i = 0; i < 8; i++) {
        int r = i * 8 + warp;
        int row = n0 + r;
        if (row < N) {
            const float* xr = xres + (size_t)row * 256;
            float4 lo = *(float4*)&sOut[r][lane * 4];
            float4 hi = *(float4*)&sOut[r][128 + lane * 4];
            float4 xlo = *(const float4*)(xr + lane * 4);
            float4 xhi = *(const float4*)(xr + 128 + lane * 4);
            lo.x += xlo.x; lo.y += xlo.y; lo.z += xlo.z; lo.w += xlo.w;
            hi.x += xhi.x; hi.y += xhi.y; hi.z += xhi.z; hi.w += xhi.w;
            float* op = out + (size_t)row * 256;
            *(float4*)(op + lane * 4) = lo;
            *(float4*)(op + 128 + lane * 4) = hi;
            uint32_t* xp = xs_next + (size_t)row * 128;
            xp[lane * 2]          = packh(lo.x, lo.y);
            xp[lane * 2 + 1]      = packh(lo.z, lo.w);
            xp[64 + lane * 2]     = packh(hi.x, hi.y);
            xp[64 + lane * 2 + 1] = packh(hi.z, hi.w);
        }
    }
}

// ---------------------------------------------------------------------------
extern "C" void kernel_launch(void* const* d_in, const int* in_sizes, int n_in,
                              void* d_out, int out_size) {
    const float* x_in  = (const float*)d_in[0];
    const int*   eidx  = (const int*)d_in[1];
    const float* ea    = (const float*)d_in[2];
    const float* We_w  = (const float*)d_in[3];
    const float* We_b  = (const float*)d_in[4];
    const float* g1    = (const float*)d_in[5];
    const float* b1    = (const float*)d_in[6];
    const float* Wn1_w = (const float*)d_in[7];
    const float* Wn1_b = (const float*)d_in[8];
    const float* g2    = (const float*)d_in[9];
    const float* b2    = (const float*)d_in[10];
    const float* Wn2_w = (const float*)d_in[11];
    const float* Wn2_b = (const float*)d_in[12];

    const int N  = in_sizes[0] / 256;
    const int D  = in_sizes[1] / 2;
    const int NL = in_sizes[4] / 256;

    float *bufA, *bufB, *aggp;
    uint32_t *y1h, *y2h, *xs, *aggs, *tmps;
    uint2 *wE, *wN1, *wN2;
    cudaGetSymbolAddress((void**)&bufA, g_bufA);
    cudaGetSymbolAddress((void**)&bufB, g_bufB);
    cudaGetSymbolAddress((void**)&aggp, g_agg);
    cudaGetSymbolAddress((void**)&y1h,  g_y1h);
    cudaGetSymbolAddress((void**)&y2h,  g_y2h);
    cudaGetSymbolAddress((void**)&xs,   g_xs);
    cudaGetSymbolAddress((void**)&aggs, g_aggs);
    cudaGetSymbolAddress((void**)&tmps, g_tmps);
    cudaGetSymbolAddress((void**)&wE,   g_We);
    cudaGetSymbolAddress((void**)&wN1,  g_Wn1);
    cudaGetSymbolAddress((void**)&wN2,  g_Wn2);

    cudaFuncSetAttribute(y12_kernel,   cudaFuncAttributeMaxDynamicSharedMemorySize, SMEM_BYTES);
    cudaFuncSetAttribute(node1_kernel, cudaFuncAttributeMaxDynamicSharedMemorySize, SMEM_BYTES);
    cudaFuncSetAttribute(node2_kernel, cudaFuncAttributeMaxDynamicSharedMemorySize, SMEM_BYTES);

    // one-time packs (deterministic, inside capture)
    {
        size_t t0 = (size_t)NL * 32 * 1024;
        pack_w_frag<<<(int)((t0 + 255) / 256), 256>>>(We_w, wE, 512, 516, 32, NL);
        pack_w_frag<<<(int)((t0 + 255) / 256), 256>>>(Wn1_w, wN1, 512, 512, 32, NL);
        size_t t2 = (size_t)NL * 16 * 1024;
        pack_w_frag<<<(int)((t2 + 255) / 256), 256>>>(Wn2_w, wN2, 256, 256, 16, NL);
        int nx = N * 128;
        convert_h<<<(nx + 255) / 256, 256>>>(x_in, xs, nx);
    }

    const int nblk_n = (N + 63) / 64;
    const int nblk_e = (D + 7) / 8;
    const int n4 = (N * 256) / 4;
    const int zblk = (n4 + 255) / 256;
    const int ncv = N * 128;
    const int cvblk = (ncv + 255) / 256;

    // agg must be zero before the first edge pass; convert_zero re-zeros after.
    zero_kernel<<<zblk, 256>>>((float4*)aggp, n4);

    const float* xcur = x_in;
    for (int l = 0; l < NL; l++) {
        float* xnext = (l == NL - 1) ? (float*)d_out : ((l & 1) ? bufB : bufA);
        y12_kernel<<<dim3(nblk_n, 2), 256, SMEM_BYTES>>>(
            xs, wE + (size_t)l * 32 * 1024, y1h, y2h, N);
        edge_pass<<<nblk_e, 256>>>(
            y1h, y2h, eidx, ea,
            We_w + (size_t)l * 516 * 256 + (size_t)512 * 256,
            We_b + (size_t)l * 256, g1 + (size_t)l * 256, b1 + (size_t)l * 256,
            aggp, D);
        convert_zero<<<cvblk, 256>>>(aggp, aggs, ncv);
        node1_kernel<<<nblk_n, 256, SMEM_BYTES>>>(
            xs, aggs, wN1 + (size_t)l * 32 * 1024,
            Wn1_b + (size_t)l * 256, g2 + (size_t)l * 256, b2 + (size_t)l * 256,
            tmps, N);
        node2_kernel<<<nblk_n, 256, SMEM_BYTES>>>(
            tmps, xcur, wN2 + (size_t)l * 16 * 1024,
            Wn2_b + (size_t)l * 256, xnext, xs, N);
        xcur = xnext;
    }
}

// round 17
// speedup vs baseline: 2.2690x; 1.3715x over previous
#include <cuda_runtime.h>
#include <cuda_fp16.h>
#include <cstdint>

// ============================================================================
// GraphCastProcessor — plain fp16 mma.sync GEMMs (1 MMA/k16, fp32 acc),
// K-superchunk 64, ldmatrix A-fragments, fused convert+zero, and an edge pass
// where each warp processes 8 edges (constants loaded once per warp).
//   y1 = x@We[:256], y2 = x@We[256:512]          (fp16x2 out)
//   h_e = y1[dst]+y2[src]+ea@W3+b ; msg = silu(LN(h)); agg += msg (f32 RED)
//   u = x@Wn1[:256]+agg@Wn1[256:]+b ; t = silu(LN(u))
//   x = x + t@Wn2 + b2
// ============================================================================

#define MAXN 40962
#define MAXD 163848
#define MAXNL 6
#define EPW 8            // edges per warp in edge_pass

__device__ float g_bufA[MAXN * 256];
__device__ float g_bufB[MAXN * 256];
__device__ float g_agg [MAXN * 256];
__device__ uint32_t g_y1h [MAXN * 128];   // fp16x2 rows (512B)
__device__ uint32_t g_y2h [MAXN * 128];
__device__ uint32_t g_xs  [MAXN * 128];   // fp16x2 activations
__device__ uint32_t g_aggs[MAXN * 128];
__device__ uint32_t g_tmps[MAXN * 128];
// fragment-ordered fp16 weights: [layer][chunk16][wn(4)][nt(8)][lane(32)]
// uint2 = {k0pair, k1pair}
__device__ uint2 g_We [MAXNL * 32 * 1024];
__device__ uint2 g_Wn1[MAXNL * 32 * 1024];
__device__ uint2 g_Wn2[MAXNL * 16 * 1024];

// ---- dynamic smem layout (bytes) ----
#define SA_OFF    0
#define SA_BUF    9216
#define SB_OFF    18432
#define SB_BUF    32768
#define SOUT_OFF  0
#define SBIAS_OFF 83968
#define SG_OFF    84992
#define SBV_OFF   86016
#define MBAR_OFF  87040                   // 2 x u64
#define SMEM_BYTES 87072

__device__ __forceinline__ float fast_silu(float y) {
    return __fdividef(y, 1.0f + __expf(-y));
}

__device__ __forceinline__ uint32_t packh(float a, float b) {
    __half2 h = __floats2half2_rn(a, b);
    return *(uint32_t*)&h;
}
__device__ __forceinline__ float2 unpackh(uint32_t u) {
    __half2 h = *(__half2*)&u;
    return __half22float2(h);
}

__device__ __forceinline__ void mma_f16(float c[4], const uint32_t a[4],
                                        uint32_t b0, uint32_t b1) {
    asm volatile(
        "mma.sync.aligned.m16n8k16.row.col.f32.f16.f16.f32 "
        "{%0,%1,%2,%3}, {%4,%5,%6,%7}, {%8,%9}, {%0,%1,%2,%3};"
        : "+f"(c[0]), "+f"(c[1]), "+f"(c[2]), "+f"(c[3])
        : "r"(a[0]), "r"(a[1]), "r"(a[2]), "r"(a[3]), "r"(b0), "r"(b1));
}

__device__ __forceinline__ void ldsm_x4(uint32_t a[4], uint32_t addr) {
    asm volatile("ldmatrix.sync.aligned.m8n8.x4.shared.b16 {%0,%1,%2,%3}, [%4];"
                 : "=r"(a[0]), "=r"(a[1]), "=r"(a[2]), "=r"(a[3]) : "r"(addr));
}

__device__ __forceinline__ void red_v4(float* p, float a, float b, float c, float d) {
    asm volatile("red.global.add.v4.f32 [%0], {%1,%2,%3,%4};"
                 :: "l"(p), "f"(a), "f"(b), "f"(c), "f"(d) : "memory");
}

__device__ __forceinline__ void cp16(uint32_t smem_dst, const void* gsrc) {
    asm volatile("cp.async.cg.shared.global [%0], [%1], 16;\n"
                 :: "r"(smem_dst), "l"(gsrc));
}
#define CP_COMMIT() asm volatile("cp.async.commit_group;\n" ::: "memory")
#define CP_WAIT(n)  asm volatile("cp.async.wait_group %0;\n" :: "n"(n) : "memory")

__device__ __forceinline__ void mbar_init(uint32_t mbar, uint32_t count) {
    asm volatile("mbarrier.init.shared.b64 [%0], %1;" :: "r"(mbar), "r"(count) : "memory");
}
__device__ __forceinline__ void mbar_expect_tx(uint32_t mbar, uint32_t bytes) {
    asm volatile("mbarrier.arrive.expect_tx.shared.b64 _, [%0], %1;"
                 :: "r"(mbar), "r"(bytes) : "memory");
}
__device__ __forceinline__ void mbar_wait(uint32_t mbar, uint32_t parity) {
    asm volatile(
        "{\n\t.reg .pred P1;\n\t"
        "WAIT_LOOP_%=:\n\t"
        "mbarrier.try_wait.parity.acquire.cta.shared::cta.b64 P1, [%0], %1, 0x989680;\n\t"
        "@P1 bra.uni WAIT_DONE_%=;\n\t"
        "bra.uni WAIT_LOOP_%=;\n\t"
        "WAIT_DONE_%=:\n\t}"
        :: "r"(mbar), "r"(parity) : "memory");
}
__device__ __forceinline__ void bulk_cp(uint32_t smem_dst, const void* gsrc,
                                        uint32_t bytes, uint32_t mbar) {
    asm volatile(
        "cp.async.bulk.shared::cta.global.mbarrier::complete_tx::bytes [%0], [%1], %2, [%3];"
        :: "r"(smem_dst), "l"(gsrc), "r"(bytes), "r"(mbar) : "memory");
}

// LN(256)+SiLU; row spread as 8 vals/lane (cols tx*4+j / 128+tx*4+j-4)
__device__ __forceinline__ void ln_silu_row(float v[8], int tx,
                                            const float* sG, const float* sB) {
    float s = v[0] + v[1] + v[2] + v[3] + v[4] + v[5] + v[6] + v[7];
#pragma unroll
    for (int o = 16; o > 0; o >>= 1) s += __shfl_xor_sync(0xffffffffu, s, o);
    float mean = s * (1.0f / 256.0f);
    float vs = 0.f;
#pragma unroll
    for (int j = 0; j < 8; j++) { float d = v[j] - mean; vs += d * d; }
#pragma unroll
    for (int o = 16; o > 0; o >>= 1) vs += __shfl_xor_sync(0xffffffffu, vs, o);
    float rstd = rsqrtf(vs * (1.0f / 256.0f) + 1e-5f);
#pragma unroll
    for (int j = 0; j < 8; j++) {
        int col = (j < 4) ? (tx * 4 + j) : (128 + tx * 4 + j - 4);
        float y = (v[j] - mean) * rstd * sG[col] + sB[col];
        v[j] = fast_silu(y);
    }
}

// one K64 superchunk: four k16 halves, 1 MMA each; A via ldmatrix.x4
__device__ __forceinline__ void compute_schunk(char* smraw, uint32_t sbase, int buf,
                                               int wm, int wn, int lane,
                                               float acc[2][8][4]) {
    const uint2* sBp = (const uint2*)(smraw + SB_OFF + buf * SB_BUF);
    const uint32_t abase = sbase + SA_OFF + buf * SA_BUF
                         + (uint32_t)(lane & 15) * 144 + (uint32_t)(lane >> 4) * 16;
#pragma unroll
    for (int h = 0; h < 4; h++) {
        uint32_t a[2][4];
#pragma unroll
        for (int mt = 0; mt < 2; mt++)
            ldsm_x4(a[mt], abase + (wm * 32 + mt * 16) * 144 + h * 32);
#pragma unroll
        for (int nt = 0; nt < 8; nt++) {
            uint2 b = sBp[h * 1024 + wn * 256 + nt * 32 + lane];
#pragma unroll
            for (int mt = 0; mt < 2; mt++)
                mma_f16(acc[mt][nt], a[mt], b.x, b.y);
        }
    }
}

template <typename FA>
__device__ __forceinline__ void gemm_pipeline(FA stageA, const uint2* __restrict__ Wp,
                                              char* smraw, uint32_t sbase, int tid,
                                              int wm, int wn, int lane, int schunks,
                                              float acc[2][8][4]) {
    const uint32_t mbar0 = sbase + MBAR_OFF;
    auto issueB = [&](int c, int buf) {
        if (tid == 0) {
            uint32_t mb = mbar0 + buf * 8;
            mbar_expect_tx(mb, SB_BUF);
            bulk_cp(sbase + SB_OFF + buf * SB_BUF, Wp + (size_t)c * 4096, SB_BUF, mb);
        }
    };
    stageA(0, 0); CP_COMMIT(); issueB(0, 0);
#pragma unroll 1
    for (int c = 0; c < schunks; c++) {
        if (c + 1 < schunks) {
            stageA(c + 1, (c + 1) & 1); CP_COMMIT(); issueB(c + 1, (c + 1) & 1);
            CP_WAIT(1);
        } else {
            CP_WAIT(0);
        }
        mbar_wait(mbar0 + (c & 1) * 8, (c >> 1) & 1);
        __syncthreads();
        compute_schunk(smraw, sbase, c & 1, wm, wn, lane, acc);
        __syncthreads();
    }
}

__device__ __forceinline__ void acc_to_sout(char* smraw, int wm, int wn,
                                            int lane, float acc[2][8][4],
                                            const float* sBias) {
    float (*sOut)[260] = (float(*)[260])(smraw + SOUT_OFF);
#pragma unroll
    for (int mt = 0; mt < 2; mt++)
#pragma unroll
        for (int nt = 0; nt < 8; nt++) {
            int r0 = wm * 32 + mt * 16 + (lane >> 2);
            int c = wn * 64 + nt * 8 + 2 * (lane & 3);
            float b0 = sBias ? sBias[c] : 0.f;
            float b1 = sBias ? sBias[c + 1] : 0.f;
            sOut[r0][c]         = acc[mt][nt][0] + b0;
            sOut[r0][c + 1]     = acc[mt][nt][1] + b1;
            sOut[r0 + 8][c]     = acc[mt][nt][2] + b0;
            sOut[r0 + 8][c + 1] = acc[mt][nt][3] + b1;
        }
}

// ---------------------------------------------------------------------------
// packers
// ---------------------------------------------------------------------------
__global__ void pack_w_frag(const float* __restrict__ W, uint2* __restrict__ out,
                            int Ksrc, int lstride, int C, int NL) {
    size_t idx = (size_t)blockIdx.x * blockDim.x + threadIdx.x;
    size_t total = (size_t)NL * C * 1024;
    if (idx >= total) return;
    int t = (int)(idx & 1023);
    int lane = t & 31, nt = (t >> 5) & 7, wn = t >> 8;
    int c = (int)((idx >> 10) % C);
    int l = (int)(idx / ((size_t)C * 1024));
    int n = wn * 64 + nt * 8 + (lane >> 2);
    int q = lane & 3;
    int kp0 = c * 8 + q, kp1 = c * 8 + q + 4;
    const float* Wl = W + (size_t)l * lstride * 256;
    float a0 = (2 * kp0     < Ksrc) ? Wl[(size_t)(2 * kp0)     * 256 + n] : 0.f;
    float a1 = (2 * kp0 + 1 < Ksrc) ? Wl[(size_t)(2 * kp0 + 1) * 256 + n] : 0.f;
    float b0 = (2 * kp1     < Ksrc) ? Wl[(size_t)(2 * kp1)     * 256 + n] : 0.f;
    float b1 = (2 * kp1 + 1 < Ksrc) ? Wl[(size_t)(2 * kp1 + 1) * 256 + n] : 0.f;
    out[idx] = make_uint2(packh(a0, a1), packh(b0, b1));
}

__global__ void convert_h(const float* __restrict__ in, uint32_t* __restrict__ out,
                          int n) {
    int i = blockIdx.x * blockDim.x + threadIdx.x;
    if (i < n) {
        float2 v = ((const float2*)in)[i];
        out[i] = packh(v.x, v.y);
    }
}

// read agg -> fp16 aggs, AND re-zero agg for the next layer's edge pass
__global__ void convert_zero(float* __restrict__ agg, uint32_t* __restrict__ out,
                             int n) {
    int i = blockIdx.x * blockDim.x + threadIdx.x;
    if (i < n) {
        float2 v = ((float2*)agg)[i];
        out[i] = packh(v.x, v.y);
        ((float2*)agg)[i] = make_float2(0.f, 0.f);
    }
}

__global__ void zero_kernel(float4* __restrict__ p, int n4) {
    int i = blockIdx.x * blockDim.x + threadIdx.x;
    if (i < n4) p[i] = make_float4(0.f, 0.f, 0.f, 0.f);
}

// ---------------------------------------------------------------------------
// y12 kernel: y = x @ We[half*256 : (half+1)*256] (no bias) -> fp16x2 rows
// ---------------------------------------------------------------------------
__global__ __launch_bounds__(256, 2) void y12_kernel(
    const uint32_t* __restrict__ xs, const uint2* __restrict__ WpBase,
    uint32_t* __restrict__ y1h, uint32_t* __restrict__ y2h, int N) {
    extern __shared__ char smraw[];
    const int tid = threadIdx.x;
    const int lane = tid & 31, warp = tid >> 5;
    const int wm = warp >> 2, wn = warp & 3;
    const int n0 = blockIdx.x * 64;
    const int half = blockIdx.y;
    const uint32_t sbase = (uint32_t)__cvta_generic_to_shared(smraw);
    const int arow = tid >> 2, apart = tid & 3;
    int rowg = n0 + arow; if (rowg >= N) rowg = N - 1;

    if (tid == 0) { mbar_init(sbase + MBAR_OFF, 1); mbar_init(sbase + MBAR_OFF + 8, 1); }
    __syncthreads();

    const uint2* Wp = WpBase + (size_t)half * 16 * 1024;
    uint32_t* yout = half ? y2h : y1h;

    float acc[2][8][4];
#pragma unroll
    for (int mt = 0; mt < 2; mt++)
#pragma unroll
        for (int nt = 0; nt < 8; nt++)
#pragma unroll
            for (int j = 0; j < 4; j++) acc[mt][nt][j] = 0.f;

    auto stageA = [&](int c, int buf) {
        const char* src = (const char*)(xs + (size_t)rowg * 128) + c * 128 + apart * 32;
        uint32_t d = sbase + SA_OFF + buf * SA_BUF + arow * 144 + apart * 32;
        cp16(d, src); cp16(d + 16, src + 16);
    };
    gemm_pipeline(stageA, Wp, smraw, sbase, tid, wm, wn, lane, 4, acc);

    acc_to_sout(smraw, wm, wn, lane, acc, nullptr);
    __syncthreads();
    float (*sOut)[260] = (float(*)[260])(smraw + SOUT_OFF);
#pragma unroll 1
    for (int i = 0; i < 8; i++) {
        int r = i * 8 + warp;
        int row = n0 + r;
        if (row < N) {
            float4 lo = *(float4*)&sOut[r][lane * 4];
            float4 hi = *(float4*)&sOut[r][128 + lane * 4];
            uint32_t* op = yout + (size_t)row * 128;
            *(uint2*)(op + lane * 2)      = make_uint2(packh(lo.x, lo.y), packh(lo.z, lo.w));
            *(uint2*)(op + 64 + lane * 2) = make_uint2(packh(hi.x, hi.y), packh(hi.z, hi.w));
        }
    }
}

// ---------------------------------------------------------------------------
// Edge pass: each warp processes EPW consecutive edges; constants loaded once.
// h = y1h[dst]+y2h[src]+ea@W3+b; silu(LN(h)) -> f32 red.v4 into agg
// ---------------------------------------------------------------------------
__global__ __launch_bounds__(256) void edge_pass(
    const uint32_t* __restrict__ y1h, const uint32_t* __restrict__ y2h,
    const int* __restrict__ eidx, const float* __restrict__ ea,
    const float* __restrict__ W3, const float* __restrict__ Wb,
    const float* __restrict__ gam, const float* __restrict__ bet,
    float* __restrict__ agg, int D) {
    const int lane = threadIdx.x & 31, warp = threadIdx.x >> 5;
    const int e0 = (blockIdx.x * 8 + warp) * EPW;

    float w3r[4][8], biasr[8], gr[8], br[8];
#pragma unroll
    for (int j = 0; j < 8; j++) {
        int col = (j < 4) ? (lane * 4 + j) : (128 + lane * 4 + j - 4);
        biasr[j] = __ldg(Wb + col);
        gr[j] = __ldg(gam + col);
        br[j] = __ldg(bet + col);
#pragma unroll
        for (int k = 0; k < 4; k++) w3r[k][j] = __ldg(W3 + k * 256 + col);
    }
    if (e0 >= D) return;

#pragma unroll 1
    for (int ei = 0; ei < EPW; ei++) {
        int e = e0 + ei;
        if (e >= D) break;
        int src = __ldg(eidx + e);
        int dst = __ldg(eidx + (size_t)D + e);
        uint2 u1lo = *(const uint2*)(y1h + (size_t)dst * 128 + lane * 2);
        uint2 u1hi = *(const uint2*)(y1h + (size_t)dst * 128 + 64 + lane * 2);
        uint2 u2lo = *(const uint2*)(y2h + (size_t)src * 128 + lane * 2);
        uint2 u2hi = *(const uint2*)(y2h + (size_t)src * 128 + 64 + lane * 2);
        float4 eav = *(const float4*)(ea + (size_t)e * 4);

        float v[8];
        {
            float2 a0 = unpackh(u1lo.x), a1 = unpackh(u1lo.y);
            float2 a2 = unpackh(u1hi.x), a3 = unpackh(u1hi.y);
            float2 c0 = unpackh(u2lo.x), c1 = unpackh(u2lo.y);
            float2 c2 = unpackh(u2hi.x), c3 = unpackh(u2hi.y);
            v[0] = a0.x + c0.x; v[1] = a0.y + c0.y;
            v[2] = a1.x + c1.x; v[3] = a1.y + c1.y;
            v[4] = a2.x + c2.x; v[5] = a2.y + c2.y;
            v[6] = a3.x + c3.x; v[7] = a3.y + c3.y;
        }
#pragma unroll
        for (int j = 0; j < 8; j++) {
            float h = v[j] + biasr[j];
            h = fmaf(eav.x, w3r[0][j], h);
            h = fmaf(eav.y, w3r[1][j], h);
            h = fmaf(eav.z, w3r[2][j], h);
            h = fmaf(eav.w, w3r[3][j], h);
            v[j] = h;
        }
        float s = v[0] + v[1] + v[2] + v[3] + v[4] + v[5] + v[6] + v[7];
#pragma unroll
        for (int o = 16; o > 0; o >>= 1) s += __shfl_xor_sync(0xffffffffu, s, o);
        float mean = s * (1.0f / 256.0f);
        float vs = 0.f;
#pragma unroll
        for (int j = 0; j < 8; j++) { float d = v[j] - mean; vs += d * d; }
#pragma unroll
        for (int o = 16; o > 0; o >>= 1) vs += __shfl_xor_sync(0xffffffffu, vs, o);
        float rstd = rsqrtf(vs * (1.0f / 256.0f) + 1e-5f);

        float m[8];
#pragma unroll
        for (int j = 0; j < 8; j++)
            m[j] = fast_silu((v[j] - mean) * rstd * gr[j] + br[j]);

        float* ag = agg + (size_t)dst * 256;
        red_v4(ag + lane * 4,       m[0], m[1], m[2], m[3]);
        red_v4(ag + 128 + lane * 4, m[4], m[5], m[6], m[7]);
    }
}

// ---------------------------------------------------------------------------
// Node kernel 1: t = silu(LN(x@Wn1[:256] + aggs@Wn1[256:] + b)) -> tmps (fp16)
// ---------------------------------------------------------------------------
__global__ __launch_bounds__(256, 2) void node1_kernel(
    const uint32_t* __restrict__ xs, const uint32_t* __restrict__ aggs,
    const uint2* __restrict__ Wp, const float* __restrict__ Wb,
    const float* __restrict__ gam, const float* __restrict__ bet,
    uint32_t* __restrict__ tmps, int N) {
    extern __shared__ char smraw[];
    float* sBias = (float*)(smraw + SBIAS_OFF);
    float* sG    = (float*)(smraw + SG_OFF);
    float* sBv   = (float*)(smraw + SBV_OFF);

    const int tid = threadIdx.x;
    const int lane = tid & 31, warp = tid >> 5;
    const int wm = warp >> 2, wn = warp & 3;
    const int n0 = blockIdx.x * 64;
    const uint32_t sbase = (uint32_t)__cvta_generic_to_shared(smraw);
    const int arow = tid >> 2, apart = tid & 3;

    sBias[tid] = Wb[tid]; sG[tid] = gam[tid]; sBv[tid] = bet[tid];
    if (tid == 0) { mbar_init(sbase + MBAR_OFF, 1); mbar_init(sbase + MBAR_OFF + 8, 1); }
    __syncthreads();

    int rowg = n0 + arow; if (rowg >= N) rowg = N - 1;

    float acc[2][8][4];
#pragma unroll
    for (int mt = 0; mt < 2; mt++)
#pragma unroll
        for (int nt = 0; nt < 8; nt++)
#pragma unroll
            for (int j = 0; j < 4; j++) acc[mt][nt][j] = 0.f;

    auto stageA = [&](int c, int buf) {
        const uint32_t* bA = (c < 4) ? xs : aggs;
        const char* src = (const char*)(bA + (size_t)rowg * 128) + (c & 3) * 128 + apart * 32;
        uint32_t d = sbase + SA_OFF + buf * SA_BUF + arow * 144 + apart * 32;
        cp16(d, src); cp16(d + 16, src + 16);
    };
    gemm_pipeline(stageA, Wp, smraw, sbase, tid, wm, wn, lane, 8, acc);

    acc_to_sout(smraw, wm, wn, lane, acc, sBias);
    __syncthreads();
    float (*sOut)[260] = (float(*)[260])(smraw + SOUT_OFF);
#pragma unroll 1
    for (int i = 0; i < 8; i++) {
        int r = i * 8 + warp;
        float vv[8];
        *(float4*)&vv[0] = *(float4*)&sOut[r][lane * 4];
        *(float4*)&vv[4] = *(float4*)&sOut[r][128 + lane * 4];
        ln_silu_row(vv, lane, sG, sBv);
        int row = n0 + r;
        if (row < N) {
            uint32_t* op = tmps + (size_t)row * 128;
            op[lane * 2]          = packh(vv[0], vv[1]);
            op[lane * 2 + 1]      = packh(vv[2], vv[3]);
            op[64 + lane * 2]     = packh(vv[4], vv[5]);
            op[64 + lane * 2 + 1] = packh(vv[6], vv[7]);
        }
    }
}

// ---------------------------------------------------------------------------
// Node kernel 2: out = x + t@Wn2 + b2; also writes fp16 xs for next layer
// ---------------------------------------------------------------------------
__global__ __launch_bounds__(256, 2) void node2_kernel(
    const uint32_t* __restrict__ tmps, const float* __restrict__ xres,
    const uint2* __restrict__ Wp, const float* __restrict__ Wb,
    float* __restrict__ out, uint32_t* __restrict__ xs_next, int N) {
    extern __shared__ char smraw[];
    float* sBias = (float*)(smraw + SBIAS_OFF);

    const int tid = threadIdx.x;
    const int lane = tid & 31, warp = tid >> 5;
    const int wm = warp >> 2, wn = warp & 3;
    const int n0 = blockIdx.x * 64;
    const uint32_t sbase = (uint32_t)__cvta_generic_to_shared(smraw);
    const int arow = tid >> 2, apart = tid & 3;

    sBias[tid] = Wb[tid];
    if (tid == 0) { mbar_init(sbase + MBAR_OFF, 1); mbar_init(sbase + MBAR_OFF + 8, 1); }
    __syncthreads();

    int rowg = n0 + arow; if (rowg >= N) rowg = N - 1;

    float acc[2][8][4];
#pragma unroll
    for (int mt = 0; mt < 2; mt++)
#pragma unroll
        for (int nt = 0; nt < 8; nt++)
#pragma unroll
            for (int j = 0; j < 4; j++) acc[mt][nt][j] = 0.f;

    auto stageA = [&](int c, int buf) {
        const char* src = (const char*)(tmps + (size_t)rowg * 128) + c * 128 + apart * 32;
        uint32_t d = sbase + SA_OFF + buf * SA_BUF + arow * 144 + apart * 32;
        cp16(d, src); cp16(d + 16, src + 16);
    };
    gemm_pipeline(stageA, Wp, smraw, sbase, tid, wm, wn, lane, 4, acc);

    acc_to_sout(smraw, wm, wn, lane, acc, sBias);
    __syncthreads();
    float (*sOut)[260] = (float(*)[260])(smraw + SOUT_OFF);
#pragma unroll 1
    for (int i = 0; i < 8; i++) {
        int r = i * 8 + warp;
        int row = n0 + r;
        if (row < N) {
            const float* xr = xres + (size_t)row * 256;
            float4 lo = *(float4*)&sOut[r][lane * 4];
            float4 hi = *(float4*)&sOut[r][128 + lane * 4];
            float4 xlo = *(const float4*)(xr + lane * 4);
            float4 xhi = *(const float4*)(xr + 128 + lane * 4);
            lo.x += xlo.x; lo.y += xlo.y; lo.z += xlo.z; lo.w += xlo.w;
            hi.x += xhi.x; hi.y += xhi.y; hi.z += xhi.z; hi.w += xhi.w;
            float* op = out + (size_t)row * 256;
            *(float4*)(op + lane * 4) = lo;
            *(float4*)(op + 128 + lane * 4) = hi;
            uint32_t* xp = xs_next + (size_t)row * 128;
            xp[lane * 2]          = packh(lo.x, lo.y);
            xp[lane * 2 + 1]      = packh(lo.z, lo.w);
            xp[64 + lane * 2]     = packh(hi.x, hi.y);
            xp[64 + lane * 2 + 1] = packh(hi.z, hi.w);
        }
    }
}

// ---------------------------------------------------------------------------
extern "C" void kernel_launch(void* const* d_in, const int* in_sizes, int n_in,
                              void* d_out, int out_size) {
    const float* x_in  = (const float*)d_in[0];
    const int*   eidx  = (const int*)d_in[1];
    const float* ea    = (const float*)d_in[2];
    const float* We_w  = (const float*)d_in[3];
    const float* We_b  = (const float*)d_in[4];
    const float* g1    = (const float*)d_in[5];
    const float* b1    = (const float*)d_in[6];
    const float* Wn1_w = (const float*)d_in[7];
    const float* Wn1_b = (const float*)d_in[8];
    const float* g2    = (const float*)d_in[9];
    const float* b2    = (const float*)d_in[10];
    const float* Wn2_w = (const float*)d_in[11];
    const float* Wn2_b = (const float*)d_in[12];

    const int N  = in_sizes[0] / 256;
    const int D  = in_sizes[1] / 2;
    const int NL = in_sizes[4] / 256;

    float *bufA, *bufB, *aggp;
    uint32_t *y1h, *y2h, *xs, *aggs, *tmps;
    uint2 *wE, *wN1, *wN2;
    cudaGetSymbolAddress((void**)&bufA, g_bufA);
    cudaGetSymbolAddress((void**)&bufB, g_bufB);
    cudaGetSymbolAddress((void**)&aggp, g_agg);
    cudaGetSymbolAddress((void**)&y1h,  g_y1h);
    cudaGetSymbolAddress((void**)&y2h,  g_y2h);
    cudaGetSymbolAddress((void**)&xs,   g_xs);
    cudaGetSymbolAddress((void**)&aggs, g_aggs);
    cudaGetSymbolAddress((void**)&tmps, g_tmps);
    cudaGetSymbolAddress((void**)&wE,   g_We);
    cudaGetSymbolAddress((void**)&wN1,  g_Wn1);
    cudaGetSymbolAddress((void**)&wN2,  g_Wn2);

    cudaFuncSetAttribute(y12_kernel,   cudaFuncAttributeMaxDynamicSharedMemorySize, SMEM_BYTES);
    cudaFuncSetAttribute(node1_kernel, cudaFuncAttributeMaxDynamicSharedMemorySize, SMEM_BYTES);
    cudaFuncSetAttribute(node2_kernel, cudaFuncAttributeMaxDynamicSharedMemorySize, SMEM_BYTES);

    // one-time packs (deterministic, inside capture)
    {
        size_t t0 = (size_t)NL * 32 * 1024;
        pack_w_frag<<<(int)((t0 + 255) / 256), 256>>>(We_w, wE, 512, 516, 32, NL);
        pack_w_frag<<<(int)((t0 + 255) / 256), 256>>>(Wn1_w, wN1, 512, 512, 32, NL);
        size_t t2 = (size_t)NL * 16 * 1024;
        pack_w_frag<<<(int)((t2 + 255) / 256), 256>>>(Wn2_w, wN2, 256, 256, 16, NL);
        int nx = N * 128;
        convert_h<<<(nx + 255) / 256, 256>>>(x_in, xs, nx);
    }

    const int nblk_n = (N + 63) / 64;
    const int nblk_e = (D + 8 * EPW - 1) / (8 * EPW);
    const int n4 = (N * 256) / 4;
    const int zblk = (n4 + 255) / 256;
    const int ncv = N * 128;
    const int cvblk = (ncv + 255) / 256;

    // agg must be zero before the first edge pass; convert_zero re-zeros after.
    zero_kernel<<<zblk, 256>>>((float4*)aggp, n4);

    const float* xcur = x_in;
    for (int l = 0; l < NL; l++) {
        float* xnext = (l == NL - 1) ? (float*)d_out : ((l & 1) ? bufB : bufA);
        y12_kernel<<<dim3(nblk_n, 2), 256, SMEM_BYTES>>>(
            xs, wE + (size_t)l * 32 * 1024, y1h, y2h, N);
        edge_pass<<<nblk_e, 256>>>(
            y1h, y2h, eidx, ea,
            We_w + (size_t)l * 516 * 256 + (size_t)512 * 256,
            We_b + (size_t)l * 256, g1 + (size_t)l * 256, b1 + (size_t)l * 256,
            aggp, D);
        convert_zero<<<cvblk, 256>>>(aggp, aggs, ncv);
        node1_kernel<<<nblk_n, 256, SMEM_BYTES>>>(
            xs, aggs, wN1 + (size_t)l * 32 * 1024,
            Wn1_b + (size_t)l * 256, g2 + (size_t)l * 256, b2 + (size_t)l * 256,
            tmps, N);
        node2_kernel<<<nblk_n, 256, SMEM_BYTES>>>(
            tmps, xcur, wN2 + (size_t)l * 16 * 1024,
            Wn2_b + (size_t)l * 256, xnext, xs, N);
        xcur = xnext;
    }
}